// round 1
// baseline (speedup 1.0000x reference)
#include <cuda_runtime.h>
#include <math.h>

#define BSZ 8
#define SEQ 2048
#define EMB 768

// Scratch (device globals — no allocation allowed in kernel_launch)
__device__ float g_Q[BSZ * SEQ * EMB];                // 48 MB
__device__ float g_K[BSZ * SEQ * EMB];                // 48 MB
__device__ float g_V[BSZ * SEQ * EMB];                // 48 MB
__device__ float g_P[(size_t)BSZ * SEQ * SEQ];        // 128 MB
__device__ float g_C[BSZ * SEQ * EMB];                // 48 MB

// ---------------------------------------------------------------------------
// Classic 128x128x8 SGEMM, 256 threads, 8x8 micro-tile per thread.
// C[m,n] = alpha * sum_k A[m,k] * B(k,n) (+ bias[n])
//   TRANSB=false: B is row-major [K, N]
//   TRANSB=true : B is row-major [N, K]  (C = A * B^T)
// Shapes must be multiples of the tile (true for all launches here).
// ---------------------------------------------------------------------------
template <bool TRANSB, bool BIAS>
__global__ void __launch_bounds__(256, 2)
sgemm_kernel(const float* __restrict__ A, const float* __restrict__ B,
             const float* __restrict__ bias, float* __restrict__ C,
             int M, int N, int K, float alpha,
             long sA, long sB, long sC)
{
    __shared__ float As[8][128];
    __shared__ float Bs[8][128];

    const int tid = threadIdx.x;
    const int tx  = tid & 15;    // 0..15 -> N
    const int ty  = tid >> 4;    // 0..15 -> M
    const int bx  = blockIdx.x * 128;
    const int by  = blockIdx.y * 128;

    A += (long)blockIdx.z * sA;
    B += (long)blockIdx.z * sB;
    C += (long)blockIdx.z * sC;

    // A loader mapping: 128 rows x 8 k, one float4 per thread
    const int ar  = tid >> 1;          // 0..127
    const int akg = (tid & 1) * 4;     // 0 or 4
    const float* aPtr = A + (long)(by + ar) * K + akg;

    // B loader mapping
    const float* bPtr;
    int bkr = 0, bnc = 0;
    if (TRANSB) {
        bPtr = B + (long)(bx + ar) * K + akg;       // rows of B^T
    } else {
        bkr = tid >> 5;                             // 0..7 (k row)
        bnc = (tid & 31) * 4;                       // 0..124 (n col)
        bPtr = B + (long)bkr * N + bx + bnc;
    }

    float acc[8][8];
#pragma unroll
    for (int i = 0; i < 8; i++)
#pragma unroll
        for (int j = 0; j < 8; j++) acc[i][j] = 0.0f;

    float4 aReg = *(const float4*)aPtr;
    float4 bReg = *(const float4*)bPtr;

    const int nTiles = K >> 3;
    for (int t = 0; t < nTiles; ++t) {
        // write staged tile to smem
        As[akg + 0][ar] = aReg.x;
        As[akg + 1][ar] = aReg.y;
        As[akg + 2][ar] = aReg.z;
        As[akg + 3][ar] = aReg.w;
        if (TRANSB) {
            Bs[akg + 0][ar] = bReg.x;
            Bs[akg + 1][ar] = bReg.y;
            Bs[akg + 2][ar] = bReg.z;
            Bs[akg + 3][ar] = bReg.w;
        } else {
            *(float4*)&Bs[bkr][bnc] = bReg;
        }
        __syncthreads();

        // prefetch next tile from global (overlaps with compute below)
        aPtr += 8;
        if (TRANSB) bPtr += 8; else bPtr += (long)8 * N;
        if (t + 1 < nTiles) {
            aReg = *(const float4*)aPtr;
            bReg = *(const float4*)bPtr;
        }

#pragma unroll
        for (int k = 0; k < 8; k++) {
            float a[8], b[8];
            *(float4*)&a[0] = *(const float4*)&As[k][ty * 8];
            *(float4*)&a[4] = *(const float4*)&As[k][ty * 8 + 4];
            *(float4*)&b[0] = *(const float4*)&Bs[k][tx * 8];
            *(float4*)&b[4] = *(const float4*)&Bs[k][tx * 8 + 4];
#pragma unroll
            for (int i = 0; i < 8; i++)
#pragma unroll
                for (int j = 0; j < 8; j++)
                    acc[i][j] = fmaf(a[i], b[j], acc[i][j]);
        }
        __syncthreads();
    }

    // epilogue
    float bv[8];
#pragma unroll
    for (int j = 0; j < 8; j++)
        bv[j] = BIAS ? bias[bx + tx * 8 + j] : 0.0f;

#pragma unroll
    for (int i = 0; i < 8; i++) {
        const long off = (long)(by + ty * 8 + i) * N + bx + tx * 8;
        float4 v0, v1;
        v0.x = fmaf(acc[i][0], alpha, bv[0]);
        v0.y = fmaf(acc[i][1], alpha, bv[1]);
        v0.z = fmaf(acc[i][2], alpha, bv[2]);
        v0.w = fmaf(acc[i][3], alpha, bv[3]);
        v1.x = fmaf(acc[i][4], alpha, bv[4]);
        v1.y = fmaf(acc[i][5], alpha, bv[5]);
        v1.z = fmaf(acc[i][6], alpha, bv[6]);
        v1.w = fmaf(acc[i][7], alpha, bv[7]);
        *(float4*)&C[off]     = v0;
        *(float4*)&C[off + 4] = v1;
    }
}

// ---------------------------------------------------------------------------
// Row softmax over P: one CTA per row of 2048, in-place.
// ---------------------------------------------------------------------------
__global__ void __launch_bounds__(256)
softmax_kernel(float* __restrict__ P)
{
    __shared__ float smax[8];
    __shared__ float ssum[8];
    __shared__ float sbc[2];

    const int tid = threadIdx.x;
    float* p = P + (long)blockIdx.x * SEQ;

    float v[8];
#pragma unroll
    for (int j = 0; j < 8; j++) v[j] = p[tid + j * 256];

    float m = v[0];
#pragma unroll
    for (int j = 1; j < 8; j++) m = fmaxf(m, v[j]);
#pragma unroll
    for (int o = 16; o > 0; o >>= 1)
        m = fmaxf(m, __shfl_xor_sync(0xffffffffu, m, o));
    if ((tid & 31) == 0) smax[tid >> 5] = m;
    __syncthreads();
    if (tid == 0) {
        float t = smax[0];
#pragma unroll
        for (int w = 1; w < 8; w++) t = fmaxf(t, smax[w]);
        sbc[0] = t;
    }
    __syncthreads();
    m = sbc[0];

    float s = 0.0f;
#pragma unroll
    for (int j = 0; j < 8; j++) {
        v[j] = __expf(v[j] - m);
        s += v[j];
    }
#pragma unroll
    for (int o = 16; o > 0; o >>= 1)
        s += __shfl_xor_sync(0xffffffffu, s, o);
    if ((tid & 31) == 0) ssum[tid >> 5] = s;
    __syncthreads();
    if (tid == 0) {
        float t = ssum[0];
#pragma unroll
        for (int w = 1; w < 8; w++) t += ssum[w];
        sbc[1] = t;
    }
    __syncthreads();
    const float inv = 1.0f / sbc[1];

#pragma unroll
    for (int j = 0; j < 8; j++) p[tid + j * 256] = v[j] * inv;
}

// ---------------------------------------------------------------------------
extern "C" void kernel_launch(void* const* d_in, const int* in_sizes, int n_in,
                              void* d_out, int out_size)
{
    const float* x  = (const float*)d_in[0];
    const float* Wq = (const float*)d_in[1];
    const float* bq = (const float*)d_in[2];
    const float* Wk = (const float*)d_in[3];
    const float* bk = (const float*)d_in[4];
    const float* Wv = (const float*)d_in[5];
    const float* bv = (const float*)d_in[6];
    const float* Wo = (const float*)d_in[7];
    const float* bo = (const float*)d_in[8];
    float* out = (float*)d_out;

    float *Q, *K, *V, *P, *C;
    cudaGetSymbolAddress((void**)&Q, g_Q);
    cudaGetSymbolAddress((void**)&K, g_K);
    cudaGetSymbolAddress((void**)&V, g_V);
    cudaGetSymbolAddress((void**)&P, g_P);
    cudaGetSymbolAddress((void**)&C, g_C);

    const int  M    = BSZ * SEQ;               // 16384
    const float scl = 1.0f / sqrtf((float)EMB);
    dim3 blk(256);

    // QKV projections: [16384,768] = x @ W + b
    dim3 gProj(EMB / 128, M / 128, 1);         // (6,128)
    sgemm_kernel<false, true><<<gProj, blk>>>(x, Wq, bq, Q, M, EMB, EMB, 1.0f, 0, 0, 0);
    sgemm_kernel<false, true><<<gProj, blk>>>(x, Wk, bk, K, M, EMB, EMB, 1.0f, 0, 0, 0);
    sgemm_kernel<false, true><<<gProj, blk>>>(x, Wv, bv, V, M, EMB, EMB, 1.0f, 0, 0, 0);

    // scores = Q @ K^T * (1/sqrt(E)) per batch: [2048,2048], K=768
    dim3 gScore(SEQ / 128, SEQ / 128, BSZ);    // (16,16,8)
    sgemm_kernel<true, false><<<gScore, blk>>>(Q, K, nullptr, P, SEQ, SEQ, EMB, scl,
                                               (long)SEQ * EMB, (long)SEQ * EMB,
                                               (long)SEQ * SEQ);

    // row softmax in-place
    softmax_kernel<<<BSZ * SEQ, 256>>>(P);

    // ctx = P @ V per batch: [2048,768], K=2048
    dim3 gCtx(EMB / 128, SEQ / 128, BSZ);      // (6,16,8)
    sgemm_kernel<false, false><<<gCtx, blk>>>(P, V, nullptr, C, SEQ, EMB, SEQ, 1.0f,
                                              (long)SEQ * SEQ, (long)SEQ * EMB,
                                              (long)SEQ * EMB);

    // out = ctx @ Wo + bo : [16384,768]
    sgemm_kernel<false, true><<<gProj, blk>>>(C, Wo, bo, out, M, EMB, EMB, 1.0f, 0, 0, 0);
}

// round 3
// speedup vs baseline: 2.0495x; 2.0495x over previous
#include <cuda_runtime.h>
#include <cuda_bf16.h>
#include <math.h>
#include <stdint.h>

#define BSZ 8
#define SEQ 2048
#define EMB 768
#define MROWS (BSZ*SEQ)

// ---------------------------------------------------------------------------
// Scratch (device globals; allocation forbidden in kernel_launch)
// ---------------------------------------------------------------------------
__device__ __nv_bfloat16 g_xh[MROWS*EMB], g_xl[MROWS*EMB];
__device__ __nv_bfloat16 g_Wqh[EMB*EMB], g_Wql[EMB*EMB];
__device__ __nv_bfloat16 g_Wkh[EMB*EMB], g_Wkl[EMB*EMB];
__device__ __nv_bfloat16 g_Wvh[EMB*EMB], g_Wvl[EMB*EMB];
__device__ __nv_bfloat16 g_Woh[EMB*EMB], g_Wol[EMB*EMB];
__device__ __nv_bfloat16 g_Qh[MROWS*EMB], g_Ql[MROWS*EMB];
__device__ __nv_bfloat16 g_Kh[MROWS*EMB], g_Kl[MROWS*EMB];
__device__ __nv_bfloat16 g_Vth[MROWS*EMB], g_Vtl[MROWS*EMB];   // V^T: [B, E, S]
__device__ float         g_P[(size_t)BSZ*SEQ*SEQ];             // fp32 scores
__device__ __nv_bfloat16 g_Ph[(size_t)BSZ*SEQ*SEQ], g_Pl[(size_t)BSZ*SEQ*SEQ];
__device__ __nv_bfloat16 g_Ch[MROWS*EMB], g_Cl[MROWS*EMB];

// ---------------------------------------------------------------------------
// helpers
// ---------------------------------------------------------------------------
__device__ __forceinline__ uint32_t smem_u32(const void* p) {
    uint32_t a;
    asm("{ .reg .u64 t; cvta.to.shared.u64 t, %1; cvt.u32.u64 %0, t; }" : "=r"(a) : "l"(p));
    return a;
}
__device__ __forceinline__ void cpasync16(uint32_t s, const void* g) {
    asm volatile("cp.async.cg.shared.global [%0], [%1], 16;" :: "r"(s), "l"(g));
}
__device__ __forceinline__ void cp_commit() { asm volatile("cp.async.commit_group;"); }
__device__ __forceinline__ void cp_wait1()  { asm volatile("cp.async.wait_group 1;"); }
__device__ __forceinline__ void cp_wait0()  { asm volatile("cp.async.wait_group 0;"); }

__device__ __forceinline__ void ldm_x4(uint32_t (&r)[4], uint32_t a) {
    asm volatile("ldmatrix.sync.aligned.m8n8.x4.shared.b16 {%0,%1,%2,%3}, [%4];"
        : "=r"(r[0]), "=r"(r[1]), "=r"(r[2]), "=r"(r[3]) : "r"(a));
}
__device__ __forceinline__ void mma16816(float (&d)[4], const uint32_t (&a)[4],
                                         uint32_t b0, uint32_t b1) {
    asm volatile("mma.sync.aligned.m16n8k16.row.col.f32.bf16.bf16.f32 "
        "{%0,%1,%2,%3}, {%4,%5,%6,%7}, {%8,%9}, {%0,%1,%2,%3};"
        : "+f"(d[0]), "+f"(d[1]), "+f"(d[2]), "+f"(d[3])
        : "r"(a[0]), "r"(a[1]), "r"(a[2]), "r"(a[3]), "r"(b0), "r"(b1));
}
__device__ __forceinline__ void split_bf(float v, __nv_bfloat16& h, __nv_bfloat16& l) {
    h = __float2bfloat16(v);
    l = __float2bfloat16(v - __bfloat162float(h));
}
__device__ __forceinline__ uint32_t pack_bf2(__nv_bfloat16 a, __nv_bfloat16 b) {
    __nv_bfloat162 t(a, b);
    return *reinterpret_cast<uint32_t*>(&t);
}

// ---------------------------------------------------------------------------
// Split-bf16 warp-MMA GEMM: D[m,n] = sum_k A[m,k]*B[n,k]  (both K-major)
// D = Ah*Bh + Ah*Bl + Al*Bh, fp32 accumulate.
// CTA tile 128x128, K-chunk 32, 8 warps (warp tile 32x64), cp.async 2-stage.
// MODE 0: fp32 out (+bias). MODE 1: split hi/lo out ((acc+bias)*scale).
// MODE 2: split hi/lo, transposed per batch (V^T [b][e][s]); rows m = b*SEQ+s.
// ---------------------------------------------------------------------------
#define ROWB   144                     // padded row: 72 bf16 = 144 bytes
#define TILEB  (128*ROWB)              // 18432 bytes per matrix tile
#define OFF_AH 0
#define OFF_AL (TILEB)
#define OFF_BH (2*TILEB)
#define OFF_BL (3*TILEB)
#define STAGEB (4*TILEB)               // 73728
#define SMEMB  (2*STAGEB)              // 147456

template <int MODE>
__global__ void __launch_bounds__(256, 1)
gemm_mma(const __nv_bfloat16* __restrict__ Ah, const __nv_bfloat16* __restrict__ Al,
         const __nv_bfloat16* __restrict__ Bh, const __nv_bfloat16* __restrict__ Bl,
         int K, long ldA, long ldB, long sAb, long sBb,
         float* __restrict__ outF,
         __nv_bfloat16* __restrict__ outHi, __nv_bfloat16* __restrict__ outLo,
         const float* __restrict__ bias, float scale, long ldOut, long obs)
{
    extern __shared__ char smem[];
    const uint32_t sb = smem_u32(smem);

    const int tid    = threadIdx.x;
    const int lane   = tid & 31;
    const int wid    = tid >> 5;
    const int warp_m = wid & 3;        // 4 warps over M (32 rows each)
    const int warp_n = wid >> 2;       // 2 warps over N (64 cols each)
    const int by     = blockIdx.y * 128;
    const int bx     = blockIdx.x * 128;
    const int bz     = blockIdx.z;

    Ah += (long)bz * sAb;  Al += (long)bz * sAb;
    Bh += (long)bz * sBb;  Bl += (long)bz * sBb;

    // loader mapping: 512 16B-chunks per tile, 2 per thread
    const int lr0 = tid >> 2;          // row for e = tid
    const int lg0 = tid & 3;           // 16B group
    const int lr1 = (tid + 256) >> 2;
    const int lg1 = (tid + 256) & 3;

    auto load_chunk = [&](int kc, int stage) {
        const long kk = (long)kc * 32;
        const uint32_t s0 = sb + stage * STAGEB;
        const __nv_bfloat16* srcs[4] = {Ah, Al, Bh, Bl};
        const long lds[4]  = {ldA, ldA, ldB, ldB};
        const int  r0s[4]  = {by, by, bx, bx};
#pragma unroll
        for (int m = 0; m < 4; ++m) {
            const uint32_t sm = s0 + m * TILEB;
            cpasync16(sm + lr0 * ROWB + lg0 * 16,
                      srcs[m] + (long)(r0s[m] + lr0) * lds[m] + kk + lg0 * 8);
            cpasync16(sm + lr1 * ROWB + lg1 * 16,
                      srcs[m] + (long)(r0s[m] + lr1) * lds[m] + kk + lg1 * 8);
        }
    };

    float acc[2][8][4];
#pragma unroll
    for (int i = 0; i < 2; ++i)
#pragma unroll
        for (int j = 0; j < 8; ++j)
#pragma unroll
            for (int e = 0; e < 4; ++e) acc[i][j][e] = 0.f;

    const int nChunks = K >> 5;

    load_chunk(0, 0);
    cp_commit();

    // per-lane ldmatrix address pieces
    const int rl = lane & 7;
    const int gq = lane >> 3;
    // A: mat0 rows 0-7 k0-7 | mat1 rows 8-15 k0-7 | mat2 rows 0-7 k8-15 | mat3 rows 8-15 k8-15
    const uint32_t aoff = (uint32_t)((warp_m * 32 + (gq & 1) * 8 + rl) * ROWB + (gq >> 1) * 16);
    // B: mat0 n0-7 k0-7 | mat1 n0-7 k8-15 | mat2 n8-15 k0-7 | mat3 n8-15 k8-15
    const uint32_t boff = (uint32_t)((warp_n * 64 + (gq >> 1) * 8 + rl) * ROWB + (gq & 1) * 16);

    for (int kc = 0; kc < nChunks; ++kc) {
        const int s = kc & 1;
        if (kc + 1 < nChunks) {
            load_chunk(kc + 1, s ^ 1);
            cp_commit();
            cp_wait1();
        } else {
            cp_wait0();
        }
        __syncthreads();

        const uint32_t st = sb + s * STAGEB;
#pragma unroll
        for (int ks = 0; ks < 2; ++ks) {
            const uint32_t kb = ks * 32;   // 16 bf16 = 32 bytes
            uint32_t ah[2][4], al[2][4];
#pragma unroll
            for (int i = 0; i < 2; ++i) {
                ldm_x4(ah[i], st + OFF_AH + aoff + i * (16 * ROWB) + kb);
                ldm_x4(al[i], st + OFF_AL + aoff + i * (16 * ROWB) + kb);
            }
            uint32_t bh[4][4], bl[4][4];
#pragma unroll
            for (int g = 0; g < 4; ++g) {
                ldm_x4(bh[g], st + OFF_BH + boff + g * (16 * ROWB) + kb);
                ldm_x4(bl[g], st + OFF_BL + boff + g * (16 * ROWB) + kb);
            }
#pragma unroll
            for (int i = 0; i < 2; ++i)
#pragma unroll
                for (int j = 0; j < 8; ++j) {
                    const int g = j >> 1, o = (j & 1) * 2;
                    mma16816(acc[i][j], ah[i], bh[g][o], bh[g][o + 1]);
                    mma16816(acc[i][j], ah[i], bl[g][o], bl[g][o + 1]);
                    mma16816(acc[i][j], al[i], bh[g][o], bh[g][o + 1]);
                }
        }
        __syncthreads();
    }

    // ---------------- epilogue ----------------
    const int r_in  = lane >> 2;         // 0..7
    const int c_in  = (lane & 3) * 2;    // 0,2,4,6

#pragma unroll
    for (int i = 0; i < 2; ++i) {
#pragma unroll
        for (int j = 0; j < 8; ++j) {
            const int row0 = by + warp_m * 32 + i * 16 + r_in;   // d0,d1
            const int row1 = row0 + 8;                           // d2,d3
            const int col  = bx + warp_n * 64 + j * 8 + c_in;

            if (MODE == 0) {
                float b0 = bias ? bias[col]     : 0.f;
                float b1 = bias ? bias[col + 1] : 0.f;
                float2 v0 = make_float2(acc[i][j][0] + b0, acc[i][j][1] + b1);
                float2 v1 = make_float2(acc[i][j][2] + b0, acc[i][j][3] + b1);
                *reinterpret_cast<float2*>(outF + (long)bz * obs + (long)row0 * ldOut + col) = v0;
                *reinterpret_cast<float2*>(outF + (long)bz * obs + (long)row1 * ldOut + col) = v1;
            } else if (MODE == 1) {
                float b0 = bias ? bias[col]     : 0.f;
                float b1 = bias ? bias[col + 1] : 0.f;
                float v00 = (acc[i][j][0] + b0) * scale, v01 = (acc[i][j][1] + b1) * scale;
                float v10 = (acc[i][j][2] + b0) * scale, v11 = (acc[i][j][3] + b1) * scale;
                __nv_bfloat16 h0, l0, h1, l1;
                split_bf(v00, h0, l0); split_bf(v01, h1, l1);
                const long o0 = (long)bz * obs + (long)row0 * ldOut + col;
                *reinterpret_cast<uint32_t*>(outHi + o0) = pack_bf2(h0, h1);
                *reinterpret_cast<uint32_t*>(outLo + o0) = pack_bf2(l0, l1);
                split_bf(v10, h0, l0); split_bf(v11, h1, l1);
                const long o1 = (long)bz * obs + (long)row1 * ldOut + col;
                *reinterpret_cast<uint32_t*>(outHi + o1) = pack_bf2(h0, h1);
                *reinterpret_cast<uint32_t*>(outLo + o1) = pack_bf2(l0, l1);
            } else {  // MODE 2: V^T scatter, rows m = b*SEQ + s ; out[b][e][s]
                float b0 = bias ? bias[col]     : 0.f;
                float b1 = bias ? bias[col + 1] : 0.f;
#pragma unroll
                for (int e = 0; e < 4; ++e) {
                    const int row = (e < 2) ? row0 : row1;
                    const int cc  = col + (e & 1);
                    const float v = acc[i][j][e] + ((e & 1) ? b1 : b0);
                    __nv_bfloat16 h, l;
                    split_bf(v, h, l);
                    const long a = (long)(row >> 11) * ((long)EMB * SEQ)
                                 + (long)cc * SEQ + (row & 2047);
                    outHi[a] = h;
                    outLo[a] = l;
                }
            }
        }
    }
}

// ---------------------------------------------------------------------------
// Elementwise split: fp32 -> (hi, lo) bf16, 4 elems/thread
// ---------------------------------------------------------------------------
__global__ void split2d(const float4* __restrict__ in,
                        __nv_bfloat16* __restrict__ oh, __nv_bfloat16* __restrict__ ol,
                        int n4)
{
    const int i = blockIdx.x * blockDim.x + threadIdx.x;
    if (i >= n4) return;
    const float4 v = in[i];
    __nv_bfloat16 h0, l0, h1, l1, h2, l2, h3, l3;
    split_bf(v.x, h0, l0); split_bf(v.y, h1, l1);
    split_bf(v.z, h2, l2); split_bf(v.w, h3, l3);
    uint2 H, L;
    H.x = pack_bf2(h0, h1); H.y = pack_bf2(h2, h3);
    L.x = pack_bf2(l0, l1); L.y = pack_bf2(l2, l3);
    *reinterpret_cast<uint2*>(oh + 4 * (long)i) = H;
    *reinterpret_cast<uint2*>(ol + 4 * (long)i) = L;
}

// ---------------------------------------------------------------------------
// Weight transpose + split: W[K,N] fp32 -> Wt hi/lo [N,K] bf16
// ---------------------------------------------------------------------------
__global__ void wsplit(const float* __restrict__ W,
                       __nv_bfloat16* __restrict__ oh, __nv_bfloat16* __restrict__ ol)
{
    __shared__ float t[32][33];
    const int n0 = blockIdx.x * 32, k0 = blockIdx.y * 32;
    const int tx = threadIdx.x, ty = threadIdx.y;
#pragma unroll
    for (int i = 0; i < 32; i += 8)
        t[ty + i][tx] = W[(long)(k0 + ty + i) * EMB + n0 + tx];
    __syncthreads();
#pragma unroll
    for (int i = 0; i < 32; i += 8) {
        __nv_bfloat16 h, l;
        split_bf(t[tx][ty + i], h, l);
        const long o = (long)(n0 + ty + i) * EMB + k0 + tx;
        oh[o] = h;
        ol[o] = l;
    }
}

// ---------------------------------------------------------------------------
// Row softmax over fp32 P, emitting split bf16 hi/lo
// ---------------------------------------------------------------------------
__global__ void __launch_bounds__(256)
softmax_split(const float* __restrict__ P,
              __nv_bfloat16* __restrict__ Ph, __nv_bfloat16* __restrict__ Pl)
{
    __shared__ float sred[8];
    __shared__ float sbc[2];
    const int tid = threadIdx.x;
    const long base = (long)blockIdx.x * SEQ;

    float v[8];
#pragma unroll
    for (int j = 0; j < 8; j++) v[j] = P[base + tid + j * 256];

    float m = v[0];
#pragma unroll
    for (int j = 1; j < 8; j++) m = fmaxf(m, v[j]);
#pragma unroll
    for (int o = 16; o > 0; o >>= 1) m = fmaxf(m, __shfl_xor_sync(0xffffffffu, m, o));
    if ((tid & 31) == 0) sred[tid >> 5] = m;
    __syncthreads();
    if (tid == 0) {
        float t = sred[0];
#pragma unroll
        for (int w = 1; w < 8; w++) t = fmaxf(t, sred[w]);
        sbc[0] = t;
    }
    __syncthreads();
    m = sbc[0];

    float s = 0.f;
#pragma unroll
    for (int j = 0; j < 8; j++) { v[j] = __expf(v[j] - m); s += v[j]; }
#pragma unroll
    for (int o = 16; o > 0; o >>= 1) s += __shfl_xor_sync(0xffffffffu, s, o);
    __syncthreads();
    if ((tid & 31) == 0) sred[tid >> 5] = s;
    __syncthreads();
    if (tid == 0) {
        float t = sred[0];
#pragma unroll
        for (int w = 1; w < 8; w++) t += sred[w];
        sbc[1] = t;
    }
    __syncthreads();
    const float inv = 1.f / sbc[1];

#pragma unroll
    for (int j = 0; j < 8; j++) {
        __nv_bfloat16 h, l;
        split_bf(v[j] * inv, h, l);
        Ph[base + tid + j * 256] = h;
        Pl[base + tid + j * 256] = l;
    }
}

// ---------------------------------------------------------------------------
// Host side
// ---------------------------------------------------------------------------
extern "C" void kernel_launch(void* const* d_in, const int* in_sizes, int n_in,
                              void* d_out, int out_size)
{
    const float* x  = (const float*)d_in[0];
    const float* Wq = (const float*)d_in[1];
    const float* bq = (const float*)d_in[2];
    const float* Wk = (const float*)d_in[3];
    const float* bk = (const float*)d_in[4];
    const float* Wv = (const float*)d_in[5];
    const float* bv = (const float*)d_in[6];
    const float* Wo = (const float*)d_in[7];
    const float* bo = (const float*)d_in[8];
    float* out = (float*)d_out;

    void *xh, *xl, *Wqh, *Wql, *Wkh, *Wkl, *Wvh, *Wvl, *Woh, *Wol;
    void *Qh, *Ql, *Kh, *Kl, *Vth, *Vtl, *Pf, *Ph, *Pl, *Ch, *Cl;
    cudaGetSymbolAddress(&xh, g_xh);   cudaGetSymbolAddress(&xl, g_xl);
    cudaGetSymbolAddress(&Wqh, g_Wqh); cudaGetSymbolAddress(&Wql, g_Wql);
    cudaGetSymbolAddress(&Wkh, g_Wkh); cudaGetSymbolAddress(&Wkl, g_Wkl);
    cudaGetSymbolAddress(&Wvh, g_Wvh); cudaGetSymbolAddress(&Wvl, g_Wvl);
    cudaGetSymbolAddress(&Woh, g_Woh); cudaGetSymbolAddress(&Wol, g_Wol);
    cudaGetSymbolAddress(&Qh, g_Qh);   cudaGetSymbolAddress(&Ql, g_Ql);
    cudaGetSymbolAddress(&Kh, g_Kh);   cudaGetSymbolAddress(&Kl, g_Kl);
    cudaGetSymbolAddress(&Vth, g_Vth); cudaGetSymbolAddress(&Vtl, g_Vtl);
    cudaGetSymbolAddress(&Pf, g_P);
    cudaGetSymbolAddress(&Ph, g_Ph);   cudaGetSymbolAddress(&Pl, g_Pl);
    cudaGetSymbolAddress(&Ch, g_Ch);   cudaGetSymbolAddress(&Cl, g_Cl);

    cudaFuncSetAttribute(gemm_mma<0>, cudaFuncAttributeMaxDynamicSharedMemorySize, SMEMB);
    cudaFuncSetAttribute(gemm_mma<1>, cudaFuncAttributeMaxDynamicSharedMemorySize, SMEMB);
    cudaFuncSetAttribute(gemm_mma<2>, cudaFuncAttributeMaxDynamicSharedMemorySize, SMEMB);

    const float scl = 1.0f / sqrtf((float)EMB);
    const dim3 blk(256);

    // 1) split inputs
    {
        const int n4 = MROWS * EMB / 4;
        split2d<<<(n4 + 255) / 256, 256>>>((const float4*)x, (__nv_bfloat16*)xh,
                                           (__nv_bfloat16*)xl, n4);
        dim3 wg(24, 24), wb(32, 8);
        wsplit<<<wg, wb>>>(Wq, (__nv_bfloat16*)Wqh, (__nv_bfloat16*)Wql);
        wsplit<<<wg, wb>>>(Wk, (__nv_bfloat16*)Wkh, (__nv_bfloat16*)Wkl);
        wsplit<<<wg, wb>>>(Wv, (__nv_bfloat16*)Wvh, (__nv_bfloat16*)Wvl);
        wsplit<<<wg, wb>>>(Wo, (__nv_bfloat16*)Woh, (__nv_bfloat16*)Wol);
    }

    // 2) projections: [16384,768] x [768,768]^T, K=768
    gemm_mma<1><<<dim3(6, 128, 1), blk, SMEMB>>>(
        (const __nv_bfloat16*)xh, (const __nv_bfloat16*)xl,
        (const __nv_bfloat16*)Wqh, (const __nv_bfloat16*)Wql,
        EMB, EMB, EMB, 0, 0,
        nullptr, (__nv_bfloat16*)Qh, (__nv_bfloat16*)Ql, bq, scl, EMB, 0);
    gemm_mma<1><<<dim3(6, 128, 1), blk, SMEMB>>>(
        (const __nv_bfloat16*)xh, (const __nv_bfloat16*)xl,
        (const __nv_bfloat16*)Wkh, (const __nv_bfloat16*)Wkl,
        EMB, EMB, EMB, 0, 0,
        nullptr, (__nv_bfloat16*)Kh, (__nv_bfloat16*)Kl, bk, 1.0f, EMB, 0);
    gemm_mma<2><<<dim3(6, 128, 1), blk, SMEMB>>>(
        (const __nv_bfloat16*)xh, (const __nv_bfloat16*)xl,
        (const __nv_bfloat16*)Wvh, (const __nv_bfloat16*)Wvl,
        EMB, EMB, EMB, 0, 0,
        nullptr, (__nv_bfloat16*)Vth, (__nv_bfloat16*)Vtl, bv, 1.0f, 0, 0);

    // 3) scores = Q' @ K^T (scale folded into Q), fp32 out
    gemm_mma<0><<<dim3(16, 16, 8), blk, SMEMB>>>(
        (const __nv_bfloat16*)Qh, (const __nv_bfloat16*)Ql,
        (const __nv_bfloat16*)Kh, (const __nv_bfloat16*)Kl,
        EMB, EMB, EMB, (long)SEQ * EMB, (long)SEQ * EMB,
        (float*)Pf, nullptr, nullptr, nullptr, 1.0f, SEQ, (long)SEQ * SEQ);

    // 4) softmax -> split P
    softmax_split<<<MROWS, 256>>>((const float*)Pf, (__nv_bfloat16*)Ph, (__nv_bfloat16*)Pl);

    // 5) ctx = P @ V : A = P [b,q,s], B = V^T [b,e,s], K=2048
    gemm_mma<1><<<dim3(6, 16, 8), blk, SMEMB>>>(
        (const __nv_bfloat16*)Ph, (const __nv_bfloat16*)Pl,
        (const __nv_bfloat16*)Vth, (const __nv_bfloat16*)Vtl,
        SEQ, SEQ, SEQ, (long)SEQ * SEQ, (long)EMB * SEQ,
        nullptr, (__nv_bfloat16*)Ch, (__nv_bfloat16*)Cl, nullptr, 1.0f, EMB, (long)SEQ * EMB);

    // 6) out = C @ Wo^T + bo, fp32
    gemm_mma<0><<<dim3(6, 128, 1), blk, SMEMB>>>(
        (const __nv_bfloat16*)Ch, (const __nv_bfloat16*)Cl,
        (const __nv_bfloat16*)Woh, (const __nv_bfloat16*)Wol,
        EMB, EMB, EMB, 0, 0,
        out, nullptr, nullptr, bo, 1.0f, EMB, 0);
}

// round 4
// speedup vs baseline: 3.0833x; 1.5044x over previous
#include <cuda_runtime.h>
#include <cuda_fp16.h>
#include <math.h>
#include <stdint.h>

#define BSZ 8
#define SEQ 2048
#define EMB 768
#define MROWS (BSZ*SEQ)

// ---------------------------------------------------------------------------
// Scratch (device globals; allocation forbidden in kernel_launch)
// ---------------------------------------------------------------------------
__device__ __align__(256) __half g_xh[MROWS*EMB], g_xl[MROWS*EMB];
__device__ __align__(256) __half g_Wqh[EMB*EMB], g_Wql[EMB*EMB];
__device__ __align__(256) __half g_Wkh[EMB*EMB], g_Wkl[EMB*EMB];
__device__ __align__(256) __half g_Wvh[EMB*EMB], g_Wvl[EMB*EMB];
__device__ __align__(256) __half g_Woh[EMB*EMB];
__device__ __align__(256) __half g_Qh[MROWS*EMB], g_Ql[MROWS*EMB];
__device__ __align__(256) __half g_Kh[MROWS*EMB];
__device__ __align__(256) __half g_Vth[MROWS*EMB];                 // V^T: [B,E,S]
__device__ __align__(256) float  g_P[(size_t)BSZ*SEQ*SEQ];         // fp32 scores
__device__ __align__(256) __half g_Ph[(size_t)BSZ*SEQ*SEQ], g_Pl[(size_t)BSZ*SEQ*SEQ];
__device__ __align__(256) __half g_Ch[MROWS*EMB], g_Cl[MROWS*EMB];

#define P_SCALE 1024.0f

// ---------------------------------------------------------------------------
// helpers
// ---------------------------------------------------------------------------
__device__ __forceinline__ uint32_t smem_u32(const void* p) {
    uint32_t a;
    asm("{ .reg .u64 t; cvta.to.shared.u64 t, %1; cvt.u32.u64 %0, t; }" : "=r"(a) : "l"(p));
    return a;
}
__device__ __forceinline__ void cpasync16(uint32_t s, const void* g) {
    asm volatile("cp.async.cg.shared.global [%0], [%1], 16;" :: "r"(s), "l"(g));
}
__device__ __forceinline__ void cp_commit() { asm volatile("cp.async.commit_group;"); }
__device__ __forceinline__ void cp_wait1()  { asm volatile("cp.async.wait_group 1;"); }
__device__ __forceinline__ void cp_wait0()  { asm volatile("cp.async.wait_group 0;"); }

__device__ __forceinline__ void ldm_x4(uint32_t (&r)[4], uint32_t a) {
    asm volatile("ldmatrix.sync.aligned.m8n8.x4.shared.b16 {%0,%1,%2,%3}, [%4];"
        : "=r"(r[0]), "=r"(r[1]), "=r"(r[2]), "=r"(r[3]) : "r"(a));
}
__device__ __forceinline__ void mma16816(float (&d)[4], const uint32_t (&a)[4],
                                         uint32_t b0, uint32_t b1) {
    asm volatile("mma.sync.aligned.m16n8k16.row.col.f32.f16.f16.f32 "
        "{%0,%1,%2,%3}, {%4,%5,%6,%7}, {%8,%9}, {%0,%1,%2,%3};"
        : "+f"(d[0]), "+f"(d[1]), "+f"(d[2]), "+f"(d[3])
        : "r"(a[0]), "r"(a[1]), "r"(a[2]), "r"(a[3]), "r"(b0), "r"(b1));
}
__device__ __forceinline__ void split_h(float v, __half& h, __half& l) {
    h = __float2half_rn(v);
    l = __float2half_rn(v - __half2float(h));
}
__device__ __forceinline__ uint32_t pack_h2(__half a, __half b) {
    __half2 t(a, b);
    return *reinterpret_cast<uint32_t*>(&t);
}

// ---------------------------------------------------------------------------
// Split-fp16 warp-MMA GEMM: D[m,n] = sum_k A[m,k]*B[n,k]  (both K-major)
// NTERMS=2: D = Ah*Bh + Al*Bh           (B hi only)
// NTERMS=3: D = Ah*Bh + Al*Bh + Ah*Bl
// CTA tile 128x128, K-chunk 32, 8 warps (32x64 each), cp.async 2-stage.
// MODE 0: fp32 out (+bias). MODE 1: split hi/lo ((acc+bias)*scale).
// MODE 2: hi-only ((acc+bias)*scale). MODE 3: hi-only, V^T scatter (+bias).
// ---------------------------------------------------------------------------
#define ROWB   80                       // padded row: 64B data + 16B pad
#define TILEB  (128*ROWB)               // 10240 B

template <int MODE, int NTERMS>
__global__ void __launch_bounds__(256, 2)
gemm_mma(const __half* __restrict__ Ah, const __half* __restrict__ Al,
         const __half* __restrict__ Bh, const __half* __restrict__ Bl,
         int K, long ldA, long ldB, long sAb, long sBb,
         float* __restrict__ outF,
         __half* __restrict__ outHi, __half* __restrict__ outLo,
         const float* __restrict__ bias, float scale, long ldOut, long obs)
{
    constexpr int NT     = (NTERMS == 3) ? 4 : 3;   // tiles per stage
    constexpr int STAGEB = NT * TILEB;

    extern __shared__ char smem[];
    const uint32_t sb = smem_u32(smem);

    const int tid    = threadIdx.x;
    const int lane   = tid & 31;
    const int wid    = tid >> 5;
    const int warp_m = wid & 3;
    const int warp_n = wid >> 2;
    const int by     = blockIdx.y * 128;
    const int bx     = blockIdx.x * 128;
    const int bz     = blockIdx.z;

    Ah += (long)bz * sAb;  Al += (long)bz * sAb;
    Bh += (long)bz * sBb;
    if (NTERMS == 3) Bl += (long)bz * sBb;

    const int lr0 = tid >> 2;
    const int lg0 = tid & 3;
    const int lr1 = (tid + 256) >> 2;
    const int lg1 = (tid + 256) & 3;

    auto load_chunk = [&](int kc, int stage) {
        const long kk = (long)kc * 32;
        const uint32_t s0 = sb + stage * STAGEB;
        const __half* srcs[4] = {Ah, Al, Bh, (NTERMS == 3) ? Bl : Bh};
        const long lds[4]  = {ldA, ldA, ldB, ldB};
        const int  r0s[4]  = {by, by, bx, bx};
#pragma unroll
        for (int m = 0; m < NT; ++m) {
            const uint32_t sm = s0 + m * TILEB;
            cpasync16(sm + lr0 * ROWB + lg0 * 16,
                      srcs[m] + (long)(r0s[m] + lr0) * lds[m] + kk + lg0 * 8);
            cpasync16(sm + lr1 * ROWB + lg1 * 16,
                      srcs[m] + (long)(r0s[m] + lr1) * lds[m] + kk + lg1 * 8);
        }
    };

    float acc[2][8][4];
#pragma unroll
    for (int i = 0; i < 2; ++i)
#pragma unroll
        for (int j = 0; j < 8; ++j)
#pragma unroll
            for (int e = 0; e < 4; ++e) acc[i][j][e] = 0.f;

    const int nChunks = K >> 5;

    load_chunk(0, 0);
    cp_commit();

    const int rl = lane & 7;
    const int gq = lane >> 3;
    const uint32_t aoff = (uint32_t)((warp_m * 32 + (gq & 1) * 8 + rl) * ROWB + (gq >> 1) * 16);
    const uint32_t boff = (uint32_t)((warp_n * 64 + (gq >> 1) * 8 + rl) * ROWB + (gq & 1) * 16);

    for (int kc = 0; kc < nChunks; ++kc) {
        const int s = kc & 1;
        if (kc + 1 < nChunks) {
            load_chunk(kc + 1, s ^ 1);
            cp_commit();
            cp_wait1();
        } else {
            cp_wait0();
        }
        __syncthreads();

        const uint32_t st = sb + s * STAGEB;
#pragma unroll
        for (int ks = 0; ks < 2; ++ks) {
            const uint32_t kb = ks * 32;
            uint32_t ah[2][4], al[2][4];
#pragma unroll
            for (int i = 0; i < 2; ++i) {
                ldm_x4(ah[i], st + 0 * TILEB + aoff + i * (16 * ROWB) + kb);
                ldm_x4(al[i], st + 1 * TILEB + aoff + i * (16 * ROWB) + kb);
            }
            uint32_t bh[4][4];
#pragma unroll
            for (int g = 0; g < 4; ++g)
                ldm_x4(bh[g], st + 2 * TILEB + boff + g * (16 * ROWB) + kb);
#pragma unroll
            for (int i = 0; i < 2; ++i)
#pragma unroll
                for (int j = 0; j < 8; ++j) {
                    const int g = j >> 1, o = (j & 1) * 2;
                    mma16816(acc[i][j], ah[i], bh[g][o], bh[g][o + 1]);
                    mma16816(acc[i][j], al[i], bh[g][o], bh[g][o + 1]);
                }
            if (NTERMS == 3) {
                uint32_t bl[4][4];
#pragma unroll
                for (int g = 0; g < 4; ++g)
                    ldm_x4(bl[g], st + 3 * TILEB + boff + g * (16 * ROWB) + kb);
#pragma unroll
                for (int i = 0; i < 2; ++i)
#pragma unroll
                    for (int j = 0; j < 8; ++j) {
                        const int g = j >> 1, o = (j & 1) * 2;
                        mma16816(acc[i][j], ah[i], bl[g][o], bl[g][o + 1]);
                    }
            }
        }
        __syncthreads();
    }

    // ---------------- epilogue ----------------
    const int r_in = lane >> 2;
    const int c_in = (lane & 3) * 2;

#pragma unroll
    for (int i = 0; i < 2; ++i) {
#pragma unroll
        for (int j = 0; j < 8; ++j) {
            const int row0 = by + warp_m * 32 + i * 16 + r_in;
            const int row1 = row0 + 8;
            const int col  = bx + warp_n * 64 + j * 8 + c_in;
            const float b0 = bias ? bias[col]     : 0.f;
            const float b1 = bias ? bias[col + 1] : 0.f;

            if (MODE == 0) {
                float2 v0 = make_float2(acc[i][j][0] + b0, acc[i][j][1] + b1);
                float2 v1 = make_float2(acc[i][j][2] + b0, acc[i][j][3] + b1);
                *reinterpret_cast<float2*>(outF + (long)bz * obs + (long)row0 * ldOut + col) = v0;
                *reinterpret_cast<float2*>(outF + (long)bz * obs + (long)row1 * ldOut + col) = v1;
            } else if (MODE == 1) {
                float v00 = (acc[i][j][0] + b0) * scale, v01 = (acc[i][j][1] + b1) * scale;
                float v10 = (acc[i][j][2] + b0) * scale, v11 = (acc[i][j][3] + b1) * scale;
                __half h0, l0, h1, l1;
                split_h(v00, h0, l0); split_h(v01, h1, l1);
                const long o0 = (long)bz * obs + (long)row0 * ldOut + col;
                *reinterpret_cast<uint32_t*>(outHi + o0) = pack_h2(h0, h1);
                *reinterpret_cast<uint32_t*>(outLo + o0) = pack_h2(l0, l1);
                split_h(v10, h0, l0); split_h(v11, h1, l1);
                const long o1 = (long)bz * obs + (long)row1 * ldOut + col;
                *reinterpret_cast<uint32_t*>(outHi + o1) = pack_h2(h0, h1);
                *reinterpret_cast<uint32_t*>(outLo + o1) = pack_h2(l0, l1);
            } else if (MODE == 2) {
                float v00 = (acc[i][j][0] + b0) * scale, v01 = (acc[i][j][1] + b1) * scale;
                float v10 = (acc[i][j][2] + b0) * scale, v11 = (acc[i][j][3] + b1) * scale;
                const long o0 = (long)bz * obs + (long)row0 * ldOut + col;
                const long o1 = (long)bz * obs + (long)row1 * ldOut + col;
                *reinterpret_cast<uint32_t*>(outHi + o0) =
                    pack_h2(__float2half_rn(v00), __float2half_rn(v01));
                *reinterpret_cast<uint32_t*>(outHi + o1) =
                    pack_h2(__float2half_rn(v10), __float2half_rn(v11));
            } else {  // MODE 3: V^T scatter, rows m = b*SEQ + s ; out[b][e][s]
#pragma unroll
                for (int e = 0; e < 4; ++e) {
                    const int row = (e < 2) ? row0 : row1;
                    const int cc  = col + (e & 1);
                    const float v = acc[i][j][e] + ((e & 1) ? b1 : b0);
                    const long a = (long)(row >> 11) * ((long)EMB * SEQ)
                                 + (long)cc * SEQ + (row & 2047);
                    outHi[a] = __float2half_rn(v);
                }
            }
        }
    }
}

// ---------------------------------------------------------------------------
// Elementwise split: fp32 -> (hi, lo) fp16
// ---------------------------------------------------------------------------
__global__ void split2d(const float4* __restrict__ in,
                        __half* __restrict__ oh, __half* __restrict__ ol, int n4)
{
    const int i = blockIdx.x * blockDim.x + threadIdx.x;
    if (i >= n4) return;
    const float4 v = in[i];
    __half h0, l0, h1, l1, h2, l2, h3, l3;
    split_h(v.x, h0, l0); split_h(v.y, h1, l1);
    split_h(v.z, h2, l2); split_h(v.w, h3, l3);
    uint2 H, L;
    H.x = pack_h2(h0, h1); H.y = pack_h2(h2, h3);
    L.x = pack_h2(l0, l1); L.y = pack_h2(l2, l3);
    *reinterpret_cast<uint2*>(oh + 4 * (long)i) = H;
    *reinterpret_cast<uint2*>(ol + 4 * (long)i) = L;
}

// ---------------------------------------------------------------------------
// Weight transpose + split: W[K,N] fp32 -> Wt hi/lo [N,K] fp16 (lo optional)
// ---------------------------------------------------------------------------
__global__ void wsplit(const float* __restrict__ W,
                       __half* __restrict__ oh, __half* __restrict__ ol)
{
    __shared__ float t[32][33];
    const int n0 = blockIdx.x * 32, k0 = blockIdx.y * 32;
    const int tx = threadIdx.x, ty = threadIdx.y;
#pragma unroll
    for (int i = 0; i < 32; i += 8)
        t[ty + i][tx] = W[(long)(k0 + ty + i) * EMB + n0 + tx];
    __syncthreads();
#pragma unroll
    for (int i = 0; i < 32; i += 8) {
        __half h, l;
        split_h(t[tx][ty + i], h, l);
        const long o = (long)(n0 + ty + i) * EMB + k0 + tx;
        oh[o] = h;
        if (ol) ol[o] = l;
    }
}

// ---------------------------------------------------------------------------
// Row softmax over fp32 P, emitting split fp16 hi/lo scaled by P_SCALE
// ---------------------------------------------------------------------------
__global__ void __launch_bounds__(256)
softmax_split(const float* __restrict__ P,
              __half* __restrict__ Ph, __half* __restrict__ Pl)
{
    __shared__ float sred[8];
    __shared__ float sbc[2];
    const int tid = threadIdx.x;
    const long base = (long)blockIdx.x * SEQ;

    float v[8];
#pragma unroll
    for (int j = 0; j < 8; j++) v[j] = P[base + tid + j * 256];

    float m = v[0];
#pragma unroll
    for (int j = 1; j < 8; j++) m = fmaxf(m, v[j]);
#pragma unroll
    for (int o = 16; o > 0; o >>= 1) m = fmaxf(m, __shfl_xor_sync(0xffffffffu, m, o));
    if ((tid & 31) == 0) sred[tid >> 5] = m;
    __syncthreads();
    if (tid == 0) {
        float t = sred[0];
#pragma unroll
        for (int w = 1; w < 8; w++) t = fmaxf(t, sred[w]);
        sbc[0] = t;
    }
    __syncthreads();
    m = sbc[0];

    float s = 0.f;
#pragma unroll
    for (int j = 0; j < 8; j++) { v[j] = __expf(v[j] - m); s += v[j]; }
#pragma unroll
    for (int o = 16; o > 0; o >>= 1) s += __shfl_xor_sync(0xffffffffu, s, o);
    __syncthreads();
    if ((tid & 31) == 0) sred[tid >> 5] = s;
    __syncthreads();
    if (tid == 0) {
        float t = sred[0];
#pragma unroll
        for (int w = 1; w < 8; w++) t += sred[w];
        sbc[1] = t;
    }
    __syncthreads();
    const float inv = P_SCALE / sbc[1];

#pragma unroll
    for (int j = 0; j < 8; j++) {
        __half h, l;
        split_h(v[j] * inv, h, l);
        Ph[base + tid + j * 256] = h;
        Pl[base + tid + j * 256] = l;
    }
}

// ---------------------------------------------------------------------------
// Host side
// ---------------------------------------------------------------------------
extern "C" void kernel_launch(void* const* d_in, const int* in_sizes, int n_in,
                              void* d_out, int out_size)
{
    const float* x  = (const float*)d_in[0];
    const float* Wq = (const float*)d_in[1];
    const float* bq = (const float*)d_in[2];
    const float* Wk = (const float*)d_in[3];
    const float* bk = (const float*)d_in[4];
    const float* Wv = (const float*)d_in[5];
    const float* bv = (const float*)d_in[6];
    const float* Wo = (const float*)d_in[7];
    const float* bo = (const float*)d_in[8];
    float* out = (float*)d_out;

    void *xh, *xl, *Wqh, *Wql, *Wkh, *Wkl, *Wvh, *Wvl, *Woh;
    void *Qh, *Ql, *Kh, *Vth, *Pf, *Ph, *Pl, *Ch, *Cl;
    cudaGetSymbolAddress(&xh, g_xh);   cudaGetSymbolAddress(&xl, g_xl);
    cudaGetSymbolAddress(&Wqh, g_Wqh); cudaGetSymbolAddress(&Wql, g_Wql);
    cudaGetSymbolAddress(&Wkh, g_Wkh); cudaGetSymbolAddress(&Wkl, g_Wkl);
    cudaGetSymbolAddress(&Wvh, g_Wvh); cudaGetSymbolAddress(&Wvl, g_Wvl);
    cudaGetSymbolAddress(&Woh, g_Woh);
    cudaGetSymbolAddress(&Qh, g_Qh);   cudaGetSymbolAddress(&Ql, g_Ql);
    cudaGetSymbolAddress(&Kh, g_Kh);
    cudaGetSymbolAddress(&Vth, g_Vth);
    cudaGetSymbolAddress(&Pf, g_P);
    cudaGetSymbolAddress(&Ph, g_Ph);   cudaGetSymbolAddress(&Pl, g_Pl);
    cudaGetSymbolAddress(&Ch, g_Ch);   cudaGetSymbolAddress(&Cl, g_Cl);

    const int SM2 = 2 * 3 * TILEB;   // 61440 (2-term)
    const int SM3 = 2 * 4 * TILEB;   // 81920 (3-term)
    cudaFuncSetAttribute(gemm_mma<0,2>, cudaFuncAttributeMaxDynamicSharedMemorySize, SM2);
    cudaFuncSetAttribute(gemm_mma<1,2>, cudaFuncAttributeMaxDynamicSharedMemorySize, SM2);
    cudaFuncSetAttribute(gemm_mma<1,3>, cudaFuncAttributeMaxDynamicSharedMemorySize, SM3);
    cudaFuncSetAttribute(gemm_mma<2,3>, cudaFuncAttributeMaxDynamicSharedMemorySize, SM3);
    cudaFuncSetAttribute(gemm_mma<3,3>, cudaFuncAttributeMaxDynamicSharedMemorySize, SM3);

    const float scl = 1.0f / sqrtf((float)EMB);
    const dim3 blk(256);

    // 1) split inputs
    {
        const int n4 = MROWS * EMB / 4;
        split2d<<<(n4 + 255) / 256, 256>>>((const float4*)x, (__half*)xh, (__half*)xl, n4);
        dim3 wg(24, 24), wb(32, 8);
        wsplit<<<wg, wb>>>(Wq, (__half*)Wqh, (__half*)Wql);
        wsplit<<<wg, wb>>>(Wk, (__half*)Wkh, (__half*)Wkl);
        wsplit<<<wg, wb>>>(Wv, (__half*)Wvh, (__half*)Wvl);
        wsplit<<<wg, wb>>>(Wo, (__half*)Woh, nullptr);
    }

    // 2) projections: [16384,768] x [768,768]^T, K=768, 3-term
    gemm_mma<1,3><<<dim3(6, 128, 1), blk, SM3>>>(
        (const __half*)xh, (const __half*)xl, (const __half*)Wqh, (const __half*)Wql,
        EMB, EMB, EMB, 0, 0,
        nullptr, (__half*)Qh, (__half*)Ql, bq, scl, EMB, 0);
    gemm_mma<2,3><<<dim3(6, 128, 1), blk, SM3>>>(
        (const __half*)xh, (const __half*)xl, (const __half*)Wkh, (const __half*)Wkl,
        EMB, EMB, EMB, 0, 0,
        nullptr, (__half*)Kh, nullptr, bk, 1.0f, EMB, 0);
    gemm_mma<3,3><<<dim3(6, 128, 1), blk, SM3>>>(
        (const __half*)xh, (const __half*)xl, (const __half*)Wvh, (const __half*)Wvl,
        EMB, EMB, EMB, 0, 0,
        nullptr, (__half*)Vth, nullptr, bv, 1.0f, 0, 0);

    // 3) scores = Q' @ K^T (scale folded into Q), fp32 out, 2-term
    gemm_mma<0,2><<<dim3(16, 16, 8), blk, SM2>>>(
        (const __half*)Qh, (const __half*)Ql, (const __half*)Kh, nullptr,
        EMB, EMB, EMB, (long)SEQ * EMB, (long)SEQ * EMB,
        (float*)Pf, nullptr, nullptr, nullptr, 1.0f, SEQ, (long)SEQ * SEQ);

    // 4) softmax -> split P (x P_SCALE)
    softmax_split<<<MROWS, 256>>>((const float*)Pf, (__half*)Ph, (__half*)Pl);

    // 5) ctx = P @ V : A = P [b,q,s], B = V^T [b,e,s], K=2048, 2-term
    gemm_mma<1,2><<<dim3(6, 16, 8), blk, SM2>>>(
        (const __half*)Ph, (const __half*)Pl, (const __half*)Vth, nullptr,
        SEQ, SEQ, SEQ, (long)SEQ * SEQ, (long)EMB * SEQ,
        nullptr, (__half*)Ch, (__half*)Cl, nullptr, 1.0f / P_SCALE, EMB, (long)SEQ * EMB);

    // 6) out = C @ Wo^T + bo, fp32, 2-term
    gemm_mma<0,2><<<dim3(6, 128, 1), blk, SM2>>>(
        (const __half*)Ch, (const __half*)Cl, (const __half*)Woh, nullptr,
        EMB, EMB, EMB, 0, 0,
        out, nullptr, nullptr, bo, 1.0f, EMB, 0);
}

// round 6
// speedup vs baseline: 3.6065x; 1.1697x over previous
#include <cuda_runtime.h>
#include <cuda_fp16.h>
#include <math.h>
#include <stdint.h>

#define BSZ 8
#define SEQ 2048
#define EMB 768
#define MROWS (BSZ*SEQ)
#define P_SCALE 1024.0f

// ---------------------------------------------------------------------------
// Scratch (device globals; allocation forbidden in kernel_launch)
// ---------------------------------------------------------------------------
__device__ __align__(256) __half g_xh[MROWS*EMB], g_xl[MROWS*EMB];
__device__ __align__(256) __half g_Wqh[EMB*EMB], g_Wql[EMB*EMB];
__device__ __align__(256) __half g_Wkh[EMB*EMB], g_Wkl[EMB*EMB];
__device__ __align__(256) __half g_Wvh[EMB*EMB], g_Wvl[EMB*EMB];
__device__ __align__(256) __half g_Woh[EMB*EMB];
__device__ __align__(256) __half g_Qh[MROWS*EMB], g_Ql[MROWS*EMB];
__device__ __align__(256) __half g_Kh[MROWS*EMB];
__device__ __align__(256) __half g_Vh[MROWS*EMB];                  // V hi, row-major [b,s,e]
__device__ __align__(256) float  g_P[(size_t)BSZ*SEQ*SEQ];         // fp32 scores
__device__ __align__(256) __half g_Ph[(size_t)BSZ*SEQ*SEQ];        // softmax hi (x P_SCALE)
__device__ __align__(256) __half g_Ch[MROWS*EMB], g_Cl[MROWS*EMB];

// ---------------------------------------------------------------------------
// helpers
// ---------------------------------------------------------------------------
__device__ __forceinline__ uint32_t smem_u32(const void* p) {
    uint32_t a;
    asm("{ .reg .u64 t; cvta.to.shared.u64 t, %1; cvt.u32.u64 %0, t; }" : "=r"(a) : "l"(p));
    return a;
}
__device__ __forceinline__ void cpasync16(uint32_t s, const void* g) {
    asm volatile("cp.async.cg.shared.global [%0], [%1], 16;" :: "r"(s), "l"(g));
}
__device__ __forceinline__ void cp_commit() { asm volatile("cp.async.commit_group;"); }

__device__ __forceinline__ void ldm_x4(uint32_t (&r)[4], uint32_t a) {
    asm volatile("ldmatrix.sync.aligned.m8n8.x4.shared.b16 {%0,%1,%2,%3}, [%4];"
        : "=r"(r[0]), "=r"(r[1]), "=r"(r[2]), "=r"(r[3]) : "r"(a));
}
__device__ __forceinline__ void ldm_x4_t(uint32_t (&r)[4], uint32_t a) {
    asm volatile("ldmatrix.sync.aligned.m8n8.x4.trans.shared.b16 {%0,%1,%2,%3}, [%4];"
        : "=r"(r[0]), "=r"(r[1]), "=r"(r[2]), "=r"(r[3]) : "r"(a));
}
__device__ __forceinline__ void mma16816(float (&d)[4], const uint32_t (&a)[4],
                                         uint32_t b0, uint32_t b1) {
    asm volatile("mma.sync.aligned.m16n8k16.row.col.f32.f16.f16.f32 "
        "{%0,%1,%2,%3}, {%4,%5,%6,%7}, {%8,%9}, {%0,%1,%2,%3};"
        : "+f"(d[0]), "+f"(d[1]), "+f"(d[2]), "+f"(d[3])
        : "r"(a[0]), "r"(a[1]), "r"(a[2]), "r"(a[3]), "r"(b0), "r"(b1));
}
__device__ __forceinline__ void split_h(float v, __half& h, __half& l) {
    h = __float2half_rn(v);
    l = __float2half_rn(v - __half2float(h));
}
__device__ __forceinline__ uint32_t pack_h2(__half a, __half b) {
    __half2 t(a, b);
    return *reinterpret_cast<uint32_t*>(&t);
}

#define ROWB   80                       // K-major tile row: 64B data + 16B pad
#define TILEB  (128*ROWB)               // 10240 B

// ---------------------------------------------------------------------------
// Generic split-fp16 warp-MMA GEMM: D[m,n] = sum_k A[m,k]*B[n,k] (both K-major)
// Terms: Ah*Bh + [ALO] Al*Bh + [BLO] Ah*Bl.  fp32 accum.
// CTA 128x128, Kc=32, 8 warps (32x64), multi-stage cp.async.
// MODE 0: fp32 (+bias). MODE 1: split hi/lo ((acc+bias)*scale). MODE 2: hi only.
// ---------------------------------------------------------------------------
template <int MODE, bool ALO, bool BLO>
__global__ void __launch_bounds__(256, 2)
gemm_mma(const __half* __restrict__ Ah, const __half* __restrict__ Al,
         const __half* __restrict__ Bh, const __half* __restrict__ Bl,
         int K, long ldA, long ldB, long sAb, long sBb,
         float* __restrict__ outF,
         __half* __restrict__ outHi, __half* __restrict__ outLo,
         const float* __restrict__ bias, float scale, long ldOut, long obs)
{
    constexpr int NT     = 2 + (ALO ? 1 : 0) + (BLO ? 1 : 0);
    constexpr int NSTAGE = (NT == 4) ? 2 : 3;
    constexpr int STAGEB = NT * TILEB;
    constexpr int OFF_B  = (1 + (ALO ? 1 : 0)) * TILEB;   // B hi tile offset
    constexpr int OFF_BL = OFF_B + TILEB;

    extern __shared__ char smem[];
    const uint32_t sb = smem_u32(smem);

    const int tid    = threadIdx.x;
    const int lane   = tid & 31;
    const int wid    = tid >> 5;
    const int warp_m = wid & 3;
    const int warp_n = wid >> 2;
    const int by     = blockIdx.y * 128;
    const int bx     = blockIdx.x * 128;
    const int bz     = blockIdx.z;

    Ah += (long)bz * sAb;
    if (ALO) Al += (long)bz * sAb;
    Bh += (long)bz * sBb;
    if (BLO) Bl += (long)bz * sBb;

    const int lr0 = tid >> 2, lg0 = tid & 3;
    const int lr1 = (tid + 256) >> 2, lg1 = (tid + 256) & 3;

    auto load_chunk = [&](int kc, int stage) {
        const long kk = (long)kc * 32;
        const uint32_t s0 = sb + stage * STAGEB;
        const __half* srcs[4];
        int nsrc = 0;
        srcs[nsrc++] = Ah;
        if (ALO) srcs[nsrc++] = Al;
        srcs[nsrc++] = Bh;
        if (BLO) srcs[nsrc++] = Bl;
#pragma unroll
        for (int m = 0; m < NT; ++m) {
            const bool isA = (m < 1 + (ALO ? 1 : 0));
            const long ld  = isA ? ldA : ldB;
            const int  r0  = isA ? by : bx;
            const uint32_t sm = s0 + m * TILEB;
            cpasync16(sm + lr0 * ROWB + lg0 * 16,
                      srcs[m] + (long)(r0 + lr0) * ld + kk + lg0 * 8);
            cpasync16(sm + lr1 * ROWB + lg1 * 16,
                      srcs[m] + (long)(r0 + lr1) * ld + kk + lg1 * 8);
        }
    };

    float acc[2][8][4];
#pragma unroll
    for (int i = 0; i < 2; ++i)
#pragma unroll
        for (int j = 0; j < 8; ++j)
#pragma unroll
            for (int e = 0; e < 4; ++e) acc[i][j][e] = 0.f;

    const int nChunks = K >> 5;

#pragma unroll
    for (int i = 0; i < NSTAGE - 1; ++i) {
        load_chunk(i, i);
        cp_commit();
    }

    const int rl = lane & 7;
    const int gq = lane >> 3;
    const uint32_t aoff = (uint32_t)((warp_m * 32 + (gq & 1) * 8 + rl) * ROWB + (gq >> 1) * 16);
    const uint32_t boff = (uint32_t)((warp_n * 64 + (gq >> 1) * 8 + rl) * ROWB + (gq & 1) * 16);

    for (int kc = 0; kc < nChunks; ++kc) {
        const int pf = kc + NSTAGE - 1;
        if (pf < nChunks) load_chunk(pf, pf % NSTAGE);
        cp_commit();
        asm volatile("cp.async.wait_group %0;" :: "n"(NSTAGE - 1));
        __syncthreads();

        const uint32_t st = sb + (kc % NSTAGE) * STAGEB;
#pragma unroll
        for (int ks = 0; ks < 2; ++ks) {
            const uint32_t kb = ks * 32;
            uint32_t ah[2][4], al[2][4];
#pragma unroll
            for (int i = 0; i < 2; ++i) {
                ldm_x4(ah[i], st + aoff + i * (16 * ROWB) + kb);
                if (ALO) ldm_x4(al[i], st + TILEB + aoff + i * (16 * ROWB) + kb);
            }
            uint32_t bh[4][4];
#pragma unroll
            for (int g = 0; g < 4; ++g)
                ldm_x4(bh[g], st + OFF_B + boff + g * (16 * ROWB) + kb);
#pragma unroll
            for (int i = 0; i < 2; ++i)
#pragma unroll
                for (int j = 0; j < 8; ++j) {
                    const int g = j >> 1, o = (j & 1) * 2;
                    mma16816(acc[i][j], ah[i], bh[g][o], bh[g][o + 1]);
                    if (ALO) mma16816(acc[i][j], al[i], bh[g][o], bh[g][o + 1]);
                }
            if (BLO) {
                uint32_t bl[4][4];
#pragma unroll
                for (int g = 0; g < 4; ++g)
                    ldm_x4(bl[g], st + OFF_BL + boff + g * (16 * ROWB) + kb);
#pragma unroll
                for (int i = 0; i < 2; ++i)
#pragma unroll
                    for (int j = 0; j < 8; ++j) {
                        const int g = j >> 1, o = (j & 1) * 2;
                        mma16816(acc[i][j], ah[i], bl[g][o], bl[g][o + 1]);
                    }
            }
        }
        __syncthreads();
    }

    // ---------------- epilogue ----------------
    const int r_in = lane >> 2;
    const int c_in = (lane & 3) * 2;

#pragma unroll
    for (int i = 0; i < 2; ++i) {
#pragma unroll
        for (int j = 0; j < 8; ++j) {
            const int row0 = by + warp_m * 32 + i * 16 + r_in;
            const int row1 = row0 + 8;
            const int col  = bx + warp_n * 64 + j * 8 + c_in;
            const float b0 = bias ? bias[col]     : 0.f;
            const float b1 = bias ? bias[col + 1] : 0.f;

            if (MODE == 0) {
                float2 v0 = make_float2(acc[i][j][0] + b0, acc[i][j][1] + b1);
                float2 v1 = make_float2(acc[i][j][2] + b0, acc[i][j][3] + b1);
                *reinterpret_cast<float2*>(outF + (long)bz * obs + (long)row0 * ldOut + col) = v0;
                *reinterpret_cast<float2*>(outF + (long)bz * obs + (long)row1 * ldOut + col) = v1;
            } else if (MODE == 1) {
                float v00 = (acc[i][j][0] + b0) * scale, v01 = (acc[i][j][1] + b1) * scale;
                float v10 = (acc[i][j][2] + b0) * scale, v11 = (acc[i][j][3] + b1) * scale;
                __half h0, l0, h1, l1;
                split_h(v00, h0, l0); split_h(v01, h1, l1);
                const long o0 = (long)bz * obs + (long)row0 * ldOut + col;
                *reinterpret_cast<uint32_t*>(outHi + o0) = pack_h2(h0, h1);
                *reinterpret_cast<uint32_t*>(outLo + o0) = pack_h2(l0, l1);
                split_h(v10, h0, l0); split_h(v11, h1, l1);
                const long o1 = (long)bz * obs + (long)row1 * ldOut + col;
                *reinterpret_cast<uint32_t*>(outHi + o1) = pack_h2(h0, h1);
                *reinterpret_cast<uint32_t*>(outLo + o1) = pack_h2(l0, l1);
            } else {  // MODE 2: hi only
                float v00 = (acc[i][j][0] + b0) * scale, v01 = (acc[i][j][1] + b1) * scale;
                float v10 = (acc[i][j][2] + b0) * scale, v11 = (acc[i][j][3] + b1) * scale;
                const long o0 = (long)bz * obs + (long)row0 * ldOut + col;
                const long o1 = (long)bz * obs + (long)row1 * ldOut + col;
                *reinterpret_cast<uint32_t*>(outHi + o0) =
                    pack_h2(__float2half_rn(v00), __float2half_rn(v01));
                *reinterpret_cast<uint32_t*>(outHi + o1) =
                    pack_h2(__float2half_rn(v10), __float2half_rn(v11));
            }
        }
    }
}

// ---------------------------------------------------------------------------
// PV GEMM: C[m,e] = sum_s P[m,s] * V[s,e]. A = Ph K-major; B = V row-major
// [s,e] loaded via trans-ldmatrix from swizzled [k=32 x 256B] smem tiles.
// 1-term (P hi only). Epilogue: split hi/lo out, *scale.
// ---------------------------------------------------------------------------
#define PV_BTILE 8192                        // 32 rows x 256B, swizzled
#define PV_STAGE (TILEB + PV_BTILE)          // 18432
#define PV_NST   5

__global__ void __launch_bounds__(256, 2)
gemm_pv(const __half* __restrict__ Ah, const __half* __restrict__ Bv,
        int K, long ldA, long ldB, long sAb, long sBb,
        __half* __restrict__ outHi, __half* __restrict__ outLo,
        float scale, long ldOut, long obs)
{
    extern __shared__ char smem[];
    const uint32_t sb = smem_u32(smem);

    const int tid    = threadIdx.x;
    const int lane   = tid & 31;
    const int wid    = tid >> 5;
    const int warp_m = wid & 3;
    const int warp_n = wid >> 2;
    const int by     = blockIdx.y * 128;
    const int bx     = blockIdx.x * 128;
    const int bz     = blockIdx.z;

    Ah += (long)bz * sAb;
    Bv += (long)bz * sBb;

    const int lr0 = tid >> 2, lg0 = tid & 3;
    const int lr1 = (tid + 256) >> 2, lg1 = (tid + 256) & 3;
    const int bk0 = tid >> 4,  bg0 = tid & 15;
    const int bk1 = (tid + 256) >> 4, bg1 = (tid + 256) & 15;

    auto load_chunk = [&](int kc, int stage) {
        const long kk = (long)kc * 32;
        const uint32_t s0 = sb + stage * PV_STAGE;
        cpasync16(s0 + lr0 * ROWB + lg0 * 16, Ah + (long)(by + lr0) * ldA + kk + lg0 * 8);
        cpasync16(s0 + lr1 * ROWB + lg1 * 16, Ah + (long)(by + lr1) * ldA + kk + lg1 * 8);
        const uint32_t b0 = s0 + TILEB;
        cpasync16(b0 + bk0 * 256 + ((bg0 ^ (bk0 & 7)) * 16),
                  Bv + (long)(kk + bk0) * ldB + bx + bg0 * 8);
        cpasync16(b0 + bk1 * 256 + ((bg1 ^ (bk1 & 7)) * 16),
                  Bv + (long)(kk + bk1) * ldB + bx + bg1 * 8);
    };

    float acc[2][8][4];
#pragma unroll
    for (int i = 0; i < 2; ++i)
#pragma unroll
        for (int j = 0; j < 8; ++j)
#pragma unroll
            for (int e = 0; e < 4; ++e) acc[i][j][e] = 0.f;

    const int nChunks = K >> 5;

#pragma unroll
    for (int i = 0; i < PV_NST - 1; ++i) {
        load_chunk(i, i);
        cp_commit();
    }

    const int rl = lane & 7;
    const int gq = lane >> 3;
    const uint32_t aoff = (uint32_t)((warp_m * 32 + (gq & 1) * 8 + rl) * ROWB + (gq >> 1) * 16);
    // B trans-ldmatrix per-lane pieces: row k, 16B-col within 256B row
    const int brow_in = (gq & 1) * 8 + rl;            // k within 16-block
    const int bcol16  = warp_n * 8 + (gq >> 1);       // + g*2 at use site

    for (int kc = 0; kc < nChunks; ++kc) {
        const int pf = kc + PV_NST - 1;
        if (pf < nChunks) load_chunk(pf, pf % PV_NST);
        cp_commit();
        asm volatile("cp.async.wait_group %0;" :: "n"(PV_NST - 1));
        __syncthreads();

        const uint32_t st = sb + (kc % PV_NST) * PV_STAGE;
        const uint32_t bt0 = st + TILEB;
#pragma unroll
        for (int ks = 0; ks < 2; ++ks) {
            uint32_t ah[2][4];
#pragma unroll
            for (int i = 0; i < 2; ++i)
                ldm_x4(ah[i], st + aoff + i * (16 * ROWB) + ks * 32);
            uint32_t bt[4][4];
            const int row = ks * 16 + brow_in;
#pragma unroll
            for (int g = 0; g < 4; ++g) {
                const int c = (bcol16 + g * 2) ^ (row & 7);
                ldm_x4_t(bt[g], bt0 + row * 256 + c * 16);
            }
#pragma unroll
            for (int i = 0; i < 2; ++i)
#pragma unroll
                for (int j = 0; j < 8; ++j) {
                    const int g = j >> 1, o = (j & 1) * 2;
                    mma16816(acc[i][j], ah[i], bt[g][o], bt[g][o + 1]);
                }
        }
        __syncthreads();
    }

    // epilogue: split hi/lo, *scale
    const int r_in = lane >> 2;
    const int c_in = (lane & 3) * 2;
#pragma unroll
    for (int i = 0; i < 2; ++i) {
#pragma unroll
        for (int j = 0; j < 8; ++j) {
            const int row0 = by + warp_m * 32 + i * 16 + r_in;
            const int row1 = row0 + 8;
            const int col  = bx + warp_n * 64 + j * 8 + c_in;
            float v00 = acc[i][j][0] * scale, v01 = acc[i][j][1] * scale;
            float v10 = acc[i][j][2] * scale, v11 = acc[i][j][3] * scale;
            __half h0, l0, h1, l1;
            split_h(v00, h0, l0); split_h(v01, h1, l1);
            const long o0 = (long)bz * obs + (long)row0 * ldOut + col;
            *reinterpret_cast<uint32_t*>(outHi + o0) = pack_h2(h0, h1);
            *reinterpret_cast<uint32_t*>(outLo + o0) = pack_h2(l0, l1);
            split_h(v10, h0, l0); split_h(v11, h1, l1);
            const long o1 = (long)bz * obs + (long)row1 * ldOut + col;
            *reinterpret_cast<uint32_t*>(outHi + o1) = pack_h2(h0, h1);
            *reinterpret_cast<uint32_t*>(outLo + o1) = pack_h2(l0, l1);
        }
    }
}

// ---------------------------------------------------------------------------
// Elementwise split: fp32 -> (hi, lo) fp16
// ---------------------------------------------------------------------------
__global__ void split2d(const float4* __restrict__ in,
                        __half* __restrict__ oh, __half* __restrict__ ol, int n4)
{
    const int i = blockIdx.x * blockDim.x + threadIdx.x;
    if (i >= n4) return;
    const float4 v = in[i];
    __half h0, l0, h1, l1, h2, l2, h3, l3;
    split_h(v.x, h0, l0); split_h(v.y, h1, l1);
    split_h(v.z, h2, l2); split_h(v.w, h3, l3);
    uint2 H, L;
    H.x = pack_h2(h0, h1); H.y = pack_h2(h2, h3);
    L.x = pack_h2(l0, l1); L.y = pack_h2(l2, l3);
    *reinterpret_cast<uint2*>(oh + 4 * (long)i) = H;
    *reinterpret_cast<uint2*>(ol + 4 * (long)i) = L;
}

// ---------------------------------------------------------------------------
// Weight transpose + split: W[K,N] fp32 -> Wt hi/lo [N,K] fp16 (lo optional)
// ---------------------------------------------------------------------------
__global__ void wsplit(const float* __restrict__ W,
                       __half* __restrict__ oh, __half* __restrict__ ol)
{
    __shared__ float t[32][33];
    const int n0 = blockIdx.x * 32, k0 = blockIdx.y * 32;
    const int tx = threadIdx.x, ty = threadIdx.y;
#pragma unroll
    for (int i = 0; i < 32; i += 8)
        t[ty + i][tx] = W[(long)(k0 + ty + i) * EMB + n0 + tx];
    __syncthreads();
#pragma unroll
    for (int i = 0; i < 32; i += 8) {
        __half h, l;
        split_h(t[tx][ty + i], h, l);
        const long o = (long)(n0 + ty + i) * EMB + k0 + tx;
        oh[o] = h;
        if (ol) ol[o] = l;
    }
}

// ---------------------------------------------------------------------------
// Row softmax over fp32 P, emitting fp16 hi scaled by P_SCALE
// ---------------------------------------------------------------------------
__global__ void __launch_bounds__(256)
softmax_h(const float* __restrict__ P, __half* __restrict__ Ph)
{
    __shared__ float sred[8];
    __shared__ float sbc[2];
    const int tid = threadIdx.x;
    const long base = (long)blockIdx.x * SEQ;

    float v[8];
#pragma unroll
    for (int j = 0; j < 8; j++) v[j] = P[base + tid + j * 256];

    float m = v[0];
#pragma unroll
    for (int j = 1; j < 8; j++) m = fmaxf(m, v[j]);
#pragma unroll
    for (int o = 16; o > 0; o >>= 1) m = fmaxf(m, __shfl_xor_sync(0xffffffffu, m, o));
    if ((tid & 31) == 0) sred[tid >> 5] = m;
    __syncthreads();
    if (tid == 0) {
        float t = sred[0];
#pragma unroll
        for (int w = 1; w < 8; w++) t = fmaxf(t, sred[w]);
        sbc[0] = t;
    }
    __syncthreads();
    m = sbc[0];

    float s = 0.f;
#pragma unroll
    for (int j = 0; j < 8; j++) { v[j] = __expf(v[j] - m); s += v[j]; }
#pragma unroll
    for (int o = 16; o > 0; o >>= 1) s += __shfl_xor_sync(0xffffffffu, s, o);
    __syncthreads();
    if ((tid & 31) == 0) sred[tid >> 5] = s;
    __syncthreads();
    if (tid == 0) {
        float t = sred[0];
#pragma unroll
        for (int w = 1; w < 8; w++) t += sred[w];
        sbc[1] = t;
    }
    __syncthreads();
    const float inv = P_SCALE / sbc[1];

#pragma unroll
    for (int j = 0; j < 8; j++)
        Ph[base + tid + j * 256] = __float2half_rn(v[j] * inv);
}

// ---------------------------------------------------------------------------
// Host side
// ---------------------------------------------------------------------------
extern "C" void kernel_launch(void* const* d_in, const int* in_sizes, int n_in,
                              void* d_out, int out_size)
{
    const float* x  = (const float*)d_in[0];
    const float* Wq = (const float*)d_in[1];
    const float* bq = (const float*)d_in[2];
    const float* Wk = (const float*)d_in[3];
    const float* bk = (const float*)d_in[4];
    const float* Wv = (const float*)d_in[5];
    const float* bv = (const float*)d_in[6];
    const float* Wo = (const float*)d_in[7];
    const float* bo = (const float*)d_in[8];
    float* out = (float*)d_out;

    void *xh, *xl, *Wqh, *Wql, *Wkh, *Wkl, *Wvh, *Wvl, *Woh;
    void *Qh, *Ql, *Kh, *Vh, *Pf, *Ph, *Ch, *Cl;
    cudaGetSymbolAddress(&xh, g_xh);   cudaGetSymbolAddress(&xl, g_xl);
    cudaGetSymbolAddress(&Wqh, g_Wqh); cudaGetSymbolAddress(&Wql, g_Wql);
    cudaGetSymbolAddress(&Wkh, g_Wkh); cudaGetSymbolAddress(&Wkl, g_Wkl);
    cudaGetSymbolAddress(&Wvh, g_Wvh); cudaGetSymbolAddress(&Wvl, g_Wvl);
    cudaGetSymbolAddress(&Woh, g_Woh);
    cudaGetSymbolAddress(&Qh, g_Qh);   cudaGetSymbolAddress(&Ql, g_Ql);
    cudaGetSymbolAddress(&Kh, g_Kh);
    cudaGetSymbolAddress(&Vh, g_Vh);
    cudaGetSymbolAddress(&Pf, g_P);
    cudaGetSymbolAddress(&Ph, g_Ph);
    cudaGetSymbolAddress(&Ch, g_Ch);   cudaGetSymbolAddress(&Cl, g_Cl);

    const int SM4 = 2 * 4 * TILEB;       // 81920 (proj: 2 stages x 4 tiles)
    const int SM3 = 3 * 3 * TILEB;       // 92160 (scores/out: 3 stages x 3 tiles)
    const int SMP = PV_NST * PV_STAGE;   // 92160 (PV: 5 stages)
    cudaFuncSetAttribute(gemm_mma<1,true,true>,  cudaFuncAttributeMaxDynamicSharedMemorySize, SM4);
    cudaFuncSetAttribute(gemm_mma<2,true,true>,  cudaFuncAttributeMaxDynamicSharedMemorySize, SM4);
    cudaFuncSetAttribute(gemm_mma<0,true,false>, cudaFuncAttributeMaxDynamicSharedMemorySize, SM3);
    cudaFuncSetAttribute(gemm_pv,                cudaFuncAttributeMaxDynamicSharedMemorySize, SMP);

    const float scl = 1.0f / sqrtf((float)EMB);
    const dim3 blk(256);

    // 1) split inputs
    {
        const int n4 = MROWS * EMB / 4;
        split2d<<<(n4 + 255) / 256, 256>>>((const float4*)x, (__half*)xh, (__half*)xl, n4);
        dim3 wg(24, 24), wb(32, 8);
        wsplit<<<wg, wb>>>(Wq, (__half*)Wqh, (__half*)Wql);
        wsplit<<<wg, wb>>>(Wk, (__half*)Wkh, (__half*)Wkl);
        wsplit<<<wg, wb>>>(Wv, (__half*)Wvh, (__half*)Wvl);
        wsplit<<<wg, wb>>>(Wo, (__half*)Woh, nullptr);
    }

    // 2) projections: [16384,768] x [768,768]^T, K=768, 3-term
    gemm_mma<1,true,true><<<dim3(6, 128, 1), blk, SM4>>>(
        (const __half*)xh, (const __half*)xl, (const __half*)Wqh, (const __half*)Wql,
        EMB, EMB, EMB, 0, 0,
        nullptr, (__half*)Qh, (__half*)Ql, bq, scl, EMB, 0);
    gemm_mma<2,true,true><<<dim3(6, 128, 1), blk, SM4>>>(
        (const __half*)xh, (const __half*)xl, (const __half*)Wkh, (const __half*)Wkl,
        EMB, EMB, EMB, 0, 0,
        nullptr, (__half*)Kh, nullptr, bk, 1.0f, EMB, 0);
    gemm_mma<2,true,true><<<dim3(6, 128, 1), blk, SM4>>>(
        (const __half*)xh, (const __half*)xl, (const __half*)Wvh, (const __half*)Wvl,
        EMB, EMB, EMB, 0, 0,
        nullptr, (__half*)Vh, nullptr, bv, 1.0f, EMB, 0);

    // 3) scores = Q' @ K^T (scale folded into Q), fp32 out, 2-term
    gemm_mma<0,true,false><<<dim3(16, 16, 8), blk, SM3>>>(
        (const __half*)Qh, (const __half*)Ql, (const __half*)Kh, nullptr,
        EMB, EMB, EMB, (long)SEQ * EMB, (long)SEQ * EMB,
        (float*)Pf, nullptr, nullptr, nullptr, 1.0f, SEQ, (long)SEQ * SEQ);

    // 4) softmax -> P hi (x P_SCALE)
    softmax_h<<<MROWS, 256>>>((const float*)Pf, (__half*)Ph);

    // 5) ctx = P @ V, 1-term, B = V row-major via trans-ldmatrix, K=2048
    gemm_pv<<<dim3(6, 16, 8), blk, SMP>>>(
        (const __half*)Ph, (const __half*)Vh,
        SEQ, SEQ, EMB, (long)SEQ * SEQ, (long)SEQ * EMB,
        (__half*)Ch, (__half*)Cl, 1.0f / P_SCALE, EMB, (long)SEQ * EMB);

    // 6) out = C @ Wo^T + bo, fp32, 2-term
    gemm_mma<0,true,false><<<dim3(6, 128, 1), blk, SM3>>>(
        (const __half*)Ch, (const __half*)Cl, (const __half*)Woh, nullptr,
        EMB, EMB, EMB, 0, 0,
        out, nullptr, nullptr, bo, 1.0f, EMB, 0);
}

// round 7
// speedup vs baseline: 4.1157x; 1.1412x over previous
#include <cuda_runtime.h>
#include <cuda_fp16.h>
#include <math.h>
#include <stdint.h>

#define BSZ 8
#define SEQ 2048
#define EMB 768
#define MROWS (BSZ*SEQ)
#define P_SCALE 1024.0f

// ---------------------------------------------------------------------------
// Scratch (device globals; allocation forbidden in kernel_launch)
// ---------------------------------------------------------------------------
__device__ __align__(256) __half g_xh[MROWS*EMB], g_xl[MROWS*EMB];
__device__ __align__(256) __half g_Wqh[EMB*EMB], g_Wql[EMB*EMB];
__device__ __align__(256) __half g_Wkh[EMB*EMB];
__device__ __align__(256) __half g_Wvh[EMB*EMB];
__device__ __align__(256) __half g_Woh[EMB*EMB];
__device__ __align__(256) __half g_Qh[MROWS*EMB], g_Ql[MROWS*EMB];
__device__ __align__(256) __half g_Kh[MROWS*EMB];
__device__ __align__(256) __half g_Vh[MROWS*EMB];                  // V hi, row-major [b,s,e]
__device__ __align__(256) float  g_P[(size_t)BSZ*SEQ*SEQ];         // fp32 scores
__device__ __align__(256) __half g_Ph[(size_t)BSZ*SEQ*SEQ];        // softmax hi (x P_SCALE)
__device__ __align__(256) __half g_Ch[MROWS*EMB];

// ---------------------------------------------------------------------------
// helpers
// ---------------------------------------------------------------------------
__device__ __forceinline__ uint32_t smem_u32(const void* p) {
    uint32_t a;
    asm("{ .reg .u64 t; cvta.to.shared.u64 t, %1; cvt.u32.u64 %0, t; }" : "=r"(a) : "l"(p));
    return a;
}
__device__ __forceinline__ void cpasync16(uint32_t s, const void* g) {
    asm volatile("cp.async.cg.shared.global [%0], [%1], 16;" :: "r"(s), "l"(g));
}
__device__ __forceinline__ void cp_commit() { asm volatile("cp.async.commit_group;"); }

__device__ __forceinline__ void ldm_x4(uint32_t (&r)[4], uint32_t a) {
    asm volatile("ldmatrix.sync.aligned.m8n8.x4.shared.b16 {%0,%1,%2,%3}, [%4];"
        : "=r"(r[0]), "=r"(r[1]), "=r"(r[2]), "=r"(r[3]) : "r"(a));
}
__device__ __forceinline__ void ldm_x4_t(uint32_t (&r)[4], uint32_t a) {
    asm volatile("ldmatrix.sync.aligned.m8n8.x4.trans.shared.b16 {%0,%1,%2,%3}, [%4];"
        : "=r"(r[0]), "=r"(r[1]), "=r"(r[2]), "=r"(r[3]) : "r"(a));
}
__device__ __forceinline__ void mma16816(float (&d)[4], const uint32_t (&a)[4],
                                         uint32_t b0, uint32_t b1) {
    asm volatile("mma.sync.aligned.m16n8k16.row.col.f32.f16.f16.f32 "
        "{%0,%1,%2,%3}, {%4,%5,%6,%7}, {%8,%9}, {%0,%1,%2,%3};"
        : "+f"(d[0]), "+f"(d[1]), "+f"(d[2]), "+f"(d[3])
        : "r"(a[0]), "r"(a[1]), "r"(a[2]), "r"(a[3]), "r"(b0), "r"(b1));
}
__device__ __forceinline__ void split_h(float v, __half& h, __half& l) {
    h = __float2half_rn(v);
    l = __float2half_rn(v - __half2float(h));
}
__device__ __forceinline__ uint32_t pack_h2(__half a, __half b) {
    __half2 t(a, b);
    return *reinterpret_cast<uint32_t*>(&t);
}

#define ROWB   80                       // K-major tile row: 64B data + 16B pad
#define TILEB  (128*ROWB)               // 10240 B

// ---------------------------------------------------------------------------
// Generic split-fp16 warp-MMA GEMM: D[m,n] = sum_k A[m,k]*B[n,k] (both K-major)
// Terms: Ah*Bh + [ALO] Al*Bh + [BLO] Ah*Bl.  fp32 accum.
// CTA 128x128, Kc=32, 8 warps (32x64), multi-stage cp.async:
//   NT=4 -> 2 stages, NT=3 -> 3 stages, NT=2 -> 4 stages.
// MODE 0: fp32 (+bias). MODE 1: split hi/lo ((acc+bias)*scale). MODE 2: hi only.
// ---------------------------------------------------------------------------
template <int MODE, bool ALO, bool BLO>
__global__ void __launch_bounds__(256, 2)
gemm_mma(const __half* __restrict__ Ah, const __half* __restrict__ Al,
         const __half* __restrict__ Bh, const __half* __restrict__ Bl,
         int K, long ldA, long ldB, long sAb, long sBb,
         float* __restrict__ outF,
         __half* __restrict__ outHi, __half* __restrict__ outLo,
         const float* __restrict__ bias, float scale, long ldOut, long obs)
{
    constexpr int NT     = 2 + (ALO ? 1 : 0) + (BLO ? 1 : 0);
    constexpr int NSTAGE = (NT == 4) ? 2 : ((NT == 3) ? 3 : 4);
    constexpr int STAGEB = NT * TILEB;
    constexpr int OFF_B  = (1 + (ALO ? 1 : 0)) * TILEB;   // B hi tile offset
    constexpr int OFF_BL = OFF_B + TILEB;

    extern __shared__ char smem[];
    const uint32_t sb = smem_u32(smem);

    const int tid    = threadIdx.x;
    const int lane   = tid & 31;
    const int wid    = tid >> 5;
    const int warp_m = wid & 3;
    const int warp_n = wid >> 2;
    const int by     = blockIdx.y * 128;
    const int bx     = blockIdx.x * 128;
    const int bz     = blockIdx.z;

    Ah += (long)bz * sAb;
    if (ALO) Al += (long)bz * sAb;
    Bh += (long)bz * sBb;
    if (BLO) Bl += (long)bz * sBb;

    const int lr0 = tid >> 2, lg0 = tid & 3;
    const int lr1 = (tid + 256) >> 2, lg1 = (tid + 256) & 3;

    auto load_chunk = [&](int kc, int stage) {
        const long kk = (long)kc * 32;
        const uint32_t s0 = sb + stage * STAGEB;
        const __half* srcs[4];
        int nsrc = 0;
        srcs[nsrc++] = Ah;
        if (ALO) srcs[nsrc++] = Al;
        srcs[nsrc++] = Bh;
        if (BLO) srcs[nsrc++] = Bl;
#pragma unroll
        for (int m = 0; m < NT; ++m) {
            const bool isA = (m < 1 + (ALO ? 1 : 0));
            const long ld  = isA ? ldA : ldB;
            const int  r0  = isA ? by : bx;
            const uint32_t sm = s0 + m * TILEB;
            cpasync16(sm + lr0 * ROWB + lg0 * 16,
                      srcs[m] + (long)(r0 + lr0) * ld + kk + lg0 * 8);
            cpasync16(sm + lr1 * ROWB + lg1 * 16,
                      srcs[m] + (long)(r0 + lr1) * ld + kk + lg1 * 8);
        }
    };

    float acc[2][8][4];
#pragma unroll
    for (int i = 0; i < 2; ++i)
#pragma unroll
        for (int j = 0; j < 8; ++j)
#pragma unroll
            for (int e = 0; e < 4; ++e) acc[i][j][e] = 0.f;

    const int nChunks = K >> 5;

#pragma unroll
    for (int i = 0; i < NSTAGE - 1; ++i) {
        load_chunk(i, i);
        cp_commit();
    }

    const int rl = lane & 7;
    const int gq = lane >> 3;
    const uint32_t aoff = (uint32_t)((warp_m * 32 + (gq & 1) * 8 + rl) * ROWB + (gq >> 1) * 16);
    const uint32_t boff = (uint32_t)((warp_n * 64 + (gq >> 1) * 8 + rl) * ROWB + (gq & 1) * 16);

    for (int kc = 0; kc < nChunks; ++kc) {
        const int pf = kc + NSTAGE - 1;
        if (pf < nChunks) load_chunk(pf, pf % NSTAGE);
        cp_commit();
        asm volatile("cp.async.wait_group %0;" :: "n"(NSTAGE - 1));
        __syncthreads();

        const uint32_t st = sb + (kc % NSTAGE) * STAGEB;
#pragma unroll
        for (int ks = 0; ks < 2; ++ks) {
            const uint32_t kb = ks * 32;
            uint32_t ah[2][4], al[2][4];
#pragma unroll
            for (int i = 0; i < 2; ++i) {
                ldm_x4(ah[i], st + aoff + i * (16 * ROWB) + kb);
                if (ALO) ldm_x4(al[i], st + TILEB + aoff + i * (16 * ROWB) + kb);
            }
            uint32_t bh[4][4];
#pragma unroll
            for (int g = 0; g < 4; ++g)
                ldm_x4(bh[g], st + OFF_B + boff + g * (16 * ROWB) + kb);
#pragma unroll
            for (int i = 0; i < 2; ++i)
#pragma unroll
                for (int j = 0; j < 8; ++j) {
                    const int g = j >> 1, o = (j & 1) * 2;
                    mma16816(acc[i][j], ah[i], bh[g][o], bh[g][o + 1]);
                    if (ALO) mma16816(acc[i][j], al[i], bh[g][o], bh[g][o + 1]);
                }
            if (BLO) {
                uint32_t bl[4][4];
#pragma unroll
                for (int g = 0; g < 4; ++g)
                    ldm_x4(bl[g], st + OFF_BL + boff + g * (16 * ROWB) + kb);
#pragma unroll
                for (int i = 0; i < 2; ++i)
#pragma unroll
                    for (int j = 0; j < 8; ++j) {
                        const int g = j >> 1, o = (j & 1) * 2;
                        mma16816(acc[i][j], ah[i], bl[g][o], bl[g][o + 1]);
                    }
            }
        }
        __syncthreads();
    }

    // ---------------- epilogue ----------------
    const int r_in = lane >> 2;
    const int c_in = (lane & 3) * 2;

#pragma unroll
    for (int i = 0; i < 2; ++i) {
#pragma unroll
        for (int j = 0; j < 8; ++j) {
            const int row0 = by + warp_m * 32 + i * 16 + r_in;
            const int row1 = row0 + 8;
            const int col  = bx + warp_n * 64 + j * 8 + c_in;
            const float b0 = bias ? bias[col]     : 0.f;
            const float b1 = bias ? bias[col + 1] : 0.f;

            if (MODE == 0) {
                float2 v0 = make_float2(acc[i][j][0] + b0, acc[i][j][1] + b1);
                float2 v1 = make_float2(acc[i][j][2] + b0, acc[i][j][3] + b1);
                *reinterpret_cast<float2*>(outF + (long)bz * obs + (long)row0 * ldOut + col) = v0;
                *reinterpret_cast<float2*>(outF + (long)bz * obs + (long)row1 * ldOut + col) = v1;
            } else if (MODE == 1) {
                float v00 = (acc[i][j][0] + b0) * scale, v01 = (acc[i][j][1] + b1) * scale;
                float v10 = (acc[i][j][2] + b0) * scale, v11 = (acc[i][j][3] + b1) * scale;
                __half h0, l0, h1, l1;
                split_h(v00, h0, l0); split_h(v01, h1, l1);
                const long o0 = (long)bz * obs + (long)row0 * ldOut + col;
                *reinterpret_cast<uint32_t*>(outHi + o0) = pack_h2(h0, h1);
                *reinterpret_cast<uint32_t*>(outLo + o0) = pack_h2(l0, l1);
                split_h(v10, h0, l0); split_h(v11, h1, l1);
                const long o1 = (long)bz * obs + (long)row1 * ldOut + col;
                *reinterpret_cast<uint32_t*>(outHi + o1) = pack_h2(h0, h1);
                *reinterpret_cast<uint32_t*>(outLo + o1) = pack_h2(l0, l1);
            } else {  // MODE 2: hi only
                float v00 = (acc[i][j][0] + b0) * scale, v01 = (acc[i][j][1] + b1) * scale;
                float v10 = (acc[i][j][2] + b0) * scale, v11 = (acc[i][j][3] + b1) * scale;
                const long o0 = (long)bz * obs + (long)row0 * ldOut + col;
                const long o1 = (long)bz * obs + (long)row1 * ldOut + col;
                *reinterpret_cast<uint32_t*>(outHi + o0) =
                    pack_h2(__float2half_rn(v00), __float2half_rn(v01));
                *reinterpret_cast<uint32_t*>(outHi + o1) =
                    pack_h2(__float2half_rn(v10), __float2half_rn(v11));
            }
        }
    }
}

// ---------------------------------------------------------------------------
// PV GEMM: C[m,e] = sum_s P[m,s] * V[s,e]. A = Ph K-major; B = V row-major
// [s,e] loaded via trans-ldmatrix from swizzled [k=32 x 256B] smem tiles.
// 1-term (P hi only). Epilogue: hi-only out, *scale.
// ---------------------------------------------------------------------------
#define PV_BTILE 8192                        // 32 rows x 256B, swizzled
#define PV_STAGE (TILEB + PV_BTILE)          // 18432
#define PV_NST   5

__global__ void __launch_bounds__(256, 2)
gemm_pv(const __half* __restrict__ Ah, const __half* __restrict__ Bv,
        int K, long ldA, long ldB, long sAb, long sBb,
        __half* __restrict__ outHi, float scale, long ldOut, long obs)
{
    extern __shared__ char smem[];
    const uint32_t sb = smem_u32(smem);

    const int tid    = threadIdx.x;
    const int lane   = tid & 31;
    const int wid    = tid >> 5;
    const int warp_m = wid & 3;
    const int warp_n = wid >> 2;
    const int by     = blockIdx.y * 128;
    const int bx     = blockIdx.x * 128;
    const int bz     = blockIdx.z;

    Ah += (long)bz * sAb;
    Bv += (long)bz * sBb;

    const int lr0 = tid >> 2, lg0 = tid & 3;
    const int lr1 = (tid + 256) >> 2, lg1 = (tid + 256) & 3;
    const int bk0 = tid >> 4,  bg0 = tid & 15;
    const int bk1 = (tid + 256) >> 4, bg1 = (tid + 256) & 15;

    auto load_chunk = [&](int kc, int stage) {
        const long kk = (long)kc * 32;
        const uint32_t s0 = sb + stage * PV_STAGE;
        cpasync16(s0 + lr0 * ROWB + lg0 * 16, Ah + (long)(by + lr0) * ldA + kk + lg0 * 8);
        cpasync16(s0 + lr1 * ROWB + lg1 * 16, Ah + (long)(by + lr1) * ldA + kk + lg1 * 8);
        const uint32_t b0 = s0 + TILEB;
        cpasync16(b0 + bk0 * 256 + ((bg0 ^ (bk0 & 7)) * 16),
                  Bv + (long)(kk + bk0) * ldB + bx + bg0 * 8);
        cpasync16(b0 + bk1 * 256 + ((bg1 ^ (bk1 & 7)) * 16),
                  Bv + (long)(kk + bk1) * ldB + bx + bg1 * 8);
    };

    float acc[2][8][4];
#pragma unroll
    for (int i = 0; i < 2; ++i)
#pragma unroll
        for (int j = 0; j < 8; ++j)
#pragma unroll
            for (int e = 0; e < 4; ++e) acc[i][j][e] = 0.f;

    const int nChunks = K >> 5;

#pragma unroll
    for (int i = 0; i < PV_NST - 1; ++i) {
        load_chunk(i, i);
        cp_commit();
    }

    const int rl = lane & 7;
    const int gq = lane >> 3;
    const uint32_t aoff = (uint32_t)((warp_m * 32 + (gq & 1) * 8 + rl) * ROWB + (gq >> 1) * 16);
    const int brow_in = (gq & 1) * 8 + rl;            // k within 16-block
    const int bcol16  = warp_n * 8 + (gq >> 1);       // + g*2 at use site

    for (int kc = 0; kc < nChunks; ++kc) {
        const int pf = kc + PV_NST - 1;
        if (pf < nChunks) load_chunk(pf, pf % PV_NST);
        cp_commit();
        asm volatile("cp.async.wait_group %0;" :: "n"(PV_NST - 1));
        __syncthreads();

        const uint32_t st = sb + (kc % PV_NST) * PV_STAGE;
        const uint32_t bt0 = st + TILEB;
#pragma unroll
        for (int ks = 0; ks < 2; ++ks) {
            uint32_t ah[2][4];
#pragma unroll
            for (int i = 0; i < 2; ++i)
                ldm_x4(ah[i], st + aoff + i * (16 * ROWB) + ks * 32);
            uint32_t bt[4][4];
            const int row = ks * 16 + brow_in;
#pragma unroll
            for (int g = 0; g < 4; ++g) {
                const int c = (bcol16 + g * 2) ^ (row & 7);
                ldm_x4_t(bt[g], bt0 + row * 256 + c * 16);
            }
#pragma unroll
            for (int i = 0; i < 2; ++i)
#pragma unroll
                for (int j = 0; j < 8; ++j) {
                    const int g = j >> 1, o = (j & 1) * 2;
                    mma16816(acc[i][j], ah[i], bt[g][o], bt[g][o + 1]);
                }
        }
        __syncthreads();
    }

    // epilogue: hi only, *scale
    const int r_in = lane >> 2;
    const int c_in = (lane & 3) * 2;
#pragma unroll
    for (int i = 0; i < 2; ++i) {
#pragma unroll
        for (int j = 0; j < 8; ++j) {
            const int row0 = by + warp_m * 32 + i * 16 + r_in;
            const int row1 = row0 + 8;
            const int col  = bx + warp_n * 64 + j * 8 + c_in;
            float v00 = acc[i][j][0] * scale, v01 = acc[i][j][1] * scale;
            float v10 = acc[i][j][2] * scale, v11 = acc[i][j][3] * scale;
            const long o0 = (long)bz * obs + (long)row0 * ldOut + col;
            const long o1 = (long)bz * obs + (long)row1 * ldOut + col;
            *reinterpret_cast<uint32_t*>(outHi + o0) =
                pack_h2(__float2half_rn(v00), __float2half_rn(v01));
            *reinterpret_cast<uint32_t*>(outHi + o1) =
                pack_h2(__float2half_rn(v10), __float2half_rn(v11));
        }
    }
}

// ---------------------------------------------------------------------------
// Elementwise split: fp32 -> (hi, lo) fp16
// ---------------------------------------------------------------------------
__global__ void split2d(const float4* __restrict__ in,
                        __half* __restrict__ oh, __half* __restrict__ ol, int n4)
{
    const int i = blockIdx.x * blockDim.x + threadIdx.x;
    if (i >= n4) return;
    const float4 v = in[i];
    __half h0, l0, h1, l1, h2, l2, h3, l3;
    split_h(v.x, h0, l0); split_h(v.y, h1, l1);
    split_h(v.z, h2, l2); split_h(v.w, h3, l3);
    uint2 H, L;
    H.x = pack_h2(h0, h1); H.y = pack_h2(h2, h3);
    L.x = pack_h2(l0, l1); L.y = pack_h2(l2, l3);
    *reinterpret_cast<uint2*>(oh + 4 * (long)i) = H;
    *reinterpret_cast<uint2*>(ol + 4 * (long)i) = L;
}

// ---------------------------------------------------------------------------
// Weight transpose + split: W[K,N] fp32 -> Wt hi/lo [N,K] fp16 (lo optional)
// ---------------------------------------------------------------------------
__global__ void wsplit(const float* __restrict__ W,
                       __half* __restrict__ oh, __half* __restrict__ ol)
{
    __shared__ float t[32][33];
    const int n0 = blockIdx.x * 32, k0 = blockIdx.y * 32;
    const int tx = threadIdx.x, ty = threadIdx.y;
#pragma unroll
    for (int i = 0; i < 32; i += 8)
        t[ty + i][tx] = W[(long)(k0 + ty + i) * EMB + n0 + tx];
    __syncthreads();
#pragma unroll
    for (int i = 0; i < 32; i += 8) {
        __half h, l;
        split_h(t[tx][ty + i], h, l);
        const long o = (long)(n0 + ty + i) * EMB + k0 + tx;
        oh[o] = h;
        if (ol) ol[o] = l;
    }
}

// ---------------------------------------------------------------------------
// Row softmax over fp32 P, emitting fp16 hi scaled by P_SCALE
// ---------------------------------------------------------------------------
__global__ void __launch_bounds__(256)
softmax_h(const float* __restrict__ P, __half* __restrict__ Ph)
{
    __shared__ float sred[8];
    __shared__ float sbc[2];
    const int tid = threadIdx.x;
    const long base = (long)blockIdx.x * SEQ;

    float v[8];
#pragma unroll
    for (int j = 0; j < 8; j++) v[j] = P[base + tid + j * 256];

    float m = v[0];
#pragma unroll
    for (int j = 1; j < 8; j++) m = fmaxf(m, v[j]);
#pragma unroll
    for (int o = 16; o > 0; o >>= 1) m = fmaxf(m, __shfl_xor_sync(0xffffffffu, m, o));
    if ((tid & 31) == 0) sred[tid >> 5] = m;
    __syncthreads();
    if (tid == 0) {
        float t = sred[0];
#pragma unroll
        for (int w = 1; w < 8; w++) t = fmaxf(t, sred[w]);
        sbc[0] = t;
    }
    __syncthreads();
    m = sbc[0];

    float s = 0.f;
#pragma unroll
    for (int j = 0; j < 8; j++) { v[j] = __expf(v[j] - m); s += v[j]; }
#pragma unroll
    for (int o = 16; o > 0; o >>= 1) s += __shfl_xor_sync(0xffffffffu, s, o);
    __syncthreads();
    if ((tid & 31) == 0) sred[tid >> 5] = s;
    __syncthreads();
    if (tid == 0) {
        float t = sred[0];
#pragma unroll
        for (int w = 1; w < 8; w++) t += sred[w];
        sbc[1] = t;
    }
    __syncthreads();
    const float inv = P_SCALE / sbc[1];

#pragma unroll
    for (int j = 0; j < 8; j++)
        Ph[base + tid + j * 256] = __float2half_rn(v[j] * inv);
}

// ---------------------------------------------------------------------------
// Host side
// ---------------------------------------------------------------------------
extern "C" void kernel_launch(void* const* d_in, const int* in_sizes, int n_in,
                              void* d_out, int out_size)
{
    const float* x  = (const float*)d_in[0];
    const float* Wq = (const float*)d_in[1];
    const float* bq = (const float*)d_in[2];
    const float* Wk = (const float*)d_in[3];
    const float* bk = (const float*)d_in[4];
    const float* Wv = (const float*)d_in[5];
    const float* bv = (const float*)d_in[6];
    const float* Wo = (const float*)d_in[7];
    const float* bo = (const float*)d_in[8];
    float* out = (float*)d_out;

    void *xh, *xl, *Wqh, *Wql, *Wkh, *Wvh, *Woh;
    void *Qh, *Ql, *Kh, *Vh, *Pf, *Ph, *Ch;
    cudaGetSymbolAddress(&xh, g_xh);   cudaGetSymbolAddress(&xl, g_xl);
    cudaGetSymbolAddress(&Wqh, g_Wqh); cudaGetSymbolAddress(&Wql, g_Wql);
    cudaGetSymbolAddress(&Wkh, g_Wkh);
    cudaGetSymbolAddress(&Wvh, g_Wvh);
    cudaGetSymbolAddress(&Woh, g_Woh);
    cudaGetSymbolAddress(&Qh, g_Qh);   cudaGetSymbolAddress(&Ql, g_Ql);
    cudaGetSymbolAddress(&Kh, g_Kh);
    cudaGetSymbolAddress(&Vh, g_Vh);
    cudaGetSymbolAddress(&Pf, g_P);
    cudaGetSymbolAddress(&Ph, g_Ph);
    cudaGetSymbolAddress(&Ch, g_Ch);

    const int SM4 = 2 * 4 * TILEB;       // 81920 (Q proj: 2 stages x 4 tiles)
    const int SM3 = 3 * 3 * TILEB;       // 92160 (K/V proj, scores: 3 stages x 3 tiles)
    const int SM2 = 4 * 2 * TILEB;       // 81920 (out proj: 4 stages x 2 tiles)
    const int SMP = PV_NST * PV_STAGE;   // 92160 (PV: 5 stages)
    cudaFuncSetAttribute(gemm_mma<1,true,true>,   cudaFuncAttributeMaxDynamicSharedMemorySize, SM4);
    cudaFuncSetAttribute(gemm_mma<2,true,false>,  cudaFuncAttributeMaxDynamicSharedMemorySize, SM3);
    cudaFuncSetAttribute(gemm_mma<0,true,false>,  cudaFuncAttributeMaxDynamicSharedMemorySize, SM3);
    cudaFuncSetAttribute(gemm_mma<0,false,false>, cudaFuncAttributeMaxDynamicSharedMemorySize, SM2);
    cudaFuncSetAttribute(gemm_pv,                 cudaFuncAttributeMaxDynamicSharedMemorySize, SMP);

    const float scl = 1.0f / sqrtf((float)EMB);
    const dim3 blk(256);

    // 1) split inputs
    {
        const int n4 = MROWS * EMB / 4;
        split2d<<<(n4 + 255) / 256, 256>>>((const float4*)x, (__half*)xh, (__half*)xl, n4);
        dim3 wg(24, 24), wb(32, 8);
        wsplit<<<wg, wb>>>(Wq, (__half*)Wqh, (__half*)Wql);
        wsplit<<<wg, wb>>>(Wk, (__half*)Wkh, nullptr);
        wsplit<<<wg, wb>>>(Wv, (__half*)Wvh, nullptr);
        wsplit<<<wg, wb>>>(Wo, (__half*)Woh, nullptr);
    }

    // 2) projections: [16384,768] x [768,768]^T, K=768
    //    Q: 3-term (needs split output for 2-term scores); K/V: 2-term, hi out.
    gemm_mma<1,true,true><<<dim3(6, 128, 1), blk, SM4>>>(
        (const __half*)xh, (const __half*)xl, (const __half*)Wqh, (const __half*)Wql,
        EMB, EMB, EMB, 0, 0,
        nullptr, (__half*)Qh, (__half*)Ql, bq, scl, EMB, 0);
    gemm_mma<2,true,false><<<dim3(6, 128, 1), blk, SM3>>>(
        (const __half*)xh, (const __half*)xl, (const __half*)Wkh, nullptr,
        EMB, EMB, EMB, 0, 0,
        nullptr, (__half*)Kh, nullptr, bk, 1.0f, EMB, 0);
    gemm_mma<2,true,false><<<dim3(6, 128, 1), blk, SM3>>>(
        (const __half*)xh, (const __half*)xl, (const __half*)Wvh, nullptr,
        EMB, EMB, EMB, 0, 0,
        nullptr, (__half*)Vh, nullptr, bv, 1.0f, EMB, 0);

    // 3) scores = Q' @ K^T (scale folded into Q), fp32 out, 2-term
    gemm_mma<0,true,false><<<dim3(16, 16, 8), blk, SM3>>>(
        (const __half*)Qh, (const __half*)Ql, (const __half*)Kh, nullptr,
        EMB, EMB, EMB, (long)SEQ * EMB, (long)SEQ * EMB,
        (float*)Pf, nullptr, nullptr, nullptr, 1.0f, SEQ, (long)SEQ * SEQ);

    // 4) softmax -> P hi (x P_SCALE)
    softmax_h<<<MROWS, 256>>>((const float*)Pf, (__half*)Ph);

    // 5) ctx = P @ V, 1-term, B = V row-major via trans-ldmatrix, K=2048
    gemm_pv<<<dim3(6, 16, 8), blk, SMP>>>(
        (const __half*)Ph, (const __half*)Vh,
        SEQ, SEQ, EMB, (long)SEQ * SEQ, (long)SEQ * EMB,
        (__half*)Ch, 1.0f / P_SCALE, EMB, (long)SEQ * EMB);

    // 6) out = C @ Wo^T + bo, fp32, 1-term
    gemm_mma<0,false,false><<<dim3(6, 128, 1), blk, SM2>>>(
        (const __half*)Ch, nullptr, (const __half*)Woh, nullptr,
        EMB, EMB, EMB, 0, 0,
        out, nullptr, nullptr, bo, 1.0f, EMB, 0);
}

// round 8
// speedup vs baseline: 4.2887x; 1.0420x over previous
#include <cuda_runtime.h>
#include <cuda_fp16.h>
#include <math.h>
#include <stdint.h>

#define BSZ 8
#define SEQ 2048
#define EMB 768
#define MROWS (BSZ*SEQ)
#define P_SCALE 1024.0f

// ---------------------------------------------------------------------------
// Scratch (device globals; allocation forbidden in kernel_launch)
// ---------------------------------------------------------------------------
__device__ __align__(256) __half g_xh[MROWS*EMB], g_xl[MROWS*EMB];
__device__ __align__(256) __half g_Wqh[EMB*EMB], g_Wql[EMB*EMB];
__device__ __align__(256) __half g_Wkh[EMB*EMB];
__device__ __align__(256) __half g_Wvh[EMB*EMB];
__device__ __align__(256) __half g_Woh[EMB*EMB];
__device__ __align__(256) __half g_Qh[MROWS*EMB], g_Ql[MROWS*EMB];
__device__ __align__(256) __half g_Kh[MROWS*EMB];
__device__ __align__(256) __half g_Vh[MROWS*EMB];                  // V hi, row-major [b,s,e]
__device__ __align__(256) float  g_P[(size_t)BSZ*SEQ*SEQ];         // fp32 scores
__device__ __align__(256) __half g_Ph[(size_t)BSZ*SEQ*SEQ];        // softmax hi (x P_SCALE)
__device__ __align__(256) __half g_Ch[MROWS*EMB];

// ---------------------------------------------------------------------------
// helpers
// ---------------------------------------------------------------------------
__device__ __forceinline__ uint32_t smem_u32(const void* p) {
    uint32_t a;
    asm("{ .reg .u64 t; cvta.to.shared.u64 t, %1; cvt.u32.u64 %0, t; }" : "=r"(a) : "l"(p));
    return a;
}
__device__ __forceinline__ void cpasync16(uint32_t s, const void* g) {
    asm volatile("cp.async.cg.shared.global [%0], [%1], 16;" :: "r"(s), "l"(g));
}
__device__ __forceinline__ void cp_commit() { asm volatile("cp.async.commit_group;"); }

__device__ __forceinline__ void ldm_x4(uint32_t (&r)[4], uint32_t a) {
    asm volatile("ldmatrix.sync.aligned.m8n8.x4.shared.b16 {%0,%1,%2,%3}, [%4];"
        : "=r"(r[0]), "=r"(r[1]), "=r"(r[2]), "=r"(r[3]) : "r"(a));
}
__device__ __forceinline__ void ldm_x4_t(uint32_t (&r)[4], uint32_t a) {
    asm volatile("ldmatrix.sync.aligned.m8n8.x4.trans.shared.b16 {%0,%1,%2,%3}, [%4];"
        : "=r"(r[0]), "=r"(r[1]), "=r"(r[2]), "=r"(r[3]) : "r"(a));
}
__device__ __forceinline__ void mma16816(float (&d)[4], const uint32_t (&a)[4],
                                         uint32_t b0, uint32_t b1) {
    asm volatile("mma.sync.aligned.m16n8k16.row.col.f32.f16.f16.f32 "
        "{%0,%1,%2,%3}, {%4,%5,%6,%7}, {%8,%9}, {%0,%1,%2,%3};"
        : "+f"(d[0]), "+f"(d[1]), "+f"(d[2]), "+f"(d[3])
        : "r"(a[0]), "r"(a[1]), "r"(a[2]), "r"(a[3]), "r"(b0), "r"(b1));
}
__device__ __forceinline__ void split_h(float v, __half& h, __half& l) {
    h = __float2half_rn(v);
    l = __float2half_rn(v - __half2float(h));
}
__device__ __forceinline__ uint32_t pack_h2(__half a, __half b) {
    __half2 t(a, b);
    return *reinterpret_cast<uint32_t*>(&t);
}

#define ROWB   80                       // K-major tile row: 64B data + 16B pad
#define TILEB  (128*ROWB)               // 10240 B

// ---------------------------------------------------------------------------
// Generic split-fp16 warp-MMA GEMM: D[m,n] = sum_k A[m,k]*B[n,k] (both K-major)
// Terms: Ah*Bh + [ALO] Al*Bh + [BLO] Ah*Bl.  fp32 accum.
// CTA 128x128, Kc=32, 8 warps (32x64), multi-stage cp.async:
//   NT=4 -> 2 stages (two-sync loop), NT=3 -> 3 stages, NT=2 -> 4 stages
//   (NSTAGE>=3 use the single-sync loop: wait -> sync -> load next -> compute).
// MODE 0: fp32 (+bias). MODE 1: split hi/lo ((acc+bias)*scale). MODE 2: hi only.
// Optional B-set split: CTAs with blockIdx.x >= splitX use Bh2/bias2/outHi2
// (merges K and V projections into one launch to amortize wave tails).
// ---------------------------------------------------------------------------
template <int MODE, bool ALO, bool BLO>
__global__ void __launch_bounds__(256, 2)
gemm_mma(const __half* __restrict__ Ah, const __half* __restrict__ Al,
         const __half* __restrict__ Bh, const __half* __restrict__ Bl,
         int K, long ldA, long ldB, long sAb, long sBb,
         float* __restrict__ outF,
         __half* __restrict__ outHi, __half* __restrict__ outLo,
         const float* __restrict__ bias, float scale, long ldOut, long obs,
         const __half* __restrict__ Bh2, const float* __restrict__ bias2,
         __half* __restrict__ outHi2, int splitX)
{
    constexpr int NT     = 2 + (ALO ? 1 : 0) + (BLO ? 1 : 0);
    constexpr int NSTAGE = (NT == 4) ? 2 : ((NT == 3) ? 3 : 4);
    constexpr int STAGEB = NT * TILEB;
    constexpr int OFF_B  = (1 + (ALO ? 1 : 0)) * TILEB;   // B hi tile offset
    constexpr int OFF_BL = OFF_B + TILEB;

    extern __shared__ char smem[];
    const uint32_t sb = smem_u32(smem);

    const int tid    = threadIdx.x;
    const int lane   = tid & 31;
    const int wid    = tid >> 5;
    const int warp_m = wid & 3;
    const int warp_n = wid >> 2;

    int bxi = blockIdx.x;
    if (splitX > 0 && bxi >= splitX) {
        Bh    = Bh2;
        bias  = bias2;
        outHi = outHi2;
        bxi  -= splitX;
    }
    const int by = blockIdx.y * 128;
    const int bx = bxi * 128;
    const int bz = blockIdx.z;

    Ah += (long)bz * sAb;
    if (ALO) Al += (long)bz * sAb;
    Bh += (long)bz * sBb;
    if (BLO) Bl += (long)bz * sBb;

    const int lr0 = tid >> 2, lg0 = tid & 3;
    const int lr1 = (tid + 256) >> 2, lg1 = (tid + 256) & 3;

    auto load_chunk = [&](int kc, int stage) {
        const long kk = (long)kc * 32;
        const uint32_t s0 = sb + stage * STAGEB;
        const __half* srcs[4];
        int nsrc = 0;
        srcs[nsrc++] = Ah;
        if (ALO) srcs[nsrc++] = Al;
        srcs[nsrc++] = Bh;
        if (BLO) srcs[nsrc++] = Bl;
#pragma unroll
        for (int m = 0; m < NT; ++m) {
            const bool isA = (m < 1 + (ALO ? 1 : 0));
            const long ld  = isA ? ldA : ldB;
            const int  r0  = isA ? by : bx;
            const uint32_t sm = s0 + m * TILEB;
            cpasync16(sm + lr0 * ROWB + lg0 * 16,
                      srcs[m] + (long)(r0 + lr0) * ld + kk + lg0 * 8);
            cpasync16(sm + lr1 * ROWB + lg1 * 16,
                      srcs[m] + (long)(r0 + lr1) * ld + kk + lg1 * 8);
        }
    };

    float acc[2][8][4];
#pragma unroll
    for (int i = 0; i < 2; ++i)
#pragma unroll
        for (int j = 0; j < 8; ++j)
#pragma unroll
            for (int e = 0; e < 4; ++e) acc[i][j][e] = 0.f;

    const int nChunks = K >> 5;

#pragma unroll
    for (int i = 0; i < NSTAGE - 1; ++i) {
        load_chunk(i, i);
        cp_commit();
    }

    const int rl = lane & 7;
    const int gq = lane >> 3;
    const uint32_t aoff = (uint32_t)((warp_m * 32 + (gq & 1) * 8 + rl) * ROWB + (gq >> 1) * 16);
    const uint32_t boff = (uint32_t)((warp_n * 64 + (gq >> 1) * 8 + rl) * ROWB + (gq & 1) * 16);

    auto do_chunk = [&](uint32_t st) {
#pragma unroll
        for (int ks = 0; ks < 2; ++ks) {
            const uint32_t kb = ks * 32;
            uint32_t ah[2][4], al[2][4];
#pragma unroll
            for (int i = 0; i < 2; ++i) {
                ldm_x4(ah[i], st + aoff + i * (16 * ROWB) + kb);
                if (ALO) ldm_x4(al[i], st + TILEB + aoff + i * (16 * ROWB) + kb);
            }
            uint32_t bh[4][4];
#pragma unroll
            for (int g = 0; g < 4; ++g)
                ldm_x4(bh[g], st + OFF_B + boff + g * (16 * ROWB) + kb);
#pragma unroll
            for (int i = 0; i < 2; ++i)
#pragma unroll
                for (int j = 0; j < 8; ++j) {
                    const int g = j >> 1, o = (j & 1) * 2;
                    mma16816(acc[i][j], ah[i], bh[g][o], bh[g][o + 1]);
                    if (ALO) mma16816(acc[i][j], al[i], bh[g][o], bh[g][o + 1]);
                }
            if (BLO) {
                uint32_t bl[4][4];
#pragma unroll
                for (int g = 0; g < 4; ++g)
                    ldm_x4(bl[g], st + OFF_BL + boff + g * (16 * ROWB) + kb);
#pragma unroll
                for (int i = 0; i < 2; ++i)
#pragma unroll
                    for (int j = 0; j < 8; ++j) {
                        const int g = j >> 1, o = (j & 1) * 2;
                        mma16816(acc[i][j], ah[i], bl[g][o], bl[g][o + 1]);
                    }
            }
        }
    };

    if (NSTAGE == 2) {
        // two-sync loop (load next before wait keeps one chunk in flight)
        for (int kc = 0; kc < nChunks; ++kc) {
            const int pf = kc + 1;
            if (pf < nChunks) load_chunk(pf, pf & 1);
            cp_commit();
            asm volatile("cp.async.wait_group 1;");
            __syncthreads();
            do_chunk(sb + (kc & 1) * STAGEB);
            __syncthreads();
        }
    } else {
        // single-sync loop: wait(kc ready) -> sync (all warps done kc-1)
        // -> issue loads into slot (kc-1)%NSTAGE -> compute kc.
        for (int kc = 0; kc < nChunks; ++kc) {
            asm volatile("cp.async.wait_group %0;" :: "n"(NSTAGE - 2));
            __syncthreads();
            const int pf = kc + NSTAGE - 1;
            if (pf < nChunks) load_chunk(pf, pf % NSTAGE);
            cp_commit();
            do_chunk(sb + (kc % NSTAGE) * STAGEB);
        }
    }

    // ---------------- epilogue ----------------
    const int r_in = lane >> 2;
    const int c_in = (lane & 3) * 2;

#pragma unroll
    for (int i = 0; i < 2; ++i) {
#pragma unroll
        for (int j = 0; j < 8; ++j) {
            const int row0 = by + warp_m * 32 + i * 16 + r_in;
            const int row1 = row0 + 8;
            const int col  = bx + warp_n * 64 + j * 8 + c_in;
            const float b0 = bias ? bias[col]     : 0.f;
            const float b1 = bias ? bias[col + 1] : 0.f;

            if (MODE == 0) {
                float2 v0 = make_float2(acc[i][j][0] + b0, acc[i][j][1] + b1);
                float2 v1 = make_float2(acc[i][j][2] + b0, acc[i][j][3] + b1);
                *reinterpret_cast<float2*>(outF + (long)bz * obs + (long)row0 * ldOut + col) = v0;
                *reinterpret_cast<float2*>(outF + (long)bz * obs + (long)row1 * ldOut + col) = v1;
            } else if (MODE == 1) {
                float v00 = (acc[i][j][0] + b0) * scale, v01 = (acc[i][j][1] + b1) * scale;
                float v10 = (acc[i][j][2] + b0) * scale, v11 = (acc[i][j][3] + b1) * scale;
                __half h0, l0, h1, l1;
                split_h(v00, h0, l0); split_h(v01, h1, l1);
                const long o0 = (long)bz * obs + (long)row0 * ldOut + col;
                *reinterpret_cast<uint32_t*>(outHi + o0) = pack_h2(h0, h1);
                *reinterpret_cast<uint32_t*>(outLo + o0) = pack_h2(l0, l1);
                split_h(v10, h0, l0); split_h(v11, h1, l1);
                const long o1 = (long)bz * obs + (long)row1 * ldOut + col;
                *reinterpret_cast<uint32_t*>(outHi + o1) = pack_h2(h0, h1);
                *reinterpret_cast<uint32_t*>(outLo + o1) = pack_h2(l0, l1);
            } else {  // MODE 2: hi only
                float v00 = (acc[i][j][0] + b0) * scale, v01 = (acc[i][j][1] + b1) * scale;
                float v10 = (acc[i][j][2] + b0) * scale, v11 = (acc[i][j][3] + b1) * scale;
                const long o0 = (long)bz * obs + (long)row0 * ldOut + col;
                const long o1 = (long)bz * obs + (long)row1 * ldOut + col;
                *reinterpret_cast<uint32_t*>(outHi + o0) =
                    pack_h2(__float2half_rn(v00), __float2half_rn(v01));
                *reinterpret_cast<uint32_t*>(outHi + o1) =
                    pack_h2(__float2half_rn(v10), __float2half_rn(v11));
            }
        }
    }
}

// ---------------------------------------------------------------------------
// PV GEMM: C[m,e] = sum_s P[m,s] * V[s,e]. A = Ph K-major; B = V row-major
// [s,e] loaded via trans-ldmatrix from swizzled [k=32 x 256B] smem tiles.
// 1-term (P hi only). Single-sync 5-stage pipeline. Hi-only out, *scale.
// ---------------------------------------------------------------------------
#define PV_BTILE 8192                        // 32 rows x 256B, swizzled
#define PV_STAGE (TILEB + PV_BTILE)          // 18432
#define PV_NST   5

__global__ void __launch_bounds__(256, 2)
gemm_pv(const __half* __restrict__ Ah, const __half* __restrict__ Bv,
        int K, long ldA, long ldB, long sAb, long sBb,
        __half* __restrict__ outHi, float scale, long ldOut, long obs)
{
    extern __shared__ char smem[];
    const uint32_t sb = smem_u32(smem);

    const int tid    = threadIdx.x;
    const int lane   = tid & 31;
    const int wid    = tid >> 5;
    const int warp_m = wid & 3;
    const int warp_n = wid >> 2;
    const int by     = blockIdx.y * 128;
    const int bx     = blockIdx.x * 128;
    const int bz     = blockIdx.z;

    Ah += (long)bz * sAb;
    Bv += (long)bz * sBb;

    const int lr0 = tid >> 2, lg0 = tid & 3;
    const int lr1 = (tid + 256) >> 2, lg1 = (tid + 256) & 3;
    const int bk0 = tid >> 4,  bg0 = tid & 15;
    const int bk1 = (tid + 256) >> 4, bg1 = (tid + 256) & 15;

    auto load_chunk = [&](int kc, int stage) {
        const long kk = (long)kc * 32;
        const uint32_t s0 = sb + stage * PV_STAGE;
        cpasync16(s0 + lr0 * ROWB + lg0 * 16, Ah + (long)(by + lr0) * ldA + kk + lg0 * 8);
        cpasync16(s0 + lr1 * ROWB + lg1 * 16, Ah + (long)(by + lr1) * ldA + kk + lg1 * 8);
        const uint32_t b0 = s0 + TILEB;
        cpasync16(b0 + bk0 * 256 + ((bg0 ^ (bk0 & 7)) * 16),
                  Bv + (long)(kk + bk0) * ldB + bx + bg0 * 8);
        cpasync16(b0 + bk1 * 256 + ((bg1 ^ (bk1 & 7)) * 16),
                  Bv + (long)(kk + bk1) * ldB + bx + bg1 * 8);
    };

    float acc[2][8][4];
#pragma unroll
    for (int i = 0; i < 2; ++i)
#pragma unroll
        for (int j = 0; j < 8; ++j)
#pragma unroll
            for (int e = 0; e < 4; ++e) acc[i][j][e] = 0.f;

    const int nChunks = K >> 5;

#pragma unroll
    for (int i = 0; i < PV_NST - 1; ++i) {
        load_chunk(i, i);
        cp_commit();
    }

    const int rl = lane & 7;
    const int gq = lane >> 3;
    const uint32_t aoff = (uint32_t)((warp_m * 32 + (gq & 1) * 8 + rl) * ROWB + (gq >> 1) * 16);
    const int brow_in = (gq & 1) * 8 + rl;            // k within 16-block
    const int bcol16  = warp_n * 8 + (gq >> 1);       // + g*2 at use site

    for (int kc = 0; kc < nChunks; ++kc) {
        asm volatile("cp.async.wait_group %0;" :: "n"(PV_NST - 2));
        __syncthreads();
        const int pf = kc + PV_NST - 1;
        if (pf < nChunks) load_chunk(pf, pf % PV_NST);
        cp_commit();

        const uint32_t st = sb + (kc % PV_NST) * PV_STAGE;
        const uint32_t bt0 = st + TILEB;
#pragma unroll
        for (int ks = 0; ks < 2; ++ks) {
            uint32_t ah[2][4];
#pragma unroll
            for (int i = 0; i < 2; ++i)
                ldm_x4(ah[i], st + aoff + i * (16 * ROWB) + ks * 32);
            uint32_t bt[4][4];
            const int row = ks * 16 + brow_in;
#pragma unroll
            for (int g = 0; g < 4; ++g) {
                const int c = (bcol16 + g * 2) ^ (row & 7);
                ldm_x4_t(bt[g], bt0 + row * 256 + c * 16);
            }
#pragma unroll
            for (int i = 0; i < 2; ++i)
#pragma unroll
                for (int j = 0; j < 8; ++j) {
                    const int g = j >> 1, o = (j & 1) * 2;
                    mma16816(acc[i][j], ah[i], bt[g][o], bt[g][o + 1]);
                }
        }
    }

    // epilogue: hi only, *scale
    const int r_in = lane >> 2;
    const int c_in = (lane & 3) * 2;
#pragma unroll
    for (int i = 0; i < 2; ++i) {
#pragma unroll
        for (int j = 0; j < 8; ++j) {
            const int row0 = by + warp_m * 32 + i * 16 + r_in;
            const int row1 = row0 + 8;
            const int col  = bx + warp_n * 64 + j * 8 + c_in;
            float v00 = acc[i][j][0] * scale, v01 = acc[i][j][1] * scale;
            float v10 = acc[i][j][2] * scale, v11 = acc[i][j][3] * scale;
            const long o0 = (long)bz * obs + (long)row0 * ldOut + col;
            const long o1 = (long)bz * obs + (long)row1 * ldOut + col;
            *reinterpret_cast<uint32_t*>(outHi + o0) =
                pack_h2(__float2half_rn(v00), __float2half_rn(v01));
            *reinterpret_cast<uint32_t*>(outHi + o1) =
                pack_h2(__float2half_rn(v10), __float2half_rn(v11));
        }
    }
}

// ---------------------------------------------------------------------------
// Elementwise split: fp32 -> (hi, lo) fp16
// ---------------------------------------------------------------------------
__global__ void split2d(const float4* __restrict__ in,
                        __half* __restrict__ oh, __half* __restrict__ ol, int n4)
{
    const int i = blockIdx.x * blockDim.x + threadIdx.x;
    if (i >= n4) return;
    const float4 v = in[i];
    __half h0, l0, h1, l1, h2, l2, h3, l3;
    split_h(v.x, h0, l0); split_h(v.y, h1, l1);
    split_h(v.z, h2, l2); split_h(v.w, h3, l3);
    uint2 H, L;
    H.x = pack_h2(h0, h1); H.y = pack_h2(h2, h3);
    L.x = pack_h2(l0, l1); L.y = pack_h2(l2, l3);
    *reinterpret_cast<uint2*>(oh + 4 * (long)i) = H;
    *reinterpret_cast<uint2*>(ol + 4 * (long)i) = L;
}

// ---------------------------------------------------------------------------
// Weight transpose + split: W[K,N] fp32 -> Wt hi/lo [N,K] fp16 (lo optional)
// ---------------------------------------------------------------------------
__global__ void wsplit(const float* __restrict__ W,
                       __half* __restrict__ oh, __half* __restrict__ ol)
{
    __shared__ float t[32][33];
    const int n0 = blockIdx.x * 32, k0 = blockIdx.y * 32;
    const int tx = threadIdx.x, ty = threadIdx.y;
#pragma unroll
    for (int i = 0; i < 32; i += 8)
        t[ty + i][tx] = W[(long)(k0 + ty + i) * EMB + n0 + tx];
    __syncthreads();
#pragma unroll
    for (int i = 0; i < 32; i += 8) {
        __half h, l;
        split_h(t[tx][ty + i], h, l);
        const long o = (long)(n0 + ty + i) * EMB + k0 + tx;
        oh[o] = h;
        if (ol) ol[o] = l;
    }
}

// ---------------------------------------------------------------------------
// Row softmax over fp32 P, emitting fp16 hi scaled by P_SCALE.
// Vectorized: per-thread 8 contiguous floats (2x float4 in, 1x uint4 out).
// ---------------------------------------------------------------------------
__global__ void __launch_bounds__(256)
softmax_h(const float* __restrict__ P, __half* __restrict__ Ph)
{
    __shared__ float sred[8];
    __shared__ float sbc[2];
    const int tid = threadIdx.x;
    const long base = (long)blockIdx.x * SEQ;

    float v[8];
    {
        const float4 a = *reinterpret_cast<const float4*>(P + base + tid * 8);
        const float4 b = *reinterpret_cast<const float4*>(P + base + tid * 8 + 4);
        v[0] = a.x; v[1] = a.y; v[2] = a.z; v[3] = a.w;
        v[4] = b.x; v[5] = b.y; v[6] = b.z; v[7] = b.w;
    }

    float m = v[0];
#pragma unroll
    for (int j = 1; j < 8; j++) m = fmaxf(m, v[j]);
#pragma unroll
    for (int o = 16; o > 0; o >>= 1) m = fmaxf(m, __shfl_xor_sync(0xffffffffu, m, o));
    if ((tid & 31) == 0) sred[tid >> 5] = m;
    __syncthreads();
    if (tid == 0) {
        float t = sred[0];
#pragma unroll
        for (int w = 1; w < 8; w++) t = fmaxf(t, sred[w]);
        sbc[0] = t;
    }
    __syncthreads();
    m = sbc[0];

    float s = 0.f;
#pragma unroll
    for (int j = 0; j < 8; j++) { v[j] = __expf(v[j] - m); s += v[j]; }
#pragma unroll
    for (int o = 16; o > 0; o >>= 1) s += __shfl_xor_sync(0xffffffffu, s, o);
    __syncthreads();
    if ((tid & 31) == 0) sred[tid >> 5] = s;
    __syncthreads();
    if (tid == 0) {
        float t = sred[0];
#pragma unroll
        for (int w = 1; w < 8; w++) t += sred[w];
        sbc[1] = t;
    }
    __syncthreads();
    const float inv = P_SCALE / sbc[1];

    uint4 o;
    o.x = pack_h2(__float2half_rn(v[0] * inv), __float2half_rn(v[1] * inv));
    o.y = pack_h2(__float2half_rn(v[2] * inv), __float2half_rn(v[3] * inv));
    o.z = pack_h2(__float2half_rn(v[4] * inv), __float2half_rn(v[5] * inv));
    o.w = pack_h2(__float2half_rn(v[6] * inv), __float2half_rn(v[7] * inv));
    *reinterpret_cast<uint4*>(Ph + base + tid * 8) = o;
}

// ---------------------------------------------------------------------------
// Host side
// ---------------------------------------------------------------------------
extern "C" void kernel_launch(void* const* d_in, const int* in_sizes, int n_in,
                              void* d_out, int out_size)
{
    const float* x  = (const float*)d_in[0];
    const float* Wq = (const float*)d_in[1];
    const float* bq = (const float*)d_in[2];
    const float* Wk = (const float*)d_in[3];
    const float* bk = (const float*)d_in[4];
    const float* Wv = (const float*)d_in[5];
    const float* bv = (const float*)d_in[6];
    const float* Wo = (const float*)d_in[7];
    const float* bo = (const float*)d_in[8];
    float* out = (float*)d_out;

    void *xh, *xl, *Wqh, *Wql, *Wkh, *Wvh, *Woh;
    void *Qh, *Ql, *Kh, *Vh, *Pf, *Ph, *Ch;
    cudaGetSymbolAddress(&xh, g_xh);   cudaGetSymbolAddress(&xl, g_xl);
    cudaGetSymbolAddress(&Wqh, g_Wqh); cudaGetSymbolAddress(&Wql, g_Wql);
    cudaGetSymbolAddress(&Wkh, g_Wkh);
    cudaGetSymbolAddress(&Wvh, g_Wvh);
    cudaGetSymbolAddress(&Woh, g_Woh);
    cudaGetSymbolAddress(&Qh, g_Qh);   cudaGetSymbolAddress(&Ql, g_Ql);
    cudaGetSymbolAddress(&Kh, g_Kh);
    cudaGetSymbolAddress(&Vh, g_Vh);
    cudaGetSymbolAddress(&Pf, g_P);
    cudaGetSymbolAddress(&Ph, g_Ph);
    cudaGetSymbolAddress(&Ch, g_Ch);

    const int SM4 = 2 * 4 * TILEB;       // 81920 (Q proj: 2 stages x 4 tiles)
    const int SM3 = 3 * 3 * TILEB;       // 92160 (K/V proj, scores: 3 stages x 3 tiles)
    const int SM2 = 4 * 2 * TILEB;       // 81920 (out proj: 4 stages x 2 tiles)
    const int SMP = PV_NST * PV_STAGE;   // 92160 (PV: 5 stages)
    cudaFuncSetAttribute(gemm_mma<1,true,true>,   cudaFuncAttributeMaxDynamicSharedMemorySize, SM4);
    cudaFuncSetAttribute(gemm_mma<2,true,false>,  cudaFuncAttributeMaxDynamicSharedMemorySize, SM3);
    cudaFuncSetAttribute(gemm_mma<0,true,false>,  cudaFuncAttributeMaxDynamicSharedMemorySize, SM3);
    cudaFuncSetAttribute(gemm_mma<0,false,false>, cudaFuncAttributeMaxDynamicSharedMemorySize, SM2);
    cudaFuncSetAttribute(gemm_pv,                 cudaFuncAttributeMaxDynamicSharedMemorySize, SMP);

    const float scl = 1.0f / sqrtf((float)EMB);
    const dim3 blk(256);

    // 1) split inputs
    {
        const int n4 = MROWS * EMB / 4;
        split2d<<<(n4 + 255) / 256, 256>>>((const float4*)x, (__half*)xh, (__half*)xl, n4);
        dim3 wg(24, 24), wb(32, 8);
        wsplit<<<wg, wb>>>(Wq, (__half*)Wqh, (__half*)Wql);
        wsplit<<<wg, wb>>>(Wk, (__half*)Wkh, nullptr);
        wsplit<<<wg, wb>>>(Wv, (__half*)Wvh, nullptr);
        wsplit<<<wg, wb>>>(Wo, (__half*)Woh, nullptr);
    }

    // 2) projections: [16384,768] x [768,768]^T, K=768
    //    Q: 3-term, split out.  K+V: merged launch, 2-term, hi out.
    gemm_mma<1,true,true><<<dim3(6, 128, 1), blk, SM4>>>(
        (const __half*)xh, (const __half*)xl, (const __half*)Wqh, (const __half*)Wql,
        EMB, EMB, EMB, 0, 0,
        nullptr, (__half*)Qh, (__half*)Ql, bq, scl, EMB, 0,
        nullptr, nullptr, nullptr, 0);
    gemm_mma<2,true,false><<<dim3(12, 128, 1), blk, SM3>>>(
        (const __half*)xh, (const __half*)xl, (const __half*)Wkh, nullptr,
        EMB, EMB, EMB, 0, 0,
        nullptr, (__half*)Kh, nullptr, bk, 1.0f, EMB, 0,
        (const __half*)Wvh, bv, (__half*)Vh, 6);

    // 3) scores = Q' @ K^T (scale folded into Q), fp32 out, 2-term
    gemm_mma<0,true,false><<<dim3(16, 16, 8), blk, SM3>>>(
        (const __half*)Qh, (const __half*)Ql, (const __half*)Kh, nullptr,
        EMB, EMB, EMB, (long)SEQ * EMB, (long)SEQ * EMB,
        (float*)Pf, nullptr, nullptr, nullptr, 1.0f, SEQ, (long)SEQ * SEQ,
        nullptr, nullptr, nullptr, 0);

    // 4) softmax -> P hi (x P_SCALE)
    softmax_h<<<MROWS, 256>>>((const float*)Pf, (__half*)Ph);

    // 5) ctx = P @ V, 1-term, B = V row-major via trans-ldmatrix, K=2048
    gemm_pv<<<dim3(6, 16, 8), blk, SMP>>>(
        (const __half*)Ph, (const __half*)Vh,
        SEQ, SEQ, EMB, (long)SEQ * SEQ, (long)SEQ * EMB,
        (__half*)Ch, 1.0f / P_SCALE, EMB, (long)SEQ * EMB);

    // 6) out = C @ Wo^T + bo, fp32, 1-term
    gemm_mma<0,false,false><<<dim3(6, 128, 1), blk, SM2>>>(
        (const __half*)Ch, nullptr, (const __half*)Woh, nullptr,
        EMB, EMB, EMB, 0, 0,
        out, nullptr, nullptr, bo, 1.0f, EMB, 0,
        nullptr, nullptr, nullptr, 0);
}

// round 9
// speedup vs baseline: 4.6365x; 1.0811x over previous
#include <cuda_runtime.h>
#include <cuda_fp16.h>
#include <math.h>
#include <stdint.h>

#define BSZ 8
#define SEQ 2048
#define EMB 768
#define MROWS (BSZ*SEQ)
#define P_SCALE 1024.0f

// ---------------------------------------------------------------------------
// Scratch (device globals; allocation forbidden in kernel_launch)
// ---------------------------------------------------------------------------
__device__ __align__(256) __half g_xh[MROWS*EMB], g_xl[MROWS*EMB];
__device__ __align__(256) __half g_Wqh[EMB*EMB];
__device__ __align__(256) __half g_Wkh[EMB*EMB];
__device__ __align__(256) __half g_Wvh[EMB*EMB];
__device__ __align__(256) __half g_Woh[EMB*EMB];
__device__ __align__(256) __half g_Qh[MROWS*EMB], g_Ql[MROWS*EMB];
__device__ __align__(256) __half g_Kh[MROWS*EMB];
__device__ __align__(256) __half g_Vh[MROWS*EMB];                  // V hi, row-major [b,s,e]
__device__ __align__(256) float  g_P[(size_t)BSZ*SEQ*SEQ];         // fp32 scores
__device__ __align__(256) __half g_Ph[(size_t)BSZ*SEQ*SEQ];        // softmax hi (x P_SCALE)
__device__ __align__(256) __half g_Ch[MROWS*EMB];

// ---------------------------------------------------------------------------
// helpers
// ---------------------------------------------------------------------------
__device__ __forceinline__ uint32_t smem_u32(const void* p) {
    uint32_t a;
    asm("{ .reg .u64 t; cvta.to.shared.u64 t, %1; cvt.u32.u64 %0, t; }" : "=r"(a) : "l"(p));
    return a;
}
__device__ __forceinline__ void cpasync16(uint32_t s, const void* g) {
    asm volatile("cp.async.cg.shared.global [%0], [%1], 16;" :: "r"(s), "l"(g));
}
__device__ __forceinline__ void cp_commit() { asm volatile("cp.async.commit_group;"); }

__device__ __forceinline__ void ldm_x4(uint32_t (&r)[4], uint32_t a) {
    asm volatile("ldmatrix.sync.aligned.m8n8.x4.shared.b16 {%0,%1,%2,%3}, [%4];"
        : "=r"(r[0]), "=r"(r[1]), "=r"(r[2]), "=r"(r[3]) : "r"(a));
}
__device__ __forceinline__ void ldm_x4_t(uint32_t (&r)[4], uint32_t a) {
    asm volatile("ldmatrix.sync.aligned.m8n8.x4.trans.shared.b16 {%0,%1,%2,%3}, [%4];"
        : "=r"(r[0]), "=r"(r[1]), "=r"(r[2]), "=r"(r[3]) : "r"(a));
}
__device__ __forceinline__ void mma16816(float (&d)[4], const uint32_t (&a)[4],
                                         uint32_t b0, uint32_t b1) {
    asm volatile("mma.sync.aligned.m16n8k16.row.col.f32.f16.f16.f32 "
        "{%0,%1,%2,%3}, {%4,%5,%6,%7}, {%8,%9}, {%0,%1,%2,%3};"
        : "+f"(d[0]), "+f"(d[1]), "+f"(d[2]), "+f"(d[3])
        : "r"(a[0]), "r"(a[1]), "r"(a[2]), "r"(a[3]), "r"(b0), "r"(b1));
}
__device__ __forceinline__ void split_h(float v, __half& h, __half& l) {
    h = __float2half_rn(v);
    l = __float2half_rn(v - __half2float(h));
}
__device__ __forceinline__ uint32_t pack_h2(__half a, __half b) {
    __half2 t(a, b);
    return *reinterpret_cast<uint32_t*>(&t);
}

#define ROWB   80                       // K-major tile row: 64B data + 16B pad
#define TILEB  (128*ROWB)               // 10240 B

// Per-segment output descriptor (passed by value; selected per CTA by blockIdx.x)
struct BSeg {
    const __half* Bh;
    const float*  bias;
    __half*       outHi;
    __half*       outLo;   // null -> skip lo store (OUTMODE 1)
    float         scale;
};

// ---------------------------------------------------------------------------
// Split-fp16 warp-MMA GEMM: D[m,n] = sum_k A[m,k]*B[n,k] (both K-major)
// Terms: Ah*Bh + [ALO] Al*Bh.  fp32 accum.
// CTA 128x128, Kc=32, 8 warps (32x64), single-sync multistage cp.async:
//   NT=3 -> 3 stages, NT=2 -> 4 stages.
// OUTMODE 0: fp32 out (+bias, via outF).
// OUTMODE 1: fp16 hi out ((acc+bias)*scale), optional lo if seg.outLo != null.
// Segmented B: CTAs pick {s0,s1,s2} by blockIdx.x / segW (merged QKV launch).
// ---------------------------------------------------------------------------
template <int OUTMODE, bool ALO>
__global__ void __launch_bounds__(256, 2)
gemm_mma(const __half* __restrict__ Ah, const __half* __restrict__ Al,
         int K, long ldA, long ldB, long sAb, long sBb,
         float* __restrict__ outF, long ldOut, long obs,
         BSeg s0, BSeg s1, BSeg s2, int segW)
{
    constexpr int NT     = 2 + (ALO ? 1 : 0);
    constexpr int NSTAGE = (NT == 3) ? 3 : 4;
    constexpr int STAGEB = NT * TILEB;
    constexpr int OFF_B  = (1 + (ALO ? 1 : 0)) * TILEB;   // B hi tile offset

    extern __shared__ char smem[];
    const uint32_t sb = smem_u32(smem);

    const int tid    = threadIdx.x;
    const int lane   = tid & 31;
    const int wid    = tid >> 5;
    const int warp_m = wid & 3;
    const int warp_n = wid >> 2;

    int bxi = blockIdx.x;
    BSeg seg = s0;
    if (segW > 0) {
        if (bxi >= 2 * segW)      { seg = s2; bxi -= 2 * segW; }
        else if (bxi >= segW)     { seg = s1; bxi -= segW; }
    }
    const int by = blockIdx.y * 128;
    const int bx = bxi * 128;
    const int bz = blockIdx.z;

    Ah += (long)bz * sAb;
    if (ALO) Al += (long)bz * sAb;
    const __half* Bh = seg.Bh + (long)bz * sBb;

    const int lr0 = tid >> 2, lg0 = tid & 3;
    const int lr1 = (tid + 256) >> 2, lg1 = (tid + 256) & 3;

    auto load_chunk = [&](int kc, int stage) {
        const long kk = (long)kc * 32;
        const uint32_t s0a = sb + stage * STAGEB;
        const __half* srcs[3];
        int nsrc = 0;
        srcs[nsrc++] = Ah;
        if (ALO) srcs[nsrc++] = Al;
        srcs[nsrc++] = Bh;
#pragma unroll
        for (int m = 0; m < NT; ++m) {
            const bool isA = (m < 1 + (ALO ? 1 : 0));
            const long ld  = isA ? ldA : ldB;
            const int  r0  = isA ? by : bx;
            const uint32_t sm = s0a + m * TILEB;
            cpasync16(sm + lr0 * ROWB + lg0 * 16,
                      srcs[m] + (long)(r0 + lr0) * ld + kk + lg0 * 8);
            cpasync16(sm + lr1 * ROWB + lg1 * 16,
                      srcs[m] + (long)(r0 + lr1) * ld + kk + lg1 * 8);
        }
    };

    float acc[2][8][4];
#pragma unroll
    for (int i = 0; i < 2; ++i)
#pragma unroll
        for (int j = 0; j < 8; ++j)
#pragma unroll
            for (int e = 0; e < 4; ++e) acc[i][j][e] = 0.f;

    const int nChunks = K >> 5;

#pragma unroll
    for (int i = 0; i < NSTAGE - 1; ++i) {
        load_chunk(i, i);
        cp_commit();
    }

    const int rl = lane & 7;
    const int gq = lane >> 3;
    const uint32_t aoff = (uint32_t)((warp_m * 32 + (gq & 1) * 8 + rl) * ROWB + (gq >> 1) * 16);
    const uint32_t boff = (uint32_t)((warp_n * 64 + (gq >> 1) * 8 + rl) * ROWB + (gq & 1) * 16);

    // single-sync loop: wait(kc ready) -> sync (all warps done kc-1)
    // -> issue loads into slot (kc-1)%NSTAGE -> compute kc.
    for (int kc = 0; kc < nChunks; ++kc) {
        asm volatile("cp.async.wait_group %0;" :: "n"(NSTAGE - 2));
        __syncthreads();
        const int pf = kc + NSTAGE - 1;
        if (pf < nChunks) load_chunk(pf, pf % NSTAGE);
        cp_commit();

        const uint32_t st = sb + (kc % NSTAGE) * STAGEB;
#pragma unroll
        for (int ks = 0; ks < 2; ++ks) {
            const uint32_t kb = ks * 32;
            uint32_t ah[2][4], al[2][4];
#pragma unroll
            for (int i = 0; i < 2; ++i) {
                ldm_x4(ah[i], st + aoff + i * (16 * ROWB) + kb);
                if (ALO) ldm_x4(al[i], st + TILEB + aoff + i * (16 * ROWB) + kb);
            }
            uint32_t bh[4][4];
#pragma unroll
            for (int g = 0; g < 4; ++g)
                ldm_x4(bh[g], st + OFF_B + boff + g * (16 * ROWB) + kb);
#pragma unroll
            for (int i = 0; i < 2; ++i)
#pragma unroll
                for (int j = 0; j < 8; ++j) {
                    const int g = j >> 1, o = (j & 1) * 2;
                    mma16816(acc[i][j], ah[i], bh[g][o], bh[g][o + 1]);
                    if (ALO) mma16816(acc[i][j], al[i], bh[g][o], bh[g][o + 1]);
                }
        }
    }

    // ---------------- epilogue ----------------
    const int r_in = lane >> 2;
    const int c_in = (lane & 3) * 2;
    const bool doLo = (OUTMODE == 1) && (seg.outLo != nullptr);

#pragma unroll
    for (int i = 0; i < 2; ++i) {
#pragma unroll
        for (int j = 0; j < 8; ++j) {
            const int row0 = by + warp_m * 32 + i * 16 + r_in;
            const int row1 = row0 + 8;
            const int col  = bx + warp_n * 64 + j * 8 + c_in;
            const float b0 = seg.bias ? seg.bias[col]     : 0.f;
            const float b1 = seg.bias ? seg.bias[col + 1] : 0.f;

            if (OUTMODE == 0) {
                float2 v0 = make_float2(acc[i][j][0] + b0, acc[i][j][1] + b1);
                float2 v1 = make_float2(acc[i][j][2] + b0, acc[i][j][3] + b1);
                *reinterpret_cast<float2*>(outF + (long)bz * obs + (long)row0 * ldOut + col) = v0;
                *reinterpret_cast<float2*>(outF + (long)bz * obs + (long)row1 * ldOut + col) = v1;
            } else {
                float v00 = (acc[i][j][0] + b0) * seg.scale, v01 = (acc[i][j][1] + b1) * seg.scale;
                float v10 = (acc[i][j][2] + b0) * seg.scale, v11 = (acc[i][j][3] + b1) * seg.scale;
                const long o0 = (long)bz * obs + (long)row0 * ldOut + col;
                const long o1 = (long)bz * obs + (long)row1 * ldOut + col;
                if (doLo) {
                    __half h0, l0, h1, l1;
                    split_h(v00, h0, l0); split_h(v01, h1, l1);
                    *reinterpret_cast<uint32_t*>(seg.outHi + o0) = pack_h2(h0, h1);
                    *reinterpret_cast<uint32_t*>(seg.outLo + o0) = pack_h2(l0, l1);
                    split_h(v10, h0, l0); split_h(v11, h1, l1);
                    *reinterpret_cast<uint32_t*>(seg.outHi + o1) = pack_h2(h0, h1);
                    *reinterpret_cast<uint32_t*>(seg.outLo + o1) = pack_h2(l0, l1);
                } else {
                    *reinterpret_cast<uint32_t*>(seg.outHi + o0) =
                        pack_h2(__float2half_rn(v00), __float2half_rn(v01));
                    *reinterpret_cast<uint32_t*>(seg.outHi + o1) =
                        pack_h2(__float2half_rn(v10), __float2half_rn(v11));
                }
            }
        }
    }
}

// ---------------------------------------------------------------------------
// PV GEMM: C[m,e] = sum_s P[m,s] * V[s,e]. A = Ph K-major; B = V row-major
// [s,e] loaded via trans-ldmatrix from swizzled [k=32 x 256B] smem tiles.
// 1-term (P hi only). Single-sync 5-stage pipeline. Hi-only out, *scale.
// ---------------------------------------------------------------------------
#define PV_BTILE 8192                        // 32 rows x 256B, swizzled
#define PV_STAGE (TILEB + PV_BTILE)          // 18432
#define PV_NST   5

__global__ void __launch_bounds__(256, 2)
gemm_pv(const __half* __restrict__ Ah, const __half* __restrict__ Bv,
        int K, long ldA, long ldB, long sAb, long sBb,
        __half* __restrict__ outHi, float scale, long ldOut, long obs)
{
    extern __shared__ char smem[];
    const uint32_t sb = smem_u32(smem);

    const int tid    = threadIdx.x;
    const int lane   = tid & 31;
    const int wid    = tid >> 5;
    const int warp_m = wid & 3;
    const int warp_n = wid >> 2;
    const int by     = blockIdx.y * 128;
    const int bx     = blockIdx.x * 128;
    const int bz     = blockIdx.z;

    Ah += (long)bz * sAb;
    Bv += (long)bz * sBb;

    const int lr0 = tid >> 2, lg0 = tid & 3;
    const int lr1 = (tid + 256) >> 2, lg1 = (tid + 256) & 3;
    const int bk0 = tid >> 4,  bg0 = tid & 15;
    const int bk1 = (tid + 256) >> 4, bg1 = (tid + 256) & 15;

    auto load_chunk = [&](int kc, int stage) {
        const long kk = (long)kc * 32;
        const uint32_t s0 = sb + stage * PV_STAGE;
        cpasync16(s0 + lr0 * ROWB + lg0 * 16, Ah + (long)(by + lr0) * ldA + kk + lg0 * 8);
        cpasync16(s0 + lr1 * ROWB + lg1 * 16, Ah + (long)(by + lr1) * ldA + kk + lg1 * 8);
        const uint32_t b0 = s0 + TILEB;
        cpasync16(b0 + bk0 * 256 + ((bg0 ^ (bk0 & 7)) * 16),
                  Bv + (long)(kk + bk0) * ldB + bx + bg0 * 8);
        cpasync16(b0 + bk1 * 256 + ((bg1 ^ (bk1 & 7)) * 16),
                  Bv + (long)(kk + bk1) * ldB + bx + bg1 * 8);
    };

    float acc[2][8][4];
#pragma unroll
    for (int i = 0; i < 2; ++i)
#pragma unroll
        for (int j = 0; j < 8; ++j)
#pragma unroll
            for (int e = 0; e < 4; ++e) acc[i][j][e] = 0.f;

    const int nChunks = K >> 5;

#pragma unroll
    for (int i = 0; i < PV_NST - 1; ++i) {
        load_chunk(i, i);
        cp_commit();
    }

    const int rl = lane & 7;
    const int gq = lane >> 3;
    const uint32_t aoff = (uint32_t)((warp_m * 32 + (gq & 1) * 8 + rl) * ROWB + (gq >> 1) * 16);
    const int brow_in = (gq & 1) * 8 + rl;            // k within 16-block
    const int bcol16  = warp_n * 8 + (gq >> 1);       // + g*2 at use site

    for (int kc = 0; kc < nChunks; ++kc) {
        asm volatile("cp.async.wait_group %0;" :: "n"(PV_NST - 2));
        __syncthreads();
        const int pf = kc + PV_NST - 1;
        if (pf < nChunks) load_chunk(pf, pf % PV_NST);
        cp_commit();

        const uint32_t st = sb + (kc % PV_NST) * PV_STAGE;
        const uint32_t bt0 = st + TILEB;
#pragma unroll
        for (int ks = 0; ks < 2; ++ks) {
            uint32_t ah[2][4];
#pragma unroll
            for (int i = 0; i < 2; ++i)
                ldm_x4(ah[i], st + aoff + i * (16 * ROWB) + ks * 32);
            uint32_t bt[4][4];
            const int row = ks * 16 + brow_in;
#pragma unroll
            for (int g = 0; g < 4; ++g) {
                const int c = (bcol16 + g * 2) ^ (row & 7);
                ldm_x4_t(bt[g], bt0 + row * 256 + c * 16);
            }
#pragma unroll
            for (int i = 0; i < 2; ++i)
#pragma unroll
                for (int j = 0; j < 8; ++j) {
                    const int g = j >> 1, o = (j & 1) * 2;
                    mma16816(acc[i][j], ah[i], bt[g][o], bt[g][o + 1]);
                }
        }
    }

    // epilogue: hi only, *scale
    const int r_in = lane >> 2;
    const int c_in = (lane & 3) * 2;
#pragma unroll
    for (int i = 0; i < 2; ++i) {
#pragma unroll
        for (int j = 0; j < 8; ++j) {
            const int row0 = by + warp_m * 32 + i * 16 + r_in;
            const int row1 = row0 + 8;
            const int col  = bx + warp_n * 64 + j * 8 + c_in;
            float v00 = acc[i][j][0] * scale, v01 = acc[i][j][1] * scale;
            float v10 = acc[i][j][2] * scale, v11 = acc[i][j][3] * scale;
            const long o0 = (long)bz * obs + (long)row0 * ldOut + col;
            const long o1 = (long)bz * obs + (long)row1 * ldOut + col;
            *reinterpret_cast<uint32_t*>(outHi + o0) =
                pack_h2(__float2half_rn(v00), __float2half_rn(v01));
            *reinterpret_cast<uint32_t*>(outHi + o1) =
                pack_h2(__float2half_rn(v10), __float2half_rn(v11));
        }
    }
}

// ---------------------------------------------------------------------------
// Elementwise split: fp32 -> (hi, lo) fp16
// ---------------------------------------------------------------------------
__global__ void split2d(const float4* __restrict__ in,
                        __half* __restrict__ oh, __half* __restrict__ ol, int n4)
{
    const int i = blockIdx.x * blockDim.x + threadIdx.x;
    if (i >= n4) return;
    const float4 v = in[i];
    __half h0, l0, h1, l1, h2, l2, h3, l3;
    split_h(v.x, h0, l0); split_h(v.y, h1, l1);
    split_h(v.z, h2, l2); split_h(v.w, h3, l3);
    uint2 H, L;
    H.x = pack_h2(h0, h1); H.y = pack_h2(h2, h3);
    L.x = pack_h2(l0, l1); L.y = pack_h2(l2, l3);
    *reinterpret_cast<uint2*>(oh + 4 * (long)i) = H;
    *reinterpret_cast<uint2*>(ol + 4 * (long)i) = L;
}

// ---------------------------------------------------------------------------
// Weight transpose (hi only): W[K,N] fp32 -> Wt hi [N,K] fp16
// ---------------------------------------------------------------------------
__global__ void wsplit(const float* __restrict__ W, __half* __restrict__ oh)
{
    __shared__ float t[32][33];
    const int n0 = blockIdx.x * 32, k0 = blockIdx.y * 32;
    const int tx = threadIdx.x, ty = threadIdx.y;
#pragma unroll
    for (int i = 0; i < 32; i += 8)
        t[ty + i][tx] = W[(long)(k0 + ty + i) * EMB + n0 + tx];
    __syncthreads();
#pragma unroll
    for (int i = 0; i < 32; i += 8) {
        const long o = (long)(n0 + ty + i) * EMB + k0 + tx;
        oh[o] = __float2half_rn(t[tx][ty + i]);
    }
}

// ---------------------------------------------------------------------------
// Row softmax over fp32 P, emitting fp16 hi scaled by P_SCALE.
// Vectorized: per-thread 8 contiguous floats (2x float4 in, 1x uint4 out).
// ---------------------------------------------------------------------------
__global__ void __launch_bounds__(256)
softmax_h(const float* __restrict__ P, __half* __restrict__ Ph)
{
    __shared__ float sred[8];
    __shared__ float sbc[2];
    const int tid = threadIdx.x;
    const long base = (long)blockIdx.x * SEQ;

    float v[8];
    {
        const float4 a = *reinterpret_cast<const float4*>(P + base + tid * 8);
        const float4 b = *reinterpret_cast<const float4*>(P + base + tid * 8 + 4);
        v[0] = a.x; v[1] = a.y; v[2] = a.z; v[3] = a.w;
        v[4] = b.x; v[5] = b.y; v[6] = b.z; v[7] = b.w;
    }

    float m = v[0];
#pragma unroll
    for (int j = 1; j < 8; j++) m = fmaxf(m, v[j]);
#pragma unroll
    for (int o = 16; o > 0; o >>= 1) m = fmaxf(m, __shfl_xor_sync(0xffffffffu, m, o));
    if ((tid & 31) == 0) sred[tid >> 5] = m;
    __syncthreads();
    if (tid == 0) {
        float t = sred[0];
#pragma unroll
        for (int w = 1; w < 8; w++) t = fmaxf(t, sred[w]);
        sbc[0] = t;
    }
    __syncthreads();
    m = sbc[0];

    float s = 0.f;
#pragma unroll
    for (int j = 0; j < 8; j++) { v[j] = __expf(v[j] - m); s += v[j]; }
#pragma unroll
    for (int o = 16; o > 0; o >>= 1) s += __shfl_xor_sync(0xffffffffu, s, o);
    __syncthreads();
    if ((tid & 31) == 0) sred[tid >> 5] = s;
    __syncthreads();
    if (tid == 0) {
        float t = sred[0];
#pragma unroll
        for (int w = 1; w < 8; w++) t += sred[w];
        sbc[1] = t;
    }
    __syncthreads();
    const float inv = P_SCALE / sbc[1];

    uint4 o;
    o.x = pack_h2(__float2half_rn(v[0] * inv), __float2half_rn(v[1] * inv));
    o.y = pack_h2(__float2half_rn(v[2] * inv), __float2half_rn(v[3] * inv));
    o.z = pack_h2(__float2half_rn(v[4] * inv), __float2half_rn(v[5] * inv));
    o.w = pack_h2(__float2half_rn(v[6] * inv), __float2half_rn(v[7] * inv));
    *reinterpret_cast<uint4*>(Ph + base + tid * 8) = o;
}

// ---------------------------------------------------------------------------
// Host side
// ---------------------------------------------------------------------------
extern "C" void kernel_launch(void* const* d_in, const int* in_sizes, int n_in,
                              void* d_out, int out_size)
{
    const float* x  = (const float*)d_in[0];
    const float* Wq = (const float*)d_in[1];
    const float* bq = (const float*)d_in[2];
    const float* Wk = (const float*)d_in[3];
    const float* bk = (const float*)d_in[4];
    const float* Wv = (const float*)d_in[5];
    const float* bv = (const float*)d_in[6];
    const float* Wo = (const float*)d_in[7];
    const float* bo = (const float*)d_in[8];
    float* out = (float*)d_out;

    void *xh, *xl, *Wqh, *Wkh, *Wvh, *Woh;
    void *Qh, *Ql, *Kh, *Vh, *Pf, *Ph, *Ch;
    cudaGetSymbolAddress(&xh, g_xh);   cudaGetSymbolAddress(&xl, g_xl);
    cudaGetSymbolAddress(&Wqh, g_Wqh);
    cudaGetSymbolAddress(&Wkh, g_Wkh);
    cudaGetSymbolAddress(&Wvh, g_Wvh);
    cudaGetSymbolAddress(&Woh, g_Woh);
    cudaGetSymbolAddress(&Qh, g_Qh);   cudaGetSymbolAddress(&Ql, g_Ql);
    cudaGetSymbolAddress(&Kh, g_Kh);
    cudaGetSymbolAddress(&Vh, g_Vh);
    cudaGetSymbolAddress(&Pf, g_P);
    cudaGetSymbolAddress(&Ph, g_Ph);
    cudaGetSymbolAddress(&Ch, g_Ch);

    const int SM3 = 3 * 3 * TILEB;       // 92160 (QKV proj, scores: 3 stages x 3 tiles)
    const int SM2 = 4 * 2 * TILEB;       // 81920 (out proj: 4 stages x 2 tiles)
    const int SMP = PV_NST * PV_STAGE;   // 92160 (PV: 5 stages)
    cudaFuncSetAttribute(gemm_mma<1,true>,  cudaFuncAttributeMaxDynamicSharedMemorySize, SM3);
    cudaFuncSetAttribute(gemm_mma<0,true>,  cudaFuncAttributeMaxDynamicSharedMemorySize, SM3);
    cudaFuncSetAttribute(gemm_mma<0,false>, cudaFuncAttributeMaxDynamicSharedMemorySize, SM2);
    cudaFuncSetAttribute(gemm_pv,           cudaFuncAttributeMaxDynamicSharedMemorySize, SMP);

    const float scl = 1.0f / sqrtf((float)EMB);
    const dim3 blk(256);
    const BSeg nil = {nullptr, nullptr, nullptr, nullptr, 1.0f};

    // 1) split inputs (weights: hi only)
    {
        const int n4 = MROWS * EMB / 4;
        split2d<<<(n4 + 255) / 256, 256>>>((const float4*)x, (__half*)xh, (__half*)xl, n4);
        dim3 wg(24, 24), wb(32, 8);
        wsplit<<<wg, wb>>>(Wq, (__half*)Wqh);
        wsplit<<<wg, wb>>>(Wk, (__half*)Wkh);
        wsplit<<<wg, wb>>>(Wv, (__half*)Wvh);
        wsplit<<<wg, wb>>>(Wo, (__half*)Woh);
    }

    // 2) merged QKV projections: one launch, 2-term, segmented B/out
    {
        BSeg sq = {(const __half*)Wqh, bq, (__half*)Qh, (__half*)Ql, scl};
        BSeg sk = {(const __half*)Wkh, bk, (__half*)Kh, nullptr,     1.0f};
        BSeg sv = {(const __half*)Wvh, bv, (__half*)Vh, nullptr,     1.0f};
        gemm_mma<1,true><<<dim3(18, 128, 1), blk, SM3>>>(
            (const __half*)xh, (const __half*)xl,
            EMB, EMB, EMB, 0, 0,
            nullptr, EMB, 0, sq, sk, sv, 6);
    }

    // 3) scores = Q' @ K^T (scale folded into Q), fp32 out, 2-term
    {
        BSeg sc = {(const __half*)Kh, nullptr, nullptr, nullptr, 1.0f};
        gemm_mma<0,true><<<dim3(16, 16, 8), blk, SM3>>>(
            (const __half*)Qh, (const __half*)Ql,
            EMB, EMB, EMB, (long)SEQ * EMB, (long)SEQ * EMB,
            (float*)Pf, SEQ, (long)SEQ * SEQ, sc, nil, nil, 0);
    }

    // 4) softmax -> P hi (x P_SCALE)
    softmax_h<<<MROWS, 256>>>((const float*)Pf, (__half*)Ph);

    // 5) ctx = P @ V, 1-term, B = V row-major via trans-ldmatrix, K=2048
    gemm_pv<<<dim3(6, 16, 8), blk, SMP>>>(
        (const __half*)Ph, (const __half*)Vh,
        SEQ, SEQ, EMB, (long)SEQ * SEQ, (long)SEQ * EMB,
        (__half*)Ch, 1.0f / P_SCALE, EMB, (long)SEQ * EMB);

    // 6) out = C @ Wo^T + bo, fp32, 1-term
    {
        BSeg so = {(const __half*)Woh, bo, nullptr, nullptr, 1.0f};
        gemm_mma<0,false><<<dim3(6, 128, 1), blk, SM2>>>(
            (const __half*)Ch, nullptr,
            EMB, EMB, EMB, 0, 0,
            out, EMB, 0, so, nil, nil, 0);
    }
}

// round 10
// speedup vs baseline: 5.3254x; 1.1486x over previous
#include <cuda_runtime.h>
#include <cuda_fp16.h>
#include <math.h>
#include <stdint.h>

#define BSZ 8
#define SEQ 2048
#define EMB 768
#define MROWS (BSZ*SEQ)
#define P_SCALE 1024.0f

// ---------------------------------------------------------------------------
// Scratch (device globals; allocation forbidden in kernel_launch)
// ---------------------------------------------------------------------------
__device__ __align__(256) __half g_xh[MROWS*EMB], g_xl[MROWS*EMB];
__device__ __align__(256) __half g_Wqh[EMB*EMB];
__device__ __align__(256) __half g_Wkh[EMB*EMB];
__device__ __align__(256) __half g_Wvh[EMB*EMB];
__device__ __align__(256) __half g_Woh[EMB*EMB];
__device__ __align__(256) __half g_Qh[MROWS*EMB];
__device__ __align__(256) __half g_Kh[MROWS*EMB];
__device__ __align__(256) __half g_Vh[MROWS*EMB];                  // V hi, row-major [b,s,e]
__device__ __align__(256) float  g_P[(size_t)BSZ*SEQ*SEQ];         // fp32 scores
__device__ __align__(256) __half g_Ph[(size_t)BSZ*SEQ*SEQ];        // softmax hi (x P_SCALE)
__device__ __align__(256) __half g_Ch[MROWS*EMB];

// ---------------------------------------------------------------------------
// helpers
// ---------------------------------------------------------------------------
__device__ __forceinline__ uint32_t smem_u32(const void* p) {
    uint32_t a;
    asm("{ .reg .u64 t; cvta.to.shared.u64 t, %1; cvt.u32.u64 %0, t; }" : "=r"(a) : "l"(p));
    return a;
}
__device__ __forceinline__ void cpasync16(uint32_t s, const void* g) {
    asm volatile("cp.async.cg.shared.global [%0], [%1], 16;" :: "r"(s), "l"(g));
}
__device__ __forceinline__ void cp_commit() { asm volatile("cp.async.commit_group;"); }

__device__ __forceinline__ void ldm_x4(uint32_t (&r)[4], uint32_t a) {
    asm volatile("ldmatrix.sync.aligned.m8n8.x4.shared.b16 {%0,%1,%2,%3}, [%4];"
        : "=r"(r[0]), "=r"(r[1]), "=r"(r[2]), "=r"(r[3]) : "r"(a));
}
__device__ __forceinline__ void ldm_x4_t(uint32_t (&r)[4], uint32_t a) {
    asm volatile("ldmatrix.sync.aligned.m8n8.x4.trans.shared.b16 {%0,%1,%2,%3}, [%4];"
        : "=r"(r[0]), "=r"(r[1]), "=r"(r[2]), "=r"(r[3]) : "r"(a));
}
__device__ __forceinline__ void mma16816(float (&d)[4], const uint32_t (&a)[4],
                                         uint32_t b0, uint32_t b1) {
    asm volatile("mma.sync.aligned.m16n8k16.row.col.f32.f16.f16.f32 "
        "{%0,%1,%2,%3}, {%4,%5,%6,%7}, {%8,%9}, {%0,%1,%2,%3};"
        : "+f"(d[0]), "+f"(d[1]), "+f"(d[2]), "+f"(d[3])
        : "r"(a[0]), "r"(a[1]), "r"(a[2]), "r"(a[3]), "r"(b0), "r"(b1));
}
__device__ __forceinline__ void split_h(float v, __half& h, __half& l) {
    h = __float2half_rn(v);
    l = __float2half_rn(v - __half2float(h));
}
__device__ __forceinline__ uint32_t pack_h2(__half a, __half b) {
    __half2 t(a, b);
    return *reinterpret_cast<uint32_t*>(&t);
}

#define ROWB   80                       // K-major tile row: 64B data + 16B pad
#define TILEB  (128*ROWB)               // 10240 B

// Per-segment output descriptor (passed by value; selected per CTA by blockIdx.x)
struct BSeg {
    const __half* Bh;
    const float*  bias;
    __half*       outHi;
    float         scale;
};

// ---------------------------------------------------------------------------
// Split-fp16 warp-MMA GEMM: D[m,n] = sum_k A[m,k]*B[n,k] (both K-major)
// Terms: Ah*Bh + [ALO] Al*Bh.  fp32 accum.
// CTA 128x128, Kc=32, 8 warps (32x64), single-sync multistage cp.async:
//   NT=3 -> 3 stages, NT=2 -> 4 stages.
// OUTMODE 0: fp32 out (+bias, via outF).
// OUTMODE 1: fp16 hi out ((acc+bias)*scale).
// Segmented B: CTAs pick {s0,s1,s2} by blockIdx.x / segW (merged QKV launch).
// ---------------------------------------------------------------------------
template <int OUTMODE, bool ALO>
__global__ void __launch_bounds__(256, 2)
gemm_mma(const __half* __restrict__ Ah, const __half* __restrict__ Al,
         int K, long ldA, long ldB, long sAb, long sBb,
         float* __restrict__ outF, long ldOut, long obs,
         BSeg s0, BSeg s1, BSeg s2, int segW)
{
    constexpr int NT     = 2 + (ALO ? 1 : 0);
    constexpr int NSTAGE = (NT == 3) ? 3 : 4;
    constexpr int STAGEB = NT * TILEB;
    constexpr int OFF_B  = (1 + (ALO ? 1 : 0)) * TILEB;   // B hi tile offset

    extern __shared__ char smem[];
    const uint32_t sb = smem_u32(smem);

    const int tid    = threadIdx.x;
    const int lane   = tid & 31;
    const int wid    = tid >> 5;
    const int warp_m = wid & 3;
    const int warp_n = wid >> 2;

    int bxi = blockIdx.x;
    BSeg seg = s0;
    if (segW > 0) {
        if (bxi >= 2 * segW)      { seg = s2; bxi -= 2 * segW; }
        else if (bxi >= segW)     { seg = s1; bxi -= segW; }
    }
    const int by = blockIdx.y * 128;
    const int bx = bxi * 128;
    const int bz = blockIdx.z;

    Ah += (long)bz * sAb;
    if (ALO) Al += (long)bz * sAb;
    const __half* Bh = seg.Bh + (long)bz * sBb;

    const int lr0 = tid >> 2, lg0 = tid & 3;
    const int lr1 = (tid + 256) >> 2, lg1 = (tid + 256) & 3;

    auto load_chunk = [&](int kc, int stage) {
        const long kk = (long)kc * 32;
        const uint32_t s0a = sb + stage * STAGEB;
        const __half* srcs[3];
        int nsrc = 0;
        srcs[nsrc++] = Ah;
        if (ALO) srcs[nsrc++] = Al;
        srcs[nsrc++] = Bh;
#pragma unroll
        for (int m = 0; m < NT; ++m) {
            const bool isA = (m < 1 + (ALO ? 1 : 0));
            const long ld  = isA ? ldA : ldB;
            const int  r0  = isA ? by : bx;
            const uint32_t sm = s0a + m * TILEB;
            cpasync16(sm + lr0 * ROWB + lg0 * 16,
                      srcs[m] + (long)(r0 + lr0) * ld + kk + lg0 * 8);
            cpasync16(sm + lr1 * ROWB + lg1 * 16,
                      srcs[m] + (long)(r0 + lr1) * ld + kk + lg1 * 8);
        }
    };

    float acc[2][8][4];
#pragma unroll
    for (int i = 0; i < 2; ++i)
#pragma unroll
        for (int j = 0; j < 8; ++j)
#pragma unroll
            for (int e = 0; e < 4; ++e) acc[i][j][e] = 0.f;

    const int nChunks = K >> 5;

#pragma unroll
    for (int i = 0; i < NSTAGE - 1; ++i) {
        load_chunk(i, i);
        cp_commit();
    }

    const int rl = lane & 7;
    const int gq = lane >> 3;
    const uint32_t aoff = (uint32_t)((warp_m * 32 + (gq & 1) * 8 + rl) * ROWB + (gq >> 1) * 16);
    const uint32_t boff = (uint32_t)((warp_n * 64 + (gq >> 1) * 8 + rl) * ROWB + (gq & 1) * 16);

    // single-sync loop: wait(kc ready) -> sync (all warps done kc-1)
    // -> issue loads into slot (kc-1)%NSTAGE -> compute kc.
    for (int kc = 0; kc < nChunks; ++kc) {
        asm volatile("cp.async.wait_group %0;" :: "n"(NSTAGE - 2));
        __syncthreads();
        const int pf = kc + NSTAGE - 1;
        if (pf < nChunks) load_chunk(pf, pf % NSTAGE);
        cp_commit();

        const uint32_t st = sb + (kc % NSTAGE) * STAGEB;
#pragma unroll
        for (int ks = 0; ks < 2; ++ks) {
            const uint32_t kb = ks * 32;
            uint32_t ah[2][4], al[2][4];
#pragma unroll
            for (int i = 0; i < 2; ++i) {
                ldm_x4(ah[i], st + aoff + i * (16 * ROWB) + kb);
                if (ALO) ldm_x4(al[i], st + TILEB + aoff + i * (16 * ROWB) + kb);
            }
            uint32_t bh[4][4];
#pragma unroll
            for (int g = 0; g < 4; ++g)
                ldm_x4(bh[g], st + OFF_B + boff + g * (16 * ROWB) + kb);
#pragma unroll
            for (int i = 0; i < 2; ++i)
#pragma unroll
                for (int j = 0; j < 8; ++j) {
                    const int g = j >> 1, o = (j & 1) * 2;
                    mma16816(acc[i][j], ah[i], bh[g][o], bh[g][o + 1]);
                    if (ALO) mma16816(acc[i][j], al[i], bh[g][o], bh[g][o + 1]);
                }
        }
    }

    // ---------------- epilogue ----------------
    const int r_in = lane >> 2;
    const int c_in = (lane & 3) * 2;

#pragma unroll
    for (int i = 0; i < 2; ++i) {
#pragma unroll
        for (int j = 0; j < 8; ++j) {
            const int row0 = by + warp_m * 32 + i * 16 + r_in;
            const int row1 = row0 + 8;
            const int col  = bx + warp_n * 64 + j * 8 + c_in;
            const float b0 = seg.bias ? seg.bias[col]     : 0.f;
            const float b1 = seg.bias ? seg.bias[col + 1] : 0.f;

            if (OUTMODE == 0) {
                float2 v0 = make_float2(acc[i][j][0] + b0, acc[i][j][1] + b1);
                float2 v1 = make_float2(acc[i][j][2] + b0, acc[i][j][3] + b1);
                *reinterpret_cast<float2*>(outF + (long)bz * obs + (long)row0 * ldOut + col) = v0;
                *reinterpret_cast<float2*>(outF + (long)bz * obs + (long)row1 * ldOut + col) = v1;
            } else {
                float v00 = (acc[i][j][0] + b0) * seg.scale, v01 = (acc[i][j][1] + b1) * seg.scale;
                float v10 = (acc[i][j][2] + b0) * seg.scale, v11 = (acc[i][j][3] + b1) * seg.scale;
                const long o0 = (long)bz * obs + (long)row0 * ldOut + col;
                const long o1 = (long)bz * obs + (long)row1 * ldOut + col;
                *reinterpret_cast<uint32_t*>(seg.outHi + o0) =
                    pack_h2(__float2half_rn(v00), __float2half_rn(v01));
                *reinterpret_cast<uint32_t*>(seg.outHi + o1) =
                    pack_h2(__float2half_rn(v10), __float2half_rn(v11));
            }
        }
    }
}

// ---------------------------------------------------------------------------
// PV GEMM: C[m,e] = sum_s P[m,s] * V[s,e]. A = Ph K-major; B = V row-major
// [s,e] loaded via trans-ldmatrix from swizzled [k=32 x 256B] smem tiles.
// 1-term (P hi only). Single-sync 5-stage pipeline. Hi-only out, *scale.
// ---------------------------------------------------------------------------
#define PV_BTILE 8192                        // 32 rows x 256B, swizzled
#define PV_STAGE (TILEB + PV_BTILE)          // 18432
#define PV_NST   5

__global__ void __launch_bounds__(256, 2)
gemm_pv(const __half* __restrict__ Ah, const __half* __restrict__ Bv,
        int K, long ldA, long ldB, long sAb, long sBb,
        __half* __restrict__ outHi, float scale, long ldOut, long obs)
{
    extern __shared__ char smem[];
    const uint32_t sb = smem_u32(smem);

    const int tid    = threadIdx.x;
    const int lane   = tid & 31;
    const int wid    = tid >> 5;
    const int warp_m = wid & 3;
    const int warp_n = wid >> 2;
    const int by     = blockIdx.y * 128;
    const int bx     = blockIdx.x * 128;
    const int bz     = blockIdx.z;

    Ah += (long)bz * sAb;
    Bv += (long)bz * sBb;

    const int lr0 = tid >> 2, lg0 = tid & 3;
    const int lr1 = (tid + 256) >> 2, lg1 = (tid + 256) & 3;
    const int bk0 = tid >> 4,  bg0 = tid & 15;
    const int bk1 = (tid + 256) >> 4, bg1 = (tid + 256) & 15;

    auto load_chunk = [&](int kc, int stage) {
        const long kk = (long)kc * 32;
        const uint32_t s0 = sb + stage * PV_STAGE;
        cpasync16(s0 + lr0 * ROWB + lg0 * 16, Ah + (long)(by + lr0) * ldA + kk + lg0 * 8);
        cpasync16(s0 + lr1 * ROWB + lg1 * 16, Ah + (long)(by + lr1) * ldA + kk + lg1 * 8);
        const uint32_t b0 = s0 + TILEB;
        cpasync16(b0 + bk0 * 256 + ((bg0 ^ (bk0 & 7)) * 16),
                  Bv + (long)(kk + bk0) * ldB + bx + bg0 * 8);
        cpasync16(b0 + bk1 * 256 + ((bg1 ^ (bk1 & 7)) * 16),
                  Bv + (long)(kk + bk1) * ldB + bx + bg1 * 8);
    };

    float acc[2][8][4];
#pragma unroll
    for (int i = 0; i < 2; ++i)
#pragma unroll
        for (int j = 0; j < 8; ++j)
#pragma unroll
            for (int e = 0; e < 4; ++e) acc[i][j][e] = 0.f;

    const int nChunks = K >> 5;

#pragma unroll
    for (int i = 0; i < PV_NST - 1; ++i) {
        load_chunk(i, i);
        cp_commit();
    }

    const int rl = lane & 7;
    const int gq = lane >> 3;
    const uint32_t aoff = (uint32_t)((warp_m * 32 + (gq & 1) * 8 + rl) * ROWB + (gq >> 1) * 16);
    const int brow_in = (gq & 1) * 8 + rl;            // k within 16-block
    const int bcol16  = warp_n * 8 + (gq >> 1);       // + g*2 at use site

    for (int kc = 0; kc < nChunks; ++kc) {
        asm volatile("cp.async.wait_group %0;" :: "n"(PV_NST - 2));
        __syncthreads();
        const int pf = kc + PV_NST - 1;
        if (pf < nChunks) load_chunk(pf, pf % PV_NST);
        cp_commit();

        const uint32_t st = sb + (kc % PV_NST) * PV_STAGE;
        const uint32_t bt0 = st + TILEB;
#pragma unroll
        for (int ks = 0; ks < 2; ++ks) {
            uint32_t ah[2][4];
#pragma unroll
            for (int i = 0; i < 2; ++i)
                ldm_x4(ah[i], st + aoff + i * (16 * ROWB) + ks * 32);
            uint32_t bt[4][4];
            const int row = ks * 16 + brow_in;
#pragma unroll
            for (int g = 0; g < 4; ++g) {
                const int c = (bcol16 + g * 2) ^ (row & 7);
                ldm_x4_t(bt[g], bt0 + row * 256 + c * 16);
            }
#pragma unroll
            for (int i = 0; i < 2; ++i)
#pragma unroll
                for (int j = 0; j < 8; ++j) {
                    const int g = j >> 1, o = (j & 1) * 2;
                    mma16816(acc[i][j], ah[i], bt[g][o], bt[g][o + 1]);
                }
        }
    }

    // epilogue: hi only, *scale
    const int r_in = lane >> 2;
    const int c_in = (lane & 3) * 2;
#pragma unroll
    for (int i = 0; i < 2; ++i) {
#pragma unroll
        for (int j = 0; j < 8; ++j) {
            const int row0 = by + warp_m * 32 + i * 16 + r_in;
            const int row1 = row0 + 8;
            const int col  = bx + warp_n * 64 + j * 8 + c_in;
            float v00 = acc[i][j][0] * scale, v01 = acc[i][j][1] * scale;
            float v10 = acc[i][j][2] * scale, v11 = acc[i][j][3] * scale;
            const long o0 = (long)bz * obs + (long)row0 * ldOut + col;
            const long o1 = (long)bz * obs + (long)row1 * ldOut + col;
            *reinterpret_cast<uint32_t*>(outHi + o0) =
                pack_h2(__float2half_rn(v00), __float2half_rn(v01));
            *reinterpret_cast<uint32_t*>(outHi + o1) =
                pack_h2(__float2half_rn(v10), __float2half_rn(v11));
        }
    }
}

// ---------------------------------------------------------------------------
// Elementwise split: fp32 -> (hi, lo) fp16
// ---------------------------------------------------------------------------
__global__ void split2d(const float4* __restrict__ in,
                        __half* __restrict__ oh, __half* __restrict__ ol, int n4)
{
    const int i = blockIdx.x * blockDim.x + threadIdx.x;
    if (i >= n4) return;
    const float4 v = in[i];
    __half h0, l0, h1, l1, h2, l2, h3, l3;
    split_h(v.x, h0, l0); split_h(v.y, h1, l1);
    split_h(v.z, h2, l2); split_h(v.w, h3, l3);
    uint2 H, L;
    H.x = pack_h2(h0, h1); H.y = pack_h2(h2, h3);
    L.x = pack_h2(l0, l1); L.y = pack_h2(l2, l3);
    *reinterpret_cast<uint2*>(oh + 4 * (long)i) = H;
    *reinterpret_cast<uint2*>(ol + 4 * (long)i) = L;
}

// ---------------------------------------------------------------------------
// Weight transpose (hi only): W[K,N] fp32 -> Wt hi [N,K] fp16
// ---------------------------------------------------------------------------
__global__ void wsplit(const float* __restrict__ W, __half* __restrict__ oh)
{
    __shared__ float t[32][33];
    const int n0 = blockIdx.x * 32, k0 = blockIdx.y * 32;
    const int tx = threadIdx.x, ty = threadIdx.y;
#pragma unroll
    for (int i = 0; i < 32; i += 8)
        t[ty + i][tx] = W[(long)(k0 + ty + i) * EMB + n0 + tx];
    __syncthreads();
#pragma unroll
    for (int i = 0; i < 32; i += 8) {
        const long o = (long)(n0 + ty + i) * EMB + k0 + tx;
        oh[o] = __float2half_rn(t[tx][ty + i]);
    }
}

// ---------------------------------------------------------------------------
// Row softmax over fp32 P, emitting fp16 hi scaled by P_SCALE.
// Vectorized: per-thread 8 contiguous floats (2x float4 in, 1x uint4 out).
// ---------------------------------------------------------------------------
__global__ void __launch_bounds__(256)
softmax_h(const float* __restrict__ P, __half* __restrict__ Ph)
{
    __shared__ float sred[8];
    __shared__ float sbc[2];
    const int tid = threadIdx.x;
    const long base = (long)blockIdx.x * SEQ;

    float v[8];
    {
        const float4 a = *reinterpret_cast<const float4*>(P + base + tid * 8);
        const float4 b = *reinterpret_cast<const float4*>(P + base + tid * 8 + 4);
        v[0] = a.x; v[1] = a.y; v[2] = a.z; v[3] = a.w;
        v[4] = b.x; v[5] = b.y; v[6] = b.z; v[7] = b.w;
    }

    float m = v[0];
#pragma unroll
    for (int j = 1; j < 8; j++) m = fmaxf(m, v[j]);
#pragma unroll
    for (int o = 16; o > 0; o >>= 1) m = fmaxf(m, __shfl_xor_sync(0xffffffffu, m, o));
    if ((tid & 31) == 0) sred[tid >> 5] = m;
    __syncthreads();
    if (tid == 0) {
        float t = sred[0];
#pragma unroll
        for (int w = 1; w < 8; w++) t = fmaxf(t, sred[w]);
        sbc[0] = t;
    }
    __syncthreads();
    m = sbc[0];

    float s = 0.f;
#pragma unroll
    for (int j = 0; j < 8; j++) { v[j] = __expf(v[j] - m); s += v[j]; }
#pragma unroll
    for (int o = 16; o > 0; o >>= 1) s += __shfl_xor_sync(0xffffffffu, s, o);
    __syncthreads();
    if ((tid & 31) == 0) sred[tid >> 5] = s;
    __syncthreads();
    if (tid == 0) {
        float t = sred[0];
#pragma unroll
        for (int w = 1; w < 8; w++) t += sred[w];
        sbc[1] = t;
    }
    __syncthreads();
    const float inv = P_SCALE / sbc[1];

    uint4 o;
    o.x = pack_h2(__float2half_rn(v[0] * inv), __float2half_rn(v[1] * inv));
    o.y = pack_h2(__float2half_rn(v[2] * inv), __float2half_rn(v[3] * inv));
    o.z = pack_h2(__float2half_rn(v[4] * inv), __float2half_rn(v[5] * inv));
    o.w = pack_h2(__float2half_rn(v[6] * inv), __float2half_rn(v[7] * inv));
    *reinterpret_cast<uint4*>(Ph + base + tid * 8) = o;
}

// ---------------------------------------------------------------------------
// Host side
// ---------------------------------------------------------------------------
extern "C" void kernel_launch(void* const* d_in, const int* in_sizes, int n_in,
                              void* d_out, int out_size)
{
    const float* x  = (const float*)d_in[0];
    const float* Wq = (const float*)d_in[1];
    const float* bq = (const float*)d_in[2];
    const float* Wk = (const float*)d_in[3];
    const float* bk = (const float*)d_in[4];
    const float* Wv = (const float*)d_in[5];
    const float* bv = (const float*)d_in[6];
    const float* Wo = (const float*)d_in[7];
    const float* bo = (const float*)d_in[8];
    float* out = (float*)d_out;

    void *xh, *xl, *Wqh, *Wkh, *Wvh, *Woh;
    void *Qh, *Kh, *Vh, *Pf, *Ph, *Ch;
    cudaGetSymbolAddress(&xh, g_xh);   cudaGetSymbolAddress(&xl, g_xl);
    cudaGetSymbolAddress(&Wqh, g_Wqh);
    cudaGetSymbolAddress(&Wkh, g_Wkh);
    cudaGetSymbolAddress(&Wvh, g_Wvh);
    cudaGetSymbolAddress(&Woh, g_Woh);
    cudaGetSymbolAddress(&Qh, g_Qh);
    cudaGetSymbolAddress(&Kh, g_Kh);
    cudaGetSymbolAddress(&Vh, g_Vh);
    cudaGetSymbolAddress(&Pf, g_P);
    cudaGetSymbolAddress(&Ph, g_Ph);
    cudaGetSymbolAddress(&Ch, g_Ch);

    const int SM3 = 3 * 3 * TILEB;       // 92160 (QKV proj: 3 stages x 3 tiles)
    const int SM2 = 4 * 2 * TILEB;       // 81920 (scores, out proj: 4 stages x 2 tiles)
    const int SMP = PV_NST * PV_STAGE;   // 92160 (PV: 5 stages)
    cudaFuncSetAttribute(gemm_mma<1,true>,  cudaFuncAttributeMaxDynamicSharedMemorySize, SM3);
    cudaFuncSetAttribute(gemm_mma<0,false>, cudaFuncAttributeMaxDynamicSharedMemorySize, SM2);
    cudaFuncSetAttribute(gemm_pv,           cudaFuncAttributeMaxDynamicSharedMemorySize, SMP);

    const float scl = 1.0f / sqrtf((float)EMB);
    const dim3 blk(256);
    const BSeg nil = {nullptr, nullptr, nullptr, 1.0f};

    // 1) split inputs (x: hi+lo; weights: hi only)
    {
        const int n4 = MROWS * EMB / 4;
        split2d<<<(n4 + 255) / 256, 256>>>((const float4*)x, (__half*)xh, (__half*)xl, n4);
        dim3 wg(24, 24), wb(32, 8);
        wsplit<<<wg, wb>>>(Wq, (__half*)Wqh);
        wsplit<<<wg, wb>>>(Wk, (__half*)Wkh);
        wsplit<<<wg, wb>>>(Wv, (__half*)Wvh);
        wsplit<<<wg, wb>>>(Wo, (__half*)Woh);
    }

    // 2) merged QKV projections: one launch, 2-term, segmented B/out, hi out
    {
        BSeg sq = {(const __half*)Wqh, bq, (__half*)Qh, scl};
        BSeg sk = {(const __half*)Wkh, bk, (__half*)Kh, 1.0f};
        BSeg sv = {(const __half*)Wvh, bv, (__half*)Vh, 1.0f};
        gemm_mma<1,true><<<dim3(18, 128, 1), blk, SM3>>>(
            (const __half*)xh, (const __half*)xl,
            EMB, EMB, EMB, 0, 0,
            nullptr, EMB, 0, sq, sk, sv, 6);
    }

    // 3) scores = Q' @ K^T (scale folded into Q), fp32 out, 1-term
    {
        BSeg sc = {(const __half*)Kh, nullptr, nullptr, 1.0f};
        gemm_mma<0,false><<<dim3(16, 16, 8), blk, SM2>>>(
            (const __half*)Qh, nullptr,
            EMB, EMB, EMB, (long)SEQ * EMB, (long)SEQ * EMB,
            (float*)Pf, SEQ, (long)SEQ * SEQ, sc, nil, nil, 0);
    }

    // 4) softmax -> P hi (x P_SCALE)
    softmax_h<<<MROWS, 256>>>((const float*)Pf, (__half*)Ph);

    // 5) ctx = P @ V, 1-term, B = V row-major via trans-ldmatrix, K=2048
    gemm_pv<<<dim3(6, 16, 8), blk, SMP>>>(
        (const __half*)Ph, (const __half*)Vh,
        SEQ, SEQ, EMB, (long)SEQ * SEQ, (long)SEQ * EMB,
        (__half*)Ch, 1.0f / P_SCALE, EMB, (long)SEQ * EMB);

    // 6) out = C @ Wo^T + bo, fp32, 1-term
    {
        BSeg so = {(const __half*)Woh, bo, nullptr, 1.0f};
        gemm_mma<0,false><<<dim3(6, 128, 1), blk, SM2>>>(
            (const __half*)Ch, nullptr,
            EMB, EMB, EMB, 0, 0,
            out, EMB, 0, so, nil, nil, 0);
    }
}

// round 11
// speedup vs baseline: 6.3255x; 1.1878x over previous
#include <cuda_runtime.h>
#include <cuda_fp16.h>
#include <math.h>
#include <stdint.h>

#define BSZ 8
#define SEQ 2048
#define EMB 768
#define MROWS (BSZ*SEQ)
#define P_SCALE 1024.0f

// ---------------------------------------------------------------------------
// Scratch (device globals; allocation forbidden in kernel_launch)
// ---------------------------------------------------------------------------
__device__ __align__(256) __half g_xh[MROWS*EMB];
__device__ __align__(256) __half g_Wqh[EMB*EMB];
__device__ __align__(256) __half g_Wkh[EMB*EMB];
__device__ __align__(256) __half g_Wvh[EMB*EMB];
__device__ __align__(256) __half g_Woh[EMB*EMB];
__device__ __align__(256) __half g_Qh[MROWS*EMB];
__device__ __align__(256) __half g_Kh[MROWS*EMB];
__device__ __align__(256) __half g_Vh[MROWS*EMB];                  // V hi, row-major [b,s,e]
__device__ __align__(256) float  g_P[(size_t)BSZ*SEQ*SEQ];         // fp32 scores
__device__ __align__(256) __half g_Ph[(size_t)BSZ*SEQ*SEQ];        // softmax hi (x P_SCALE)
__device__ __align__(256) __half g_Ch[MROWS*EMB];

// ---------------------------------------------------------------------------
// helpers
// ---------------------------------------------------------------------------
__device__ __forceinline__ uint32_t smem_u32(const void* p) {
    uint32_t a;
    asm("{ .reg .u64 t; cvta.to.shared.u64 t, %1; cvt.u32.u64 %0, t; }" : "=r"(a) : "l"(p));
    return a;
}
__device__ __forceinline__ void cpasync16(uint32_t s, const void* g) {
    asm volatile("cp.async.cg.shared.global [%0], [%1], 16;" :: "r"(s), "l"(g));
}
__device__ __forceinline__ void cp_commit() { asm volatile("cp.async.commit_group;"); }

__device__ __forceinline__ void ldm_x4(uint32_t (&r)[4], uint32_t a) {
    asm volatile("ldmatrix.sync.aligned.m8n8.x4.shared.b16 {%0,%1,%2,%3}, [%4];"
        : "=r"(r[0]), "=r"(r[1]), "=r"(r[2]), "=r"(r[3]) : "r"(a));
}
__device__ __forceinline__ void ldm_x4_t(uint32_t (&r)[4], uint32_t a) {
    asm volatile("ldmatrix.sync.aligned.m8n8.x4.trans.shared.b16 {%0,%1,%2,%3}, [%4];"
        : "=r"(r[0]), "=r"(r[1]), "=r"(r[2]), "=r"(r[3]) : "r"(a));
}
__device__ __forceinline__ void mma16816(float (&d)[4], const uint32_t (&a)[4],
                                         uint32_t b0, uint32_t b1) {
    asm volatile("mma.sync.aligned.m16n8k16.row.col.f32.f16.f16.f32 "
        "{%0,%1,%2,%3}, {%4,%5,%6,%7}, {%8,%9}, {%0,%1,%2,%3};"
        : "+f"(d[0]), "+f"(d[1]), "+f"(d[2]), "+f"(d[3])
        : "r"(a[0]), "r"(a[1]), "r"(a[2]), "r"(a[3]), "r"(b0), "r"(b1));
}
__device__ __forceinline__ uint32_t pack_h2(__half a, __half b) {
    __half2 t(a, b);
    return *reinterpret_cast<uint32_t*>(&t);
}

#define ROWB   80                       // K-major tile row: 64B data + 16B pad
#define TILEB  (128*ROWB)               // 10240 B

// Per-segment output descriptor (passed by value; selected per CTA by blockIdx.x)
struct BSeg {
    const __half* Bh;
    const float*  bias;
    __half*       outHi;
    float         scale;
};

// ---------------------------------------------------------------------------
// fp16 warp-MMA GEMM: D[m,n] = sum_k A[m,k]*B[n,k] (both K-major), fp32 accum.
// CTA 128x128, Kc=32, 8 warps (32x64), single-sync 4-stage cp.async.
// OUTMODE 0: fp32 out (+bias, via outF).
// OUTMODE 1: fp16 hi out ((acc+bias)*scale).
// Segmented B: CTAs pick {s0,s1,s2} by blockIdx.x / segW (merged QKV launch).
// ---------------------------------------------------------------------------
#define NSTAGE 4
#define STAGEB (2*TILEB)

template <int OUTMODE>
__global__ void __launch_bounds__(256, 2)
gemm_mma(const __half* __restrict__ Ah,
         int K, long ldA, long ldB, long sAb, long sBb,
         float* __restrict__ outF, long ldOut, long obs,
         BSeg s0, BSeg s1, BSeg s2, int segW)
{
    extern __shared__ char smem[];
    const uint32_t sb = smem_u32(smem);

    const int tid    = threadIdx.x;
    const int lane   = tid & 31;
    const int wid    = tid >> 5;
    const int warp_m = wid & 3;
    const int warp_n = wid >> 2;

    int bxi = blockIdx.x;
    BSeg seg = s0;
    if (segW > 0) {
        if (bxi >= 2 * segW)      { seg = s2; bxi -= 2 * segW; }
        else if (bxi >= segW)     { seg = s1; bxi -= segW; }
    }
    const int by = blockIdx.y * 128;
    const int bx = bxi * 128;
    const int bz = blockIdx.z;

    Ah += (long)bz * sAb;
    const __half* Bh = seg.Bh + (long)bz * sBb;

    const int lr0 = tid >> 2, lg0 = tid & 3;
    const int lr1 = (tid + 256) >> 2, lg1 = (tid + 256) & 3;

    auto load_chunk = [&](int kc, int stage) {
        const long kk = (long)kc * 32;
        const uint32_t s0a = sb + stage * STAGEB;
        // A tile
        cpasync16(s0a + lr0 * ROWB + lg0 * 16,
                  Ah + (long)(by + lr0) * ldA + kk + lg0 * 8);
        cpasync16(s0a + lr1 * ROWB + lg1 * 16,
                  Ah + (long)(by + lr1) * ldA + kk + lg1 * 8);
        // B tile
        cpasync16(s0a + TILEB + lr0 * ROWB + lg0 * 16,
                  Bh + (long)(bx + lr0) * ldB + kk + lg0 * 8);
        cpasync16(s0a + TILEB + lr1 * ROWB + lg1 * 16,
                  Bh + (long)(bx + lr1) * ldB + kk + lg1 * 8);
    };

    float acc[2][8][4];
#pragma unroll
    for (int i = 0; i < 2; ++i)
#pragma unroll
        for (int j = 0; j < 8; ++j)
#pragma unroll
            for (int e = 0; e < 4; ++e) acc[i][j][e] = 0.f;

    const int nChunks = K >> 5;

#pragma unroll
    for (int i = 0; i < NSTAGE - 1; ++i) {
        load_chunk(i, i);
        cp_commit();
    }

    const int rl = lane & 7;
    const int gq = lane >> 3;
    const uint32_t aoff = (uint32_t)((warp_m * 32 + (gq & 1) * 8 + rl) * ROWB + (gq >> 1) * 16);
    const uint32_t boff = (uint32_t)((warp_n * 64 + (gq >> 1) * 8 + rl) * ROWB + (gq & 1) * 16);

    // single-sync loop: wait(kc ready) -> sync (all warps done kc-1)
    // -> issue loads into slot (kc-1)%NSTAGE -> compute kc.
    for (int kc = 0; kc < nChunks; ++kc) {
        asm volatile("cp.async.wait_group %0;" :: "n"(NSTAGE - 2));
        __syncthreads();
        const int pf = kc + NSTAGE - 1;
        if (pf < nChunks) load_chunk(pf, pf % NSTAGE);
        cp_commit();

        const uint32_t st = sb + (kc % NSTAGE) * STAGEB;
#pragma unroll
        for (int ks = 0; ks < 2; ++ks) {
            const uint32_t kb = ks * 32;
            uint32_t ah[2][4];
#pragma unroll
            for (int i = 0; i < 2; ++i)
                ldm_x4(ah[i], st + aoff + i * (16 * ROWB) + kb);
            uint32_t bh[4][4];
#pragma unroll
            for (int g = 0; g < 4; ++g)
                ldm_x4(bh[g], st + TILEB + boff + g * (16 * ROWB) + kb);
#pragma unroll
            for (int i = 0; i < 2; ++i)
#pragma unroll
                for (int j = 0; j < 8; ++j) {
                    const int g = j >> 1, o = (j & 1) * 2;
                    mma16816(acc[i][j], ah[i], bh[g][o], bh[g][o + 1]);
                }
        }
    }

    // ---------------- epilogue ----------------
    const int r_in = lane >> 2;
    const int c_in = (lane & 3) * 2;

#pragma unroll
    for (int i = 0; i < 2; ++i) {
#pragma unroll
        for (int j = 0; j < 8; ++j) {
            const int row0 = by + warp_m * 32 + i * 16 + r_in;
            const int row1 = row0 + 8;
            const int col  = bx + warp_n * 64 + j * 8 + c_in;
            const float b0 = seg.bias ? seg.bias[col]     : 0.f;
            const float b1 = seg.bias ? seg.bias[col + 1] : 0.f;

            if (OUTMODE == 0) {
                float2 v0 = make_float2(acc[i][j][0] + b0, acc[i][j][1] + b1);
                float2 v1 = make_float2(acc[i][j][2] + b0, acc[i][j][3] + b1);
                *reinterpret_cast<float2*>(outF + (long)bz * obs + (long)row0 * ldOut + col) = v0;
                *reinterpret_cast<float2*>(outF + (long)bz * obs + (long)row1 * ldOut + col) = v1;
            } else {
                float v00 = (acc[i][j][0] + b0) * seg.scale, v01 = (acc[i][j][1] + b1) * seg.scale;
                float v10 = (acc[i][j][2] + b0) * seg.scale, v11 = (acc[i][j][3] + b1) * seg.scale;
                const long o0 = (long)bz * obs + (long)row0 * ldOut + col;
                const long o1 = (long)bz * obs + (long)row1 * ldOut + col;
                *reinterpret_cast<uint32_t*>(seg.outHi + o0) =
                    pack_h2(__float2half_rn(v00), __float2half_rn(v01));
                *reinterpret_cast<uint32_t*>(seg.outHi + o1) =
                    pack_h2(__float2half_rn(v10), __float2half_rn(v11));
            }
        }
    }
}

// ---------------------------------------------------------------------------
// PV GEMM: C[m,e] = sum_s P[m,s] * V[s,e]. A = Ph K-major; B = V row-major
// [s,e] loaded via trans-ldmatrix from swizzled [k=32 x 256B] smem tiles.
// Single-sync 5-stage pipeline. Hi-only out, *scale.
// ---------------------------------------------------------------------------
#define PV_BTILE 8192                        // 32 rows x 256B, swizzled
#define PV_STAGE (TILEB + PV_BTILE)          // 18432
#define PV_NST   5

__global__ void __launch_bounds__(256, 2)
gemm_pv(const __half* __restrict__ Ah, const __half* __restrict__ Bv,
        int K, long ldA, long ldB, long sAb, long sBb,
        __half* __restrict__ outHi, float scale, long ldOut, long obs)
{
    extern __shared__ char smem[];
    const uint32_t sb = smem_u32(smem);

    const int tid    = threadIdx.x;
    const int lane   = tid & 31;
    const int wid    = tid >> 5;
    const int warp_m = wid & 3;
    const int warp_n = wid >> 2;
    const int by     = blockIdx.y * 128;
    const int bx     = blockIdx.x * 128;
    const int bz     = blockIdx.z;

    Ah += (long)bz * sAb;
    Bv += (long)bz * sBb;

    const int lr0 = tid >> 2, lg0 = tid & 3;
    const int lr1 = (tid + 256) >> 2, lg1 = (tid + 256) & 3;
    const int bk0 = tid >> 4,  bg0 = tid & 15;
    const int bk1 = (tid + 256) >> 4, bg1 = (tid + 256) & 15;

    auto load_chunk = [&](int kc, int stage) {
        const long kk = (long)kc * 32;
        const uint32_t s0 = sb + stage * PV_STAGE;
        cpasync16(s0 + lr0 * ROWB + lg0 * 16, Ah + (long)(by + lr0) * ldA + kk + lg0 * 8);
        cpasync16(s0 + lr1 * ROWB + lg1 * 16, Ah + (long)(by + lr1) * ldA + kk + lg1 * 8);
        const uint32_t b0 = s0 + TILEB;
        cpasync16(b0 + bk0 * 256 + ((bg0 ^ (bk0 & 7)) * 16),
                  Bv + (long)(kk + bk0) * ldB + bx + bg0 * 8);
        cpasync16(b0 + bk1 * 256 + ((bg1 ^ (bk1 & 7)) * 16),
                  Bv + (long)(kk + bk1) * ldB + bx + bg1 * 8);
    };

    float acc[2][8][4];
#pragma unroll
    for (int i = 0; i < 2; ++i)
#pragma unroll
        for (int j = 0; j < 8; ++j)
#pragma unroll
            for (int e = 0; e < 4; ++e) acc[i][j][e] = 0.f;

    const int nChunks = K >> 5;

#pragma unroll
    for (int i = 0; i < PV_NST - 1; ++i) {
        load_chunk(i, i);
        cp_commit();
    }

    const int rl = lane & 7;
    const int gq = lane >> 3;
    const uint32_t aoff = (uint32_t)((warp_m * 32 + (gq & 1) * 8 + rl) * ROWB + (gq >> 1) * 16);
    const int brow_in = (gq & 1) * 8 + rl;            // k within 16-block
    const int bcol16  = warp_n * 8 + (gq >> 1);       // + g*2 at use site

    for (int kc = 0; kc < nChunks; ++kc) {
        asm volatile("cp.async.wait_group %0;" :: "n"(PV_NST - 2));
        __syncthreads();
        const int pf = kc + PV_NST - 1;
        if (pf < nChunks) load_chunk(pf, pf % PV_NST);
        cp_commit();

        const uint32_t st = sb + (kc % PV_NST) * PV_STAGE;
        const uint32_t bt0 = st + TILEB;
#pragma unroll
        for (int ks = 0; ks < 2; ++ks) {
            uint32_t ah[2][4];
#pragma unroll
            for (int i = 0; i < 2; ++i)
                ldm_x4(ah[i], st + aoff + i * (16 * ROWB) + ks * 32);
            uint32_t bt[4][4];
            const int row = ks * 16 + brow_in;
#pragma unroll
            for (int g = 0; g < 4; ++g) {
                const int c = (bcol16 + g * 2) ^ (row & 7);
                ldm_x4_t(bt[g], bt0 + row * 256 + c * 16);
            }
#pragma unroll
            for (int i = 0; i < 2; ++i)
#pragma unroll
                for (int j = 0; j < 8; ++j) {
                    const int g = j >> 1, o = (j & 1) * 2;
                    mma16816(acc[i][j], ah[i], bt[g][o], bt[g][o + 1]);
                }
        }
    }

    // epilogue: hi only, *scale
    const int r_in = lane >> 2;
    const int c_in = (lane & 3) * 2;
#pragma unroll
    for (int i = 0; i < 2; ++i) {
#pragma unroll
        for (int j = 0; j < 8; ++j) {
            const int row0 = by + warp_m * 32 + i * 16 + r_in;
            const int row1 = row0 + 8;
            const int col  = bx + warp_n * 64 + j * 8 + c_in;
            float v00 = acc[i][j][0] * scale, v01 = acc[i][j][1] * scale;
            float v10 = acc[i][j][2] * scale, v11 = acc[i][j][3] * scale;
            const long o0 = (long)bz * obs + (long)row0 * ldOut + col;
            const long o1 = (long)bz * obs + (long)row1 * ldOut + col;
            *reinterpret_cast<uint32_t*>(outHi + o0) =
                pack_h2(__float2half_rn(v00), __float2half_rn(v01));
            *reinterpret_cast<uint32_t*>(outHi + o1) =
                pack_h2(__float2half_rn(v10), __float2half_rn(v11));
        }
    }
}

// ---------------------------------------------------------------------------
// Elementwise convert: fp32 -> fp16 (hi only), 8 elems/thread
// ---------------------------------------------------------------------------
__global__ void cvt_h(const float4* __restrict__ in, __half* __restrict__ oh, int n8)
{
    const int i = blockIdx.x * blockDim.x + threadIdx.x;
    if (i >= n8) return;
    const float4 a = in[2 * i];
    const float4 b = in[2 * i + 1];
    uint4 o;
    o.x = pack_h2(__float2half_rn(a.x), __float2half_rn(a.y));
    o.y = pack_h2(__float2half_rn(a.z), __float2half_rn(a.w));
    o.z = pack_h2(__float2half_rn(b.x), __float2half_rn(b.y));
    o.w = pack_h2(__float2half_rn(b.z), __float2half_rn(b.w));
    *reinterpret_cast<uint4*>(oh + 8 * (long)i) = o;
}

// ---------------------------------------------------------------------------
// Weight transpose (hi only): W[K,N] fp32 -> Wt hi [N,K] fp16
// ---------------------------------------------------------------------------
__global__ void wsplit(const float* __restrict__ W, __half* __restrict__ oh)
{
    __shared__ float t[32][33];
    const int n0 = blockIdx.x * 32, k0 = blockIdx.y * 32;
    const int tx = threadIdx.x, ty = threadIdx.y;
#pragma unroll
    for (int i = 0; i < 32; i += 8)
        t[ty + i][tx] = W[(long)(k0 + ty + i) * EMB + n0 + tx];
    __syncthreads();
#pragma unroll
    for (int i = 0; i < 32; i += 8) {
        const long o = (long)(n0 + ty + i) * EMB + k0 + tx;
        oh[o] = __float2half_rn(t[tx][ty + i]);
    }
}

// ---------------------------------------------------------------------------
// Row softmax over fp32 P, emitting fp16 hi scaled by P_SCALE.
// Vectorized: per-thread 8 contiguous floats (2x float4 in, 1x uint4 out).
// ---------------------------------------------------------------------------
__global__ void __launch_bounds__(256)
softmax_h(const float* __restrict__ P, __half* __restrict__ Ph)
{
    __shared__ float sred[8];
    __shared__ float sbc[2];
    const int tid = threadIdx.x;
    const long base = (long)blockIdx.x * SEQ;

    float v[8];
    {
        const float4 a = *reinterpret_cast<const float4*>(P + base + tid * 8);
        const float4 b = *reinterpret_cast<const float4*>(P + base + tid * 8 + 4);
        v[0] = a.x; v[1] = a.y; v[2] = a.z; v[3] = a.w;
        v[4] = b.x; v[5] = b.y; v[6] = b.z; v[7] = b.w;
    }

    float m = v[0];
#pragma unroll
    for (int j = 1; j < 8; j++) m = fmaxf(m, v[j]);
#pragma unroll
    for (int o = 16; o > 0; o >>= 1) m = fmaxf(m, __shfl_xor_sync(0xffffffffu, m, o));
    if ((tid & 31) == 0) sred[tid >> 5] = m;
    __syncthreads();
    if (tid == 0) {
        float t = sred[0];
#pragma unroll
        for (int w = 1; w < 8; w++) t = fmaxf(t, sred[w]);
        sbc[0] = t;
    }
    __syncthreads();
    m = sbc[0];

    float s = 0.f;
#pragma unroll
    for (int j = 0; j < 8; j++) { v[j] = __expf(v[j] - m); s += v[j]; }
#pragma unroll
    for (int o = 16; o > 0; o >>= 1) s += __shfl_xor_sync(0xffffffffu, s, o);
    __syncthreads();
    if ((tid & 31) == 0) sred[tid >> 5] = s;
    __syncthreads();
    if (tid == 0) {
        float t = sred[0];
#pragma unroll
        for (int w = 1; w < 8; w++) t += sred[w];
        sbc[1] = t;
    }
    __syncthreads();
    const float inv = P_SCALE / sbc[1];

    uint4 o;
    o.x = pack_h2(__float2half_rn(v[0] * inv), __float2half_rn(v[1] * inv));
    o.y = pack_h2(__float2half_rn(v[2] * inv), __float2half_rn(v[3] * inv));
    o.z = pack_h2(__float2half_rn(v[4] * inv), __float2half_rn(v[5] * inv));
    o.w = pack_h2(__float2half_rn(v[6] * inv), __float2half_rn(v[7] * inv));
    *reinterpret_cast<uint4*>(Ph + base + tid * 8) = o;
}

// ---------------------------------------------------------------------------
// Host side
// ---------------------------------------------------------------------------
extern "C" void kernel_launch(void* const* d_in, const int* in_sizes, int n_in,
                              void* d_out, int out_size)
{
    const float* x  = (const float*)d_in[0];
    const float* Wq = (const float*)d_in[1];
    const float* bq = (const float*)d_in[2];
    const float* Wk = (const float*)d_in[3];
    const float* bk = (const float*)d_in[4];
    const float* Wv = (const float*)d_in[5];
    const float* bv = (const float*)d_in[6];
    const float* Wo = (const float*)d_in[7];
    const float* bo = (const float*)d_in[8];
    float* out = (float*)d_out;

    void *xh, *Wqh, *Wkh, *Wvh, *Woh;
    void *Qh, *Kh, *Vh, *Pf, *Ph, *Ch;
    cudaGetSymbolAddress(&xh, g_xh);
    cudaGetSymbolAddress(&Wqh, g_Wqh);
    cudaGetSymbolAddress(&Wkh, g_Wkh);
    cudaGetSymbolAddress(&Wvh, g_Wvh);
    cudaGetSymbolAddress(&Woh, g_Woh);
    cudaGetSymbolAddress(&Qh, g_Qh);
    cudaGetSymbolAddress(&Kh, g_Kh);
    cudaGetSymbolAddress(&Vh, g_Vh);
    cudaGetSymbolAddress(&Pf, g_P);
    cudaGetSymbolAddress(&Ph, g_Ph);
    cudaGetSymbolAddress(&Ch, g_Ch);

    const int SM2 = NSTAGE * STAGEB;     // 81920 (all gemm_mma: 4 stages x 2 tiles)
    const int SMP = PV_NST * PV_STAGE;   // 92160 (PV: 5 stages)
    cudaFuncSetAttribute(gemm_mma<0>, cudaFuncAttributeMaxDynamicSharedMemorySize, SM2);
    cudaFuncSetAttribute(gemm_mma<1>, cudaFuncAttributeMaxDynamicSharedMemorySize, SM2);
    cudaFuncSetAttribute(gemm_pv,     cudaFuncAttributeMaxDynamicSharedMemorySize, SMP);

    const float scl = 1.0f / sqrtf((float)EMB);
    const dim3 blk(256);
    const BSeg nil = {nullptr, nullptr, nullptr, 1.0f};

    // 1) convert inputs to fp16 hi
    {
        const int n8 = MROWS * EMB / 8;
        cvt_h<<<(n8 + 255) / 256, 256>>>((const float4*)x, (__half*)xh, n8);
        dim3 wg(24, 24), wb(32, 8);
        wsplit<<<wg, wb>>>(Wq, (__half*)Wqh);
        wsplit<<<wg, wb>>>(Wk, (__half*)Wkh);
        wsplit<<<wg, wb>>>(Wv, (__half*)Wvh);
        wsplit<<<wg, wb>>>(Wo, (__half*)Woh);
    }

    // 2) merged QKV projections: one launch, 1-term, segmented B/out, hi out
    {
        BSeg sq = {(const __half*)Wqh, bq, (__half*)Qh, scl};
        BSeg sk = {(const __half*)Wkh, bk, (__half*)Kh, 1.0f};
        BSeg sv = {(const __half*)Wvh, bv, (__half*)Vh, 1.0f};
        gemm_mma<1><<<dim3(18, 128, 1), blk, SM2>>>(
            (const __half*)xh,
            EMB, EMB, EMB, 0, 0,
            nullptr, EMB, 0, sq, sk, sv, 6);
    }

    // 3) scores = Q' @ K^T (scale folded into Q), fp32 out
    {
        BSeg sc = {(const __half*)Kh, nullptr, nullptr, 1.0f};
        gemm_mma<0><<<dim3(16, 16, 8), blk, SM2>>>(
            (const __half*)Qh,
            EMB, EMB, EMB, (long)SEQ * EMB, (long)SEQ * EMB,
            (float*)Pf, SEQ, (long)SEQ * SEQ, sc, nil, nil, 0);
    }

    // 4) softmax -> P hi (x P_SCALE)
    softmax_h<<<MROWS, 256>>>((const float*)Pf, (__half*)Ph);

    // 5) ctx = P @ V, B = V row-major via trans-ldmatrix, K=2048
    gemm_pv<<<dim3(6, 16, 8), blk, SMP>>>(
        (const __half*)Ph, (const __half*)Vh,
        SEQ, SEQ, EMB, (long)SEQ * SEQ, (long)SEQ * EMB,
        (__half*)Ch, 1.0f / P_SCALE, EMB, (long)SEQ * EMB);

    // 6) out = C @ Wo^T + bo, fp32
    {
        BSeg so = {(const __half*)Woh, bo, nullptr, 1.0f};
        gemm_mma<0><<<dim3(6, 128, 1), blk, SM2>>>(
            (const __half*)Ch,
            EMB, EMB, EMB, 0, 0,
            out, EMB, 0, so, nil, nil, 0);
    }
}

// round 12
// speedup vs baseline: 6.4507x; 1.0198x over previous
#include <cuda_runtime.h>
#include <cuda_fp16.h>
#include <math.h>
#include <stdint.h>

#define BSZ 8
#define SEQ 2048
#define EMB 768
#define MROWS (BSZ*SEQ)
#define P_SCALE 1024.0f

// ---------------------------------------------------------------------------
// Scratch (device globals; allocation forbidden in kernel_launch)
// ---------------------------------------------------------------------------
__device__ __align__(256) __half g_xh[MROWS*EMB];
__device__ __align__(256) __half g_Wqh[EMB*EMB];
__device__ __align__(256) __half g_Wkh[EMB*EMB];
__device__ __align__(256) __half g_Wvh[EMB*EMB];
__device__ __align__(256) __half g_Woh[EMB*EMB];
__device__ __align__(256) __half g_Qh[MROWS*EMB];
__device__ __align__(256) __half g_Kh[MROWS*EMB];
__device__ __align__(256) __half g_Vh[MROWS*EMB];                  // V hi, row-major [b,s,e]
__device__ __align__(256) __half g_Ph[(size_t)BSZ*SEQ*SEQ];        // fp16 scores -> probs (in place)
__device__ __align__(256) __half g_Ch[MROWS*EMB];

// ---------------------------------------------------------------------------
// helpers
// ---------------------------------------------------------------------------
__device__ __forceinline__ uint32_t smem_u32(const void* p) {
    uint32_t a;
    asm("{ .reg .u64 t; cvta.to.shared.u64 t, %1; cvt.u32.u64 %0, t; }" : "=r"(a) : "l"(p));
    return a;
}
__device__ __forceinline__ void cpasync16(uint32_t s, const void* g) {
    asm volatile("cp.async.cg.shared.global [%0], [%1], 16;" :: "r"(s), "l"(g));
}
__device__ __forceinline__ void cp_commit() { asm volatile("cp.async.commit_group;"); }

__device__ __forceinline__ void ldm_x4(uint32_t (&r)[4], uint32_t a) {
    asm volatile("ldmatrix.sync.aligned.m8n8.x4.shared.b16 {%0,%1,%2,%3}, [%4];"
        : "=r"(r[0]), "=r"(r[1]), "=r"(r[2]), "=r"(r[3]) : "r"(a));
}
__device__ __forceinline__ void ldm_x4_t(uint32_t (&r)[4], uint32_t a) {
    asm volatile("ldmatrix.sync.aligned.m8n8.x4.trans.shared.b16 {%0,%1,%2,%3}, [%4];"
        : "=r"(r[0]), "=r"(r[1]), "=r"(r[2]), "=r"(r[3]) : "r"(a));
}
__device__ __forceinline__ void mma16816(float (&d)[4], const uint32_t (&a)[4],
                                         uint32_t b0, uint32_t b1) {
    asm volatile("mma.sync.aligned.m16n8k16.row.col.f32.f16.f16.f32 "
        "{%0,%1,%2,%3}, {%4,%5,%6,%7}, {%8,%9}, {%0,%1,%2,%3};"
        : "+f"(d[0]), "+f"(d[1]), "+f"(d[2]), "+f"(d[3])
        : "r"(a[0]), "r"(a[1]), "r"(a[2]), "r"(a[3]), "r"(b0), "r"(b1));
}
__device__ __forceinline__ uint32_t pack_h2(__half a, __half b) {
    __half2 t(a, b);
    return *reinterpret_cast<uint32_t*>(&t);
}

#define ROWB   80                       // K-major tile row: 64B data + 16B pad
#define TILEB  (128*ROWB)               // 10240 B

// Per-segment output descriptor (passed by value; selected per CTA by blockIdx.x)
struct BSeg {
    const __half* Bh;
    const float*  bias;
    __half*       outHi;
    float         scale;
};

// ---------------------------------------------------------------------------
// fp16 warp-MMA GEMM: D[m,n] = sum_k A[m,k]*B[n,k] (both K-major), fp32 accum.
// CTA 128x128, Kc=32, 8 warps (32x64), single-sync 4-stage cp.async.
// OUTMODE 0: fp32 out (+bias, via outF).
// OUTMODE 1: fp16 hi out ((acc+bias)*scale).
// Segmented B: CTAs pick {s0,s1,s2} by blockIdx.x / segW (merged QKV launch).
// ---------------------------------------------------------------------------
#define NSTAGE 4
#define STAGEB (2*TILEB)

template <int OUTMODE>
__global__ void __launch_bounds__(256, 2)
gemm_mma(const __half* __restrict__ Ah,
         int K, long ldA, long ldB, long sAb, long sBb,
         float* __restrict__ outF, long ldOut, long obs,
         BSeg s0, BSeg s1, BSeg s2, int segW)
{
    extern __shared__ char smem[];
    const uint32_t sb = smem_u32(smem);

    const int tid    = threadIdx.x;
    const int lane   = tid & 31;
    const int wid    = tid >> 5;
    const int warp_m = wid & 3;
    const int warp_n = wid >> 2;

    int bxi = blockIdx.x;
    BSeg seg = s0;
    if (segW > 0) {
        if (bxi >= 2 * segW)      { seg = s2; bxi -= 2 * segW; }
        else if (bxi >= segW)     { seg = s1; bxi -= segW; }
    }
    const int by = blockIdx.y * 128;
    const int bx = bxi * 128;
    const int bz = blockIdx.z;

    Ah += (long)bz * sAb;
    const __half* Bh = seg.Bh + (long)bz * sBb;

    const int lr0 = tid >> 2, lg0 = tid & 3;
    const int lr1 = (tid + 256) >> 2, lg1 = (tid + 256) & 3;

    auto load_chunk = [&](int kc, int stage) {
        const long kk = (long)kc * 32;
        const uint32_t s0a = sb + stage * STAGEB;
        cpasync16(s0a + lr0 * ROWB + lg0 * 16,
                  Ah + (long)(by + lr0) * ldA + kk + lg0 * 8);
        cpasync16(s0a + lr1 * ROWB + lg1 * 16,
                  Ah + (long)(by + lr1) * ldA + kk + lg1 * 8);
        cpasync16(s0a + TILEB + lr0 * ROWB + lg0 * 16,
                  Bh + (long)(bx + lr0) * ldB + kk + lg0 * 8);
        cpasync16(s0a + TILEB + lr1 * ROWB + lg1 * 16,
                  Bh + (long)(bx + lr1) * ldB + kk + lg1 * 8);
    };

    float acc[2][8][4];
#pragma unroll
    for (int i = 0; i < 2; ++i)
#pragma unroll
        for (int j = 0; j < 8; ++j)
#pragma unroll
            for (int e = 0; e < 4; ++e) acc[i][j][e] = 0.f;

    const int nChunks = K >> 5;

#pragma unroll
    for (int i = 0; i < NSTAGE - 1; ++i) {
        load_chunk(i, i);
        cp_commit();
    }

    const int rl = lane & 7;
    const int gq = lane >> 3;
    const uint32_t aoff = (uint32_t)((warp_m * 32 + (gq & 1) * 8 + rl) * ROWB + (gq >> 1) * 16);
    const uint32_t boff = (uint32_t)((warp_n * 64 + (gq >> 1) * 8 + rl) * ROWB + (gq & 1) * 16);

    // single-sync loop: wait(kc ready) -> sync -> load (kc-1) slot -> compute kc
    for (int kc = 0; kc < nChunks; ++kc) {
        asm volatile("cp.async.wait_group %0;" :: "n"(NSTAGE - 2));
        __syncthreads();
        const int pf = kc + NSTAGE - 1;
        if (pf < nChunks) load_chunk(pf, pf % NSTAGE);
        cp_commit();

        const uint32_t st = sb + (kc % NSTAGE) * STAGEB;
#pragma unroll
        for (int ks = 0; ks < 2; ++ks) {
            const uint32_t kb = ks * 32;
            uint32_t ah[2][4];
#pragma unroll
            for (int i = 0; i < 2; ++i)
                ldm_x4(ah[i], st + aoff + i * (16 * ROWB) + kb);
            uint32_t bh[4][4];
#pragma unroll
            for (int g = 0; g < 4; ++g)
                ldm_x4(bh[g], st + TILEB + boff + g * (16 * ROWB) + kb);
#pragma unroll
            for (int i = 0; i < 2; ++i)
#pragma unroll
                for (int j = 0; j < 8; ++j) {
                    const int g = j >> 1, o = (j & 1) * 2;
                    mma16816(acc[i][j], ah[i], bh[g][o], bh[g][o + 1]);
                }
        }
    }

    // ---------------- epilogue ----------------
    const int r_in = lane >> 2;
    const int c_in = (lane & 3) * 2;

#pragma unroll
    for (int i = 0; i < 2; ++i) {
#pragma unroll
        for (int j = 0; j < 8; ++j) {
            const int row0 = by + warp_m * 32 + i * 16 + r_in;
            const int row1 = row0 + 8;
            const int col  = bx + warp_n * 64 + j * 8 + c_in;
            const float b0 = seg.bias ? seg.bias[col]     : 0.f;
            const float b1 = seg.bias ? seg.bias[col + 1] : 0.f;

            if (OUTMODE == 0) {
                float2 v0 = make_float2(acc[i][j][0] + b0, acc[i][j][1] + b1);
                float2 v1 = make_float2(acc[i][j][2] + b0, acc[i][j][3] + b1);
                *reinterpret_cast<float2*>(outF + (long)bz * obs + (long)row0 * ldOut + col) = v0;
                *reinterpret_cast<float2*>(outF + (long)bz * obs + (long)row1 * ldOut + col) = v1;
            } else {
                float v00 = (acc[i][j][0] + b0) * seg.scale, v01 = (acc[i][j][1] + b1) * seg.scale;
                float v10 = (acc[i][j][2] + b0) * seg.scale, v11 = (acc[i][j][3] + b1) * seg.scale;
                const long o0 = (long)bz * obs + (long)row0 * ldOut + col;
                const long o1 = (long)bz * obs + (long)row1 * ldOut + col;
                *reinterpret_cast<uint32_t*>(seg.outHi + o0) =
                    pack_h2(__float2half_rn(v00), __float2half_rn(v01));
                *reinterpret_cast<uint32_t*>(seg.outHi + o1) =
                    pack_h2(__float2half_rn(v10), __float2half_rn(v11));
            }
        }
    }
}

// ---------------------------------------------------------------------------
// PV GEMM: C[m,e] = sum_s P[m,s] * V[s,e]. A = Ph K-major; B = V row-major
// [s,e] loaded via trans-ldmatrix from swizzled [k=32 x 256B] smem tiles.
// Single-sync 5-stage pipeline. Hi-only out, *scale.
// ---------------------------------------------------------------------------
#define PV_BTILE 8192                        // 32 rows x 256B, swizzled
#define PV_STAGE (TILEB + PV_BTILE)          // 18432
#define PV_NST   5

__global__ void __launch_bounds__(256, 2)
gemm_pv(const __half* __restrict__ Ah, const __half* __restrict__ Bv,
        int K, long ldA, long ldB, long sAb, long sBb,
        __half* __restrict__ outHi, float scale, long ldOut, long obs)
{
    extern __shared__ char smem[];
    const uint32_t sb = smem_u32(smem);

    const int tid    = threadIdx.x;
    const int lane   = tid & 31;
    const int wid    = tid >> 5;
    const int warp_m = wid & 3;
    const int warp_n = wid >> 2;
    const int by     = blockIdx.y * 128;
    const int bx     = blockIdx.x * 128;
    const int bz     = blockIdx.z;

    Ah += (long)bz * sAb;
    Bv += (long)bz * sBb;

    const int lr0 = tid >> 2, lg0 = tid & 3;
    const int lr1 = (tid + 256) >> 2, lg1 = (tid + 256) & 3;
    const int bk0 = tid >> 4,  bg0 = tid & 15;
    const int bk1 = (tid + 256) >> 4, bg1 = (tid + 256) & 15;

    auto load_chunk = [&](int kc, int stage) {
        const long kk = (long)kc * 32;
        const uint32_t s0 = sb + stage * PV_STAGE;
        cpasync16(s0 + lr0 * ROWB + lg0 * 16, Ah + (long)(by + lr0) * ldA + kk + lg0 * 8);
        cpasync16(s0 + lr1 * ROWB + lg1 * 16, Ah + (long)(by + lr1) * ldA + kk + lg1 * 8);
        const uint32_t b0 = s0 + TILEB;
        cpasync16(b0 + bk0 * 256 + ((bg0 ^ (bk0 & 7)) * 16),
                  Bv + (long)(kk + bk0) * ldB + bx + bg0 * 8);
        cpasync16(b0 + bk1 * 256 + ((bg1 ^ (bk1 & 7)) * 16),
                  Bv + (long)(kk + bk1) * ldB + bx + bg1 * 8);
    };

    float acc[2][8][4];
#pragma unroll
    for (int i = 0; i < 2; ++i)
#pragma unroll
        for (int j = 0; j < 8; ++j)
#pragma unroll
            for (int e = 0; e < 4; ++e) acc[i][j][e] = 0.f;

    const int nChunks = K >> 5;

#pragma unroll
    for (int i = 0; i < PV_NST - 1; ++i) {
        load_chunk(i, i);
        cp_commit();
    }

    const int rl = lane & 7;
    const int gq = lane >> 3;
    const uint32_t aoff = (uint32_t)((warp_m * 32 + (gq & 1) * 8 + rl) * ROWB + (gq >> 1) * 16);
    const int brow_in = (gq & 1) * 8 + rl;            // k within 16-block
    const int bcol16  = warp_n * 8 + (gq >> 1);       // + g*2 at use site

    for (int kc = 0; kc < nChunks; ++kc) {
        asm volatile("cp.async.wait_group %0;" :: "n"(PV_NST - 2));
        __syncthreads();
        const int pf = kc + PV_NST - 1;
        if (pf < nChunks) load_chunk(pf, pf % PV_NST);
        cp_commit();

        const uint32_t st = sb + (kc % PV_NST) * PV_STAGE;
        const uint32_t bt0 = st + TILEB;
#pragma unroll
        for (int ks = 0; ks < 2; ++ks) {
            uint32_t ah[2][4];
#pragma unroll
            for (int i = 0; i < 2; ++i)
                ldm_x4(ah[i], st + aoff + i * (16 * ROWB) + ks * 32);
            uint32_t bt[4][4];
            const int row = ks * 16 + brow_in;
#pragma unroll
            for (int g = 0; g < 4; ++g) {
                const int c = (bcol16 + g * 2) ^ (row & 7);
                ldm_x4_t(bt[g], bt0 + row * 256 + c * 16);
            }
#pragma unroll
            for (int i = 0; i < 2; ++i)
#pragma unroll
                for (int j = 0; j < 8; ++j) {
                    const int g = j >> 1, o = (j & 1) * 2;
                    mma16816(acc[i][j], ah[i], bt[g][o], bt[g][o + 1]);
                }
        }
    }

    // epilogue: hi only, *scale
    const int r_in = lane >> 2;
    const int c_in = (lane & 3) * 2;
#pragma unroll
    for (int i = 0; i < 2; ++i) {
#pragma unroll
        for (int j = 0; j < 8; ++j) {
            const int row0 = by + warp_m * 32 + i * 16 + r_in;
            const int row1 = row0 + 8;
            const int col  = bx + warp_n * 64 + j * 8 + c_in;
            float v00 = acc[i][j][0] * scale, v01 = acc[i][j][1] * scale;
            float v10 = acc[i][j][2] * scale, v11 = acc[i][j][3] * scale;
            const long o0 = (long)bz * obs + (long)row0 * ldOut + col;
            const long o1 = (long)bz * obs + (long)row1 * ldOut + col;
            *reinterpret_cast<uint32_t*>(outHi + o0) =
                pack_h2(__float2half_rn(v00), __float2half_rn(v01));
            *reinterpret_cast<uint32_t*>(outHi + o1) =
                pack_h2(__float2half_rn(v10), __float2half_rn(v11));
        }
    }
}

// ---------------------------------------------------------------------------
// Elementwise convert: fp32 -> fp16 (hi only), 8 elems/thread
// ---------------------------------------------------------------------------
__global__ void cvt_h(const float4* __restrict__ in, __half* __restrict__ oh, int n8)
{
    const int i = blockIdx.x * blockDim.x + threadIdx.x;
    if (i >= n8) return;
    const float4 a = in[2 * i];
    const float4 b = in[2 * i + 1];
    uint4 o;
    o.x = pack_h2(__float2half_rn(a.x), __float2half_rn(a.y));
    o.y = pack_h2(__float2half_rn(a.z), __float2half_rn(a.w));
    o.z = pack_h2(__float2half_rn(b.x), __float2half_rn(b.y));
    o.w = pack_h2(__float2half_rn(b.z), __float2half_rn(b.w));
    *reinterpret_cast<uint4*>(oh + 8 * (long)i) = o;
}

// ---------------------------------------------------------------------------
// Weight transpose (hi only), 4 weights in one launch (blockIdx.z selects):
// W[K,N] fp32 -> Wt hi [N,K] fp16
// ---------------------------------------------------------------------------
struct WPair { const float* W; __half* oh; };

__global__ void wsplit4(WPair w0, WPair w1, WPair w2, WPair w3)
{
    __shared__ float t[32][33];
    const WPair wp = (blockIdx.z == 0) ? w0 : (blockIdx.z == 1) ? w1
                   : (blockIdx.z == 2) ? w2 : w3;
    const int n0 = blockIdx.x * 32, k0 = blockIdx.y * 32;
    const int tx = threadIdx.x, ty = threadIdx.y;
#pragma unroll
    for (int i = 0; i < 32; i += 8)
        t[ty + i][tx] = wp.W[(long)(k0 + ty + i) * EMB + n0 + tx];
    __syncthreads();
#pragma unroll
    for (int i = 0; i < 32; i += 8) {
        const long o = (long)(n0 + ty + i) * EMB + k0 + tx;
        wp.oh[o] = __float2half_rn(t[tx][ty + i]);
    }
}

// ---------------------------------------------------------------------------
// Row softmax over fp16 raw scores, in place, emitting fp16 probs x P_SCALE.
// Per-thread 8 contiguous halfs (1x uint4 in, 1x uint4 out).
// ---------------------------------------------------------------------------
__global__ void __launch_bounds__(256)
softmax_h(__half* __restrict__ Ph)
{
    __shared__ float sred[8];
    __shared__ float sbc[2];
    const int tid = threadIdx.x;
    const long base = (long)blockIdx.x * SEQ;

    float v[8];
    {
        const uint4 a = *reinterpret_cast<const uint4*>(Ph + base + tid * 8);
        const __half2* h = reinterpret_cast<const __half2*>(&a);
#pragma unroll
        for (int j = 0; j < 4; ++j) {
            float2 f = __half22float2(h[j]);
            v[2 * j]     = f.x;
            v[2 * j + 1] = f.y;
        }
    }

    float m = v[0];
#pragma unroll
    for (int j = 1; j < 8; j++) m = fmaxf(m, v[j]);
#pragma unroll
    for (int o = 16; o > 0; o >>= 1) m = fmaxf(m, __shfl_xor_sync(0xffffffffu, m, o));
    if ((tid & 31) == 0) sred[tid >> 5] = m;
    __syncthreads();
    if (tid == 0) {
        float t = sred[0];
#pragma unroll
        for (int w = 1; w < 8; w++) t = fmaxf(t, sred[w]);
        sbc[0] = t;
    }
    __syncthreads();
    m = sbc[0];

    float s = 0.f;
#pragma unroll
    for (int j = 0; j < 8; j++) { v[j] = __expf(v[j] - m); s += v[j]; }
#pragma unroll
    for (int o = 16; o > 0; o >>= 1) s += __shfl_xor_sync(0xffffffffu, s, o);
    __syncthreads();
    if ((tid & 31) == 0) sred[tid >> 5] = s;
    __syncthreads();
    if (tid == 0) {
        float t = sred[0];
#pragma unroll
        for (int w = 1; w < 8; w++) t += sred[w];
        sbc[1] = t;
    }
    __syncthreads();
    const float inv = P_SCALE / sbc[1];

    uint4 o;
    o.x = pack_h2(__float2half_rn(v[0] * inv), __float2half_rn(v[1] * inv));
    o.y = pack_h2(__float2half_rn(v[2] * inv), __float2half_rn(v[3] * inv));
    o.z = pack_h2(__float2half_rn(v[4] * inv), __float2half_rn(v[5] * inv));
    o.w = pack_h2(__float2half_rn(v[6] * inv), __float2half_rn(v[7] * inv));
    *reinterpret_cast<uint4*>(Ph + base + tid * 8) = o;
}

// ---------------------------------------------------------------------------
// Host side
// ---------------------------------------------------------------------------
extern "C" void kernel_launch(void* const* d_in, const int* in_sizes, int n_in,
                              void* d_out, int out_size)
{
    const float* x  = (const float*)d_in[0];
    const float* Wq = (const float*)d_in[1];
    const float* bq = (const float*)d_in[2];
    const float* Wk = (const float*)d_in[3];
    const float* bk = (const float*)d_in[4];
    const float* Wv = (const float*)d_in[5];
    const float* bv = (const float*)d_in[6];
    const float* Wo = (const float*)d_in[7];
    const float* bo = (const float*)d_in[8];
    float* out = (float*)d_out;

    void *xh, *Wqh, *Wkh, *Wvh, *Woh;
    void *Qh, *Kh, *Vh, *Ph, *Ch;
    cudaGetSymbolAddress(&xh, g_xh);
    cudaGetSymbolAddress(&Wqh, g_Wqh);
    cudaGetSymbolAddress(&Wkh, g_Wkh);
    cudaGetSymbolAddress(&Wvh, g_Wvh);
    cudaGetSymbolAddress(&Woh, g_Woh);
    cudaGetSymbolAddress(&Qh, g_Qh);
    cudaGetSymbolAddress(&Kh, g_Kh);
    cudaGetSymbolAddress(&Vh, g_Vh);
    cudaGetSymbolAddress(&Ph, g_Ph);
    cudaGetSymbolAddress(&Ch, g_Ch);

    const int SM2 = NSTAGE * STAGEB;     // 81920 (all gemm_mma: 4 stages x 2 tiles)
    const int SMP = PV_NST * PV_STAGE;   // 92160 (PV: 5 stages)
    cudaFuncSetAttribute(gemm_mma<0>, cudaFuncAttributeMaxDynamicSharedMemorySize, SM2);
    cudaFuncSetAttribute(gemm_mma<1>, cudaFuncAttributeMaxDynamicSharedMemorySize, SM2);
    cudaFuncSetAttribute(gemm_pv,     cudaFuncAttributeMaxDynamicSharedMemorySize, SMP);

    const float scl = 1.0f / sqrtf((float)EMB);
    const dim3 blk(256);
    const BSeg nil = {nullptr, nullptr, nullptr, 1.0f};

    // 1) convert inputs to fp16 hi (x + all 4 weights, 2 launches)
    {
        const int n8 = MROWS * EMB / 8;
        cvt_h<<<(n8 + 255) / 256, 256>>>((const float4*)x, (__half*)xh, n8);
        WPair w0 = {Wq, (__half*)Wqh};
        WPair w1 = {Wk, (__half*)Wkh};
        WPair w2 = {Wv, (__half*)Wvh};
        WPair w3 = {Wo, (__half*)Woh};
        wsplit4<<<dim3(24, 24, 4), dim3(32, 8)>>>(w0, w1, w2, w3);
    }

    // 2) merged QKV projections: one launch, segmented B/out, hi out
    {
        BSeg sq = {(const __half*)Wqh, bq, (__half*)Qh, scl};
        BSeg sk = {(const __half*)Wkh, bk, (__half*)Kh, 1.0f};
        BSeg sv = {(const __half*)Wvh, bv, (__half*)Vh, 1.0f};
        gemm_mma<1><<<dim3(18, 128, 1), blk, SM2>>>(
            (const __half*)xh,
            EMB, EMB, EMB, 0, 0,
            nullptr, EMB, 0, sq, sk, sv, 6);
    }

    // 3) scores = Q' @ K^T (scale folded into Q), fp16 raw scores out
    {
        BSeg sc = {(const __half*)Kh, nullptr, (__half*)Ph, 1.0f};
        gemm_mma<1><<<dim3(16, 16, 8), blk, SM2>>>(
            (const __half*)Qh,
            EMB, EMB, EMB, (long)SEQ * EMB, (long)SEQ * EMB,
            nullptr, SEQ, (long)SEQ * SEQ, sc, nil, nil, 0);
    }

    // 4) softmax in place: fp16 scores -> fp16 probs (x P_SCALE)
    softmax_h<<<MROWS, 256>>>((__half*)Ph);

    // 5) ctx = P @ V, B = V row-major via trans-ldmatrix, K=2048
    gemm_pv<<<dim3(6, 16, 8), blk, SMP>>>(
        (const __half*)Ph, (const __half*)Vh,
        SEQ, SEQ, EMB, (long)SEQ * SEQ, (long)SEQ * EMB,
        (__half*)Ch, 1.0f / P_SCALE, EMB, (long)SEQ * EMB);

    // 6) out = C @ Wo^T + bo, fp32
    {
        BSeg so = {(const __half*)Woh, bo, nullptr, 1.0f};
        gemm_mma<0><<<dim3(6, 128, 1), blk, SM2>>>(
            (const __half*)Ch,
            EMB, EMB, EMB, 0, 0,
            out, EMB, 0, so, nil, nil, 0);
    }
}

// round 13
// speedup vs baseline: 7.1405x; 1.1069x over previous
#include <cuda_runtime.h>
#include <cuda_fp16.h>
#include <math.h>
#include <stdint.h>

#define BSZ 8
#define SEQ 2048
#define EMB 768
#define MROWS (BSZ*SEQ)
#define P_SCALE 1024.0f

// ---------------------------------------------------------------------------
// Scratch (device globals; allocation forbidden in kernel_launch)
// ---------------------------------------------------------------------------
__device__ __align__(256) __half g_xh[MROWS*EMB];
__device__ __align__(256) __half g_Wqh[EMB*EMB];
__device__ __align__(256) __half g_Wkh[EMB*EMB];
__device__ __align__(256) __half g_Wvh[EMB*EMB];
__device__ __align__(256) __half g_Woh[EMB*EMB];
__device__ __align__(256) __half g_Qh[MROWS*EMB];
__device__ __align__(256) __half g_Kh[MROWS*EMB];
__device__ __align__(256) __half g_Vh[MROWS*EMB];                  // V hi, row-major [b,s,e]
__device__ __align__(256) __half g_Ph[(size_t)BSZ*SEQ*SEQ];        // fp16 scores -> probs (in place)
__device__ __align__(256) __half g_Ch[MROWS*EMB];

// ---------------------------------------------------------------------------
// helpers
// ---------------------------------------------------------------------------
__device__ __forceinline__ uint32_t smem_u32(const void* p) {
    uint32_t a;
    asm("{ .reg .u64 t; cvta.to.shared.u64 t, %1; cvt.u32.u64 %0, t; }" : "=r"(a) : "l"(p));
    return a;
}
__device__ __forceinline__ void cpasync16(uint32_t s, const void* g) {
    asm volatile("cp.async.cg.shared.global [%0], [%1], 16;" :: "r"(s), "l"(g));
}
__device__ __forceinline__ void cp_commit() { asm volatile("cp.async.commit_group;"); }

__device__ __forceinline__ void ldm_x4(uint32_t (&r)[4], uint32_t a) {
    asm volatile("ldmatrix.sync.aligned.m8n8.x4.shared.b16 {%0,%1,%2,%3}, [%4];"
        : "=r"(r[0]), "=r"(r[1]), "=r"(r[2]), "=r"(r[3]) : "r"(a));
}
__device__ __forceinline__ void ldm_x4_t(uint32_t (&r)[4], uint32_t a) {
    asm volatile("ldmatrix.sync.aligned.m8n8.x4.trans.shared.b16 {%0,%1,%2,%3}, [%4];"
        : "=r"(r[0]), "=r"(r[1]), "=r"(r[2]), "=r"(r[3]) : "r"(a));
}
__device__ __forceinline__ void mma16816(float (&d)[4], const uint32_t (&a)[4],
                                         uint32_t b0, uint32_t b1) {
    asm volatile("mma.sync.aligned.m16n8k16.row.col.f32.f16.f16.f32 "
        "{%0,%1,%2,%3}, {%4,%5,%6,%7}, {%8,%9}, {%0,%1,%2,%3};"
        : "+f"(d[0]), "+f"(d[1]), "+f"(d[2]), "+f"(d[3])
        : "r"(a[0]), "r"(a[1]), "r"(a[2]), "r"(a[3]), "r"(b0), "r"(b1));
}
__device__ __forceinline__ uint32_t pack_h2(__half a, __half b) {
    __half2 t(a, b);
    return *reinterpret_cast<uint32_t*>(&t);
}

// K-chunk = 64 halfs: row = 128B data + 16B pad (16*i mod 128 permutation
// keeps ldmatrix conflict-free, same as the old 80B row with 64-k chunks)
#define ROWB   144
#define TILEB  (128*ROWB)               // 18432 B

// Per-segment output descriptor (passed by value; selected per CTA by blockIdx.x)
struct BSeg {
    const __half* Bh;
    const float*  bias;
    __half*       outHi;
    float         scale;
};

// ---------------------------------------------------------------------------
// fp16 warp-MMA GEMM: D[m,n] = sum_k A[m,k]*B[n,k] (both K-major), fp32 accum.
// CTA 128x128, Kc=64, 8 warps (32x64), single-sync 3-stage cp.async.
// OUTMODE 0: fp32 out (+bias). OUTMODE 1: fp16 hi out ((acc+bias)*scale).
// Segmented B: CTAs pick {s0,s1,s2} by blockIdx.x / segW (merged QKV launch).
// ---------------------------------------------------------------------------
#define NSTAGE 3
#define STAGEB (2*TILEB)                // 36864

template <int OUTMODE>
__global__ void __launch_bounds__(256, 2)
gemm_mma(const __half* __restrict__ Ah,
         int K, long ldA, long ldB, long sAb, long sBb,
         float* __restrict__ outF, long ldOut, long obs,
         BSeg s0, BSeg s1, BSeg s2, int segW)
{
    extern __shared__ char smem[];
    const uint32_t sb = smem_u32(smem);

    const int tid    = threadIdx.x;
    const int lane   = tid & 31;
    const int wid    = tid >> 5;
    const int warp_m = wid & 3;
    const int warp_n = wid >> 2;

    int bxi = blockIdx.x;
    BSeg seg = s0;
    if (segW > 0) {
        if (bxi >= 2 * segW)      { seg = s2; bxi -= 2 * segW; }
        else if (bxi >= segW)     { seg = s1; bxi -= segW; }
    }
    const int by = blockIdx.y * 128;
    const int bx = bxi * 128;
    const int bz = blockIdx.z;

    Ah += (long)bz * sAb;
    const __half* Bh = seg.Bh + (long)bz * sBb;

    // loader: 1024 16B-chunks per tile, 4 per thread per tile
    auto load_chunk = [&](int kc, int stage) {
        const long kk = (long)kc * 64;
        const uint32_t s0a = sb + stage * STAGEB;
#pragma unroll
        for (int i = 0; i < 4; ++i) {
            const int c   = tid + i * 256;
            const int row = c >> 3;
            const int g   = c & 7;
            cpasync16(s0a + row * ROWB + g * 16,
                      Ah + (long)(by + row) * ldA + kk + g * 8);
            cpasync16(s0a + TILEB + row * ROWB + g * 16,
                      Bh + (long)(bx + row) * ldB + kk + g * 8);
        }
    };

    float acc[2][8][4];
#pragma unroll
    for (int i = 0; i < 2; ++i)
#pragma unroll
        for (int j = 0; j < 8; ++j)
#pragma unroll
            for (int e = 0; e < 4; ++e) acc[i][j][e] = 0.f;

    const int nChunks = K >> 6;

#pragma unroll
    for (int i = 0; i < NSTAGE - 1; ++i) {
        load_chunk(i, i);
        cp_commit();
    }

    const int rl = lane & 7;
    const int gq = lane >> 3;
    const uint32_t aoff = (uint32_t)((warp_m * 32 + (gq & 1) * 8 + rl) * ROWB + (gq >> 1) * 16);
    const uint32_t boff = (uint32_t)((warp_n * 64 + (gq >> 1) * 8 + rl) * ROWB + (gq & 1) * 16);

    // single-sync loop: wait(kc ready) -> sync -> load (kc-1) slot -> compute kc
    for (int kc = 0; kc < nChunks; ++kc) {
        asm volatile("cp.async.wait_group %0;" :: "n"(NSTAGE - 2));
        __syncthreads();
        const int pf = kc + NSTAGE - 1;
        if (pf < nChunks) load_chunk(pf, pf % NSTAGE);
        cp_commit();

        const uint32_t st = sb + (kc % NSTAGE) * STAGEB;
#pragma unroll
        for (int ks = 0; ks < 4; ++ks) {
            const uint32_t kb = ks * 32;
            uint32_t ah[2][4];
#pragma unroll
            for (int i = 0; i < 2; ++i)
                ldm_x4(ah[i], st + aoff + i * (16 * ROWB) + kb);
            uint32_t bh[4][4];
#pragma unroll
            for (int g = 0; g < 4; ++g)
                ldm_x4(bh[g], st + TILEB + boff + g * (16 * ROWB) + kb);
#pragma unroll
            for (int i = 0; i < 2; ++i)
#pragma unroll
                for (int j = 0; j < 8; ++j) {
                    const int g = j >> 1, o = (j & 1) * 2;
                    mma16816(acc[i][j], ah[i], bh[g][o], bh[g][o + 1]);
                }
        }
    }

    // ---------------- epilogue ----------------
    const int r_in = lane >> 2;
    const int c_in = (lane & 3) * 2;

#pragma unroll
    for (int i = 0; i < 2; ++i) {
#pragma unroll
        for (int j = 0; j < 8; ++j) {
            const int row0 = by + warp_m * 32 + i * 16 + r_in;
            const int row1 = row0 + 8;
            const int col  = bx + warp_n * 64 + j * 8 + c_in;
            const float b0 = seg.bias ? seg.bias[col]     : 0.f;
            const float b1 = seg.bias ? seg.bias[col + 1] : 0.f;

            if (OUTMODE == 0) {
                float2 v0 = make_float2(acc[i][j][0] + b0, acc[i][j][1] + b1);
                float2 v1 = make_float2(acc[i][j][2] + b0, acc[i][j][3] + b1);
                *reinterpret_cast<float2*>(outF + (long)bz * obs + (long)row0 * ldOut + col) = v0;
                *reinterpret_cast<float2*>(outF + (long)bz * obs + (long)row1 * ldOut + col) = v1;
            } else {
                float v00 = (acc[i][j][0] + b0) * seg.scale, v01 = (acc[i][j][1] + b1) * seg.scale;
                float v10 = (acc[i][j][2] + b0) * seg.scale, v11 = (acc[i][j][3] + b1) * seg.scale;
                const long o0 = (long)bz * obs + (long)row0 * ldOut + col;
                const long o1 = (long)bz * obs + (long)row1 * ldOut + col;
                *reinterpret_cast<uint32_t*>(seg.outHi + o0) =
                    pack_h2(__float2half_rn(v00), __float2half_rn(v01));
                *reinterpret_cast<uint32_t*>(seg.outHi + o1) =
                    pack_h2(__float2half_rn(v10), __float2half_rn(v11));
            }
        }
    }
}

// ---------------------------------------------------------------------------
// PV GEMM: C[m,e] = sum_s P[m,s] * V[s,e]. A = Ph K-major; B = V row-major
// [s,e] loaded via trans-ldmatrix from swizzled [k=64 x 256B] smem tiles.
// Single-sync 3-stage pipeline, Kc=64. Hi-only out, *scale.
// ---------------------------------------------------------------------------
#define PV_BTILE 16384                       // 64 rows x 256B, swizzled
#define PV_STAGE (TILEB + PV_BTILE)          // 34816
#define PV_NST   3

__global__ void __launch_bounds__(256, 2)
gemm_pv(const __half* __restrict__ Ah, const __half* __restrict__ Bv,
        int K, long ldA, long ldB, long sAb, long sBb,
        __half* __restrict__ outHi, float scale, long ldOut, long obs)
{
    extern __shared__ char smem[];
    const uint32_t sb = smem_u32(smem);

    const int tid    = threadIdx.x;
    const int lane   = tid & 31;
    const int wid    = tid >> 5;
    const int warp_m = wid & 3;
    const int warp_n = wid >> 2;
    const int by     = blockIdx.y * 128;
    const int bx     = blockIdx.x * 128;
    const int bz     = blockIdx.z;

    Ah += (long)bz * sAb;
    Bv += (long)bz * sBb;

    auto load_chunk = [&](int kc, int stage) {
        const long kk = (long)kc * 64;
        const uint32_t s0 = sb + stage * PV_STAGE;
        // A tile: 128 rows x 128B (+pad), 1024 chunks, 4/thread
#pragma unroll
        for (int i = 0; i < 4; ++i) {
            const int c   = tid + i * 256;
            const int row = c >> 3;
            const int g   = c & 7;
            cpasync16(s0 + row * ROWB + g * 16,
                      Ah + (long)(by + row) * ldA + kk + g * 8);
        }
        // B tile: 64 rows x 256B swizzled, 1024 chunks, 4/thread
        const uint32_t b0 = s0 + TILEB;
#pragma unroll
        for (int i = 0; i < 4; ++i) {
            const int c  = tid + i * 256;
            const int bk = c >> 4;
            const int bg = c & 15;
            cpasync16(b0 + bk * 256 + ((bg ^ (bk & 7)) * 16),
                      Bv + (long)(kk + bk) * ldB + bx + bg * 8);
        }
    };

    float acc[2][8][4];
#pragma unroll
    for (int i = 0; i < 2; ++i)
#pragma unroll
        for (int j = 0; j < 8; ++j)
#pragma unroll
            for (int e = 0; e < 4; ++e) acc[i][j][e] = 0.f;

    const int nChunks = K >> 6;

#pragma unroll
    for (int i = 0; i < PV_NST - 1; ++i) {
        load_chunk(i, i);
        cp_commit();
    }

    const int rl = lane & 7;
    const int gq = lane >> 3;
    const uint32_t aoff = (uint32_t)((warp_m * 32 + (gq & 1) * 8 + rl) * ROWB + (gq >> 1) * 16);
    const int brow_in = (gq & 1) * 8 + rl;            // k within 16-block
    const int bcol16  = warp_n * 8 + (gq >> 1);       // + g*2 at use site

    for (int kc = 0; kc < nChunks; ++kc) {
        asm volatile("cp.async.wait_group %0;" :: "n"(PV_NST - 2));
        __syncthreads();
        const int pf = kc + PV_NST - 1;
        if (pf < nChunks) load_chunk(pf, pf % PV_NST);
        cp_commit();

        const uint32_t st = sb + (kc % PV_NST) * PV_STAGE;
        const uint32_t bt0 = st + TILEB;
#pragma unroll
        for (int ks = 0; ks < 4; ++ks) {
            uint32_t ah[2][4];
#pragma unroll
            for (int i = 0; i < 2; ++i)
                ldm_x4(ah[i], st + aoff + i * (16 * ROWB) + ks * 32);
            uint32_t bt[4][4];
            const int row = ks * 16 + brow_in;
#pragma unroll
            for (int g = 0; g < 4; ++g) {
                const int c = (bcol16 + g * 2) ^ (row & 7);
                ldm_x4_t(bt[g], bt0 + row * 256 + c * 16);
            }
#pragma unroll
            for (int i = 0; i < 2; ++i)
#pragma unroll
                for (int j = 0; j < 8; ++j) {
                    const int g = j >> 1, o = (j & 1) * 2;
                    mma16816(acc[i][j], ah[i], bt[g][o], bt[g][o + 1]);
                }
        }
    }

    // epilogue: hi only, *scale
    const int r_in = lane >> 2;
    const int c_in = (lane & 3) * 2;
#pragma unroll
    for (int i = 0; i < 2; ++i) {
#pragma unroll
        for (int j = 0; j < 8; ++j) {
            const int row0 = by + warp_m * 32 + i * 16 + r_in;
            const int row1 = row0 + 8;
            const int col  = bx + warp_n * 64 + j * 8 + c_in;
            float v00 = acc[i][j][0] * scale, v01 = acc[i][j][1] * scale;
            float v10 = acc[i][j][2] * scale, v11 = acc[i][j][3] * scale;
            const long o0 = (long)bz * obs + (long)row0 * ldOut + col;
            const long o1 = (long)bz * obs + (long)row1 * ldOut + col;
            *reinterpret_cast<uint32_t*>(outHi + o0) =
                pack_h2(__float2half_rn(v00), __float2half_rn(v01));
            *reinterpret_cast<uint32_t*>(outHi + o1) =
                pack_h2(__float2half_rn(v10), __float2half_rn(v11));
        }
    }
}

// ---------------------------------------------------------------------------
// Elementwise convert: fp32 -> fp16 (hi only), 8 elems/thread
// ---------------------------------------------------------------------------
__global__ void cvt_h(const float4* __restrict__ in, __half* __restrict__ oh, int n8)
{
    const int i = blockIdx.x * blockDim.x + threadIdx.x;
    if (i >= n8) return;
    const float4 a = in[2 * i];
    const float4 b = in[2 * i + 1];
    uint4 o;
    o.x = pack_h2(__float2half_rn(a.x), __float2half_rn(a.y));
    o.y = pack_h2(__float2half_rn(a.z), __float2half_rn(a.w));
    o.z = pack_h2(__float2half_rn(b.x), __float2half_rn(b.y));
    o.w = pack_h2(__float2half_rn(b.z), __float2half_rn(b.w));
    *reinterpret_cast<uint4*>(oh + 8 * (long)i) = o;
}

// ---------------------------------------------------------------------------
// Weight transpose (hi only), 4 weights in one launch (blockIdx.z selects):
// W[K,N] fp32 -> Wt hi [N,K] fp16
// ---------------------------------------------------------------------------
struct WPair { const float* W; __half* oh; };

__global__ void wsplit4(WPair w0, WPair w1, WPair w2, WPair w3)
{
    __shared__ float t[32][33];
    const WPair wp = (blockIdx.z == 0) ? w0 : (blockIdx.z == 1) ? w1
                   : (blockIdx.z == 2) ? w2 : w3;
    const int n0 = blockIdx.x * 32, k0 = blockIdx.y * 32;
    const int tx = threadIdx.x, ty = threadIdx.y;
#pragma unroll
    for (int i = 0; i < 32; i += 8)
        t[ty + i][tx] = wp.W[(long)(k0 + ty + i) * EMB + n0 + tx];
    __syncthreads();
#pragma unroll
    for (int i = 0; i < 32; i += 8) {
        const long o = (long)(n0 + ty + i) * EMB + k0 + tx;
        wp.oh[o] = __float2half_rn(t[tx][ty + i]);
    }
}

// ---------------------------------------------------------------------------
// Row softmax over fp16 raw scores, in place, emitting fp16 probs x P_SCALE.
// ---------------------------------------------------------------------------
__global__ void __launch_bounds__(256)
softmax_h(__half* __restrict__ Ph)
{
    __shared__ float sred[8];
    __shared__ float sbc[2];
    const int tid = threadIdx.x;
    const long base = (long)blockIdx.x * SEQ;

    float v[8];
    {
        const uint4 a = *reinterpret_cast<const uint4*>(Ph + base + tid * 8);
        const __half2* h = reinterpret_cast<const __half2*>(&a);
#pragma unroll
        for (int j = 0; j < 4; ++j) {
            float2 f = __half22float2(h[j]);
            v[2 * j]     = f.x;
            v[2 * j + 1] = f.y;
        }
    }

    float m = v[0];
#pragma unroll
    for (int j = 1; j < 8; j++) m = fmaxf(m, v[j]);
#pragma unroll
    for (int o = 16; o > 0; o >>= 1) m = fmaxf(m, __shfl_xor_sync(0xffffffffu, m, o));
    if ((tid & 31) == 0) sred[tid >> 5] = m;
    __syncthreads();
    if (tid == 0) {
        float t = sred[0];
#pragma unroll
        for (int w = 1; w < 8; w++) t = fmaxf(t, sred[w]);
        sbc[0] = t;
    }
    __syncthreads();
    m = sbc[0];

    float s = 0.f;
#pragma unroll
    for (int j = 0; j < 8; j++) { v[j] = __expf(v[j] - m); s += v[j]; }
#pragma unroll
    for (int o = 16; o > 0; o >>= 1) s += __shfl_xor_sync(0xffffffffu, s, o);
    __syncthreads();
    if ((tid & 31) == 0) sred[tid >> 5] = s;
    __syncthreads();
    if (tid == 0) {
        float t = sred[0];
#pragma unroll
        for (int w = 1; w < 8; w++) t += sred[w];
        sbc[1] = t;
    }
    __syncthreads();
    const float inv = P_SCALE / sbc[1];

    uint4 o;
    o.x = pack_h2(__float2half_rn(v[0] * inv), __float2half_rn(v[1] * inv));
    o.y = pack_h2(__float2half_rn(v[2] * inv), __float2half_rn(v[3] * inv));
    o.z = pack_h2(__float2half_rn(v[4] * inv), __float2half_rn(v[5] * inv));
    o.w = pack_h2(__float2half_rn(v[6] * inv), __float2half_rn(v[7] * inv));
    *reinterpret_cast<uint4*>(Ph + base + tid * 8) = o;
}

// ---------------------------------------------------------------------------
// Host side
// ---------------------------------------------------------------------------
extern "C" void kernel_launch(void* const* d_in, const int* in_sizes, int n_in,
                              void* d_out, int out_size)
{
    const float* x  = (const float*)d_in[0];
    const float* Wq = (const float*)d_in[1];
    const float* bq = (const float*)d_in[2];
    const float* Wk = (const float*)d_in[3];
    const float* bk = (const float*)d_in[4];
    const float* Wv = (const float*)d_in[5];
    const float* bv = (const float*)d_in[6];
    const float* Wo = (const float*)d_in[7];
    const float* bo = (const float*)d_in[8];
    float* out = (float*)d_out;

    void *xh, *Wqh, *Wkh, *Wvh, *Woh;
    void *Qh, *Kh, *Vh, *Ph, *Ch;
    cudaGetSymbolAddress(&xh, g_xh);
    cudaGetSymbolAddress(&Wqh, g_Wqh);
    cudaGetSymbolAddress(&Wkh, g_Wkh);
    cudaGetSymbolAddress(&Wvh, g_Wvh);
    cudaGetSymbolAddress(&Woh, g_Woh);
    cudaGetSymbolAddress(&Qh, g_Qh);
    cudaGetSymbolAddress(&Kh, g_Kh);
    cudaGetSymbolAddress(&Vh, g_Vh);
    cudaGetSymbolAddress(&Ph, g_Ph);
    cudaGetSymbolAddress(&Ch, g_Ch);

    const int SM2 = NSTAGE * STAGEB;     // 110592 (gemm_mma: 3 stages x 2 tiles)
    const int SMP = PV_NST * PV_STAGE;   // 104448 (PV: 3 stages)
    cudaFuncSetAttribute(gemm_mma<0>, cudaFuncAttributeMaxDynamicSharedMemorySize, SM2);
    cudaFuncSetAttribute(gemm_mma<1>, cudaFuncAttributeMaxDynamicSharedMemorySize, SM2);
    cudaFuncSetAttribute(gemm_pv,     cudaFuncAttributeMaxDynamicSharedMemorySize, SMP);

    const float scl = 1.0f / sqrtf((float)EMB);
    const dim3 blk(256);
    const BSeg nil = {nullptr, nullptr, nullptr, 1.0f};

    // 1) convert inputs to fp16 hi (x + all 4 weights, 2 launches)
    {
        const int n8 = MROWS * EMB / 8;
        cvt_h<<<(n8 + 255) / 256, 256>>>((const float4*)x, (__half*)xh, n8);
        WPair w0 = {Wq, (__half*)Wqh};
        WPair w1 = {Wk, (__half*)Wkh};
        WPair w2 = {Wv, (__half*)Wvh};
        WPair w3 = {Wo, (__half*)Woh};
        wsplit4<<<dim3(24, 24, 4), dim3(32, 8)>>>(w0, w1, w2, w3);
    }

    // 2) merged QKV projections: one launch, segmented B/out, hi out
    {
        BSeg sq = {(const __half*)Wqh, bq, (__half*)Qh, scl};
        BSeg sk = {(const __half*)Wkh, bk, (__half*)Kh, 1.0f};
        BSeg sv = {(const __half*)Wvh, bv, (__half*)Vh, 1.0f};
        gemm_mma<1><<<dim3(18, 128, 1), blk, SM2>>>(
            (const __half*)xh,
            EMB, EMB, EMB, 0, 0,
            nullptr, EMB, 0, sq, sk, sv, 6);
    }

    // 3) scores = Q' @ K^T (scale folded into Q), fp16 raw scores out
    {
        BSeg sc = {(const __half*)Kh, nullptr, (__half*)Ph, 1.0f};
        gemm_mma<1><<<dim3(16, 16, 8), blk, SM2>>>(
            (const __half*)Qh,
            EMB, EMB, EMB, (long)SEQ * EMB, (long)SEQ * EMB,
            nullptr, SEQ, (long)SEQ * SEQ, sc, nil, nil, 0);
    }

    // 4) softmax in place: fp16 scores -> fp16 probs (x P_SCALE)
    softmax_h<<<MROWS, 256>>>((__half*)Ph);

    // 5) ctx = P @ V, B = V row-major via trans-ldmatrix, K=2048
    gemm_pv<<<dim3(6, 16, 8), blk, SMP>>>(
        (const __half*)Ph, (const __half*)Vh,
        SEQ, SEQ, EMB, (long)SEQ * SEQ, (long)SEQ * EMB,
        (__half*)Ch, 1.0f / P_SCALE, EMB, (long)SEQ * EMB);

    // 6) out = C @ Wo^T + bo, fp32
    {
        BSeg so = {(const __half*)Woh, bo, nullptr, 1.0f};
        gemm_mma<0><<<dim3(6, 128, 1), blk, SM2>>>(
            (const __half*)Ch,
            EMB, EMB, EMB, 0, 0,
            out, EMB, 0, so, nil, nil, 0);
    }
}